// round 10
// baseline (speedup 1.0000x reference)
#include <cuda_runtime.h>
#include <cuda_fp16.h>
#include <math.h>

#define BATCH 4
#define NPTS  40960
#define KNN   16
#define P_TOTAL (BATCH * NPTS)   // 163840

#define FS_H2  36    // fs tile row stride in half2 units (4 mod 32)
#define LG_PAD 66    // logits tile row stride (floats)
#define WH64   68    // fp16 B-tile stride, 64 cols, uint2 units
#define WH32   36    // fp16 B-tile stride, 32 cols, uint2 units
#define P4_64  66    // float4 B-tile stride, 64 cols (2 mod 8)
#define P4_128 130   // float4 B-tile stride, 128 cols (2 mod 8)
#define RP2    12    // relpos tile stride in half2 units
#define OA_PAD 100   // kern_out A tile stride (4 mod 32)

// Scratch (device globals)
__device__ float g_f_pc [P_TOTAL * 32];            // 21 MB
__device__ float g_f_agg[P_TOTAL * 32];            // 21 MB
__device__ float g_agg2 [(size_t)P_TOTAL * 64];    // 42 MB

__device__ __forceinline__ float to_tf32(float x) {
    float r;
    asm("cvt.rna.tf32.f32 %0, %1;" : "=f"(r) : "f"(x));
    return r;
}
__device__ __forceinline__ void tf32_split(float x, unsigned& h, unsigned& l) {
    float hf = to_tf32(x);
    h = __float_as_uint(hf);
    l = __float_as_uint(to_tf32(x - hf));
}
__device__ __forceinline__ unsigned f2_to_u(float a, float b) {
    __half2 h = __floats2half2_rn(a, b);
    return *(unsigned*)&h;
}

__device__ __forceinline__ void mma_tf32(float* c,
                                         unsigned a0, unsigned a1, unsigned a2, unsigned a3,
                                         unsigned b0, unsigned b1) {
    asm("mma.sync.aligned.m16n8k8.row.col.f32.tf32.tf32.f32 "
        "{%0,%1,%2,%3}, {%4,%5,%6,%7}, {%8,%9}, {%0,%1,%2,%3};"
        : "+f"(c[0]), "+f"(c[1]), "+f"(c[2]), "+f"(c[3])
        : "r"(a0), "r"(a1), "r"(a2), "r"(a3), "r"(b0), "r"(b1));
}
__device__ __forceinline__ void mma_f16(float* c,
                                        unsigned a0, unsigned a1, unsigned a2, unsigned a3,
                                        unsigned b0, unsigned b1) {
    asm("mma.sync.aligned.m16n8k16.row.col.f32.f16.f16.f32 "
        "{%0,%1,%2,%3}, {%4,%5,%6,%7}, {%8,%9}, {%0,%1,%2,%3};"
        : "+f"(c[0]), "+f"(c[1]), "+f"(c[2]), "+f"(c[3])
        : "r"(a0), "r"(a1), "r"(a2), "r"(a3), "r"(b0), "r"(b1));
}
__device__ __forceinline__ void mma3_pk(float* acc, float4 b,
                                        unsigned ah0, unsigned ah1, unsigned ah2, unsigned ah3,
                                        unsigned al0, unsigned al1, unsigned al2, unsigned al3) {
    unsigned bh0 = __float_as_uint(b.x), bh1 = __float_as_uint(b.y);
    unsigned bl0 = __float_as_uint(b.z), bl1 = __float_as_uint(b.w);
    mma_tf32(acc, ah0, ah1, ah2, ah3, bh0, bh1);
    mma_tf32(acc, al0, al1, al2, al3, bh0, bh1);
    mma_tf32(acc, ah0, ah1, ah2, ah3, bl0, bl1);
}

// dual-point logits: fs0/fs1 fp16 tiles share the B reads
__device__ __forceinline__ void logits_f16_x2(const unsigned* __restrict__ fsw0,
                                              const unsigned* __restrict__ fsw1,
                                              float* __restrict__ lg0,
                                              float* __restrict__ lg1,
                                              const uint2* __restrict__ wfc, int lane)
{
    const int gid = lane >> 2;
    const int tig = lane & 3;
    float ac0[8][4], ac1[8][4];
    #pragma unroll
    for (int n = 0; n < 8; n++)
        #pragma unroll
        for (int j = 0; j < 4; j++) { ac0[n][j] = 0.f; ac1[n][j] = 0.f; }
    #pragma unroll
    for (int q = 0; q < 4; q++) {
        unsigned a00 = fsw0[gid * FS_H2 + q * 8 + tig];
        unsigned a01 = fsw0[(gid + 8) * FS_H2 + q * 8 + tig];
        unsigned a02 = fsw0[gid * FS_H2 + q * 8 + tig + 4];
        unsigned a03 = fsw0[(gid + 8) * FS_H2 + q * 8 + tig + 4];
        unsigned a10 = fsw1[gid * FS_H2 + q * 8 + tig];
        unsigned a11 = fsw1[(gid + 8) * FS_H2 + q * 8 + tig];
        unsigned a12 = fsw1[gid * FS_H2 + q * 8 + tig + 4];
        unsigned a13 = fsw1[(gid + 8) * FS_H2 + q * 8 + tig + 4];
        const uint2* br = wfc + (q * 4 + tig) * WH64 + gid;
        #pragma unroll
        for (int n = 0; n < 8; n++) {
            uint2 b = br[8 * n];
            mma_f16(ac0[n], a00, a01, a02, a03, b.x, b.y);
            mma_f16(ac1[n], a10, a11, a12, a13, b.x, b.y);
        }
    }
    #pragma unroll
    for (int n = 0; n < 8; n++) {
        *(float2*)(lg0 + gid * LG_PAD + n * 8 + 2 * tig)       = make_float2(ac0[n][0], ac0[n][1]);
        *(float2*)(lg0 + (gid + 8) * LG_PAD + n * 8 + 2 * tig) = make_float2(ac0[n][2], ac0[n][3]);
        *(float2*)(lg1 + gid * LG_PAD + n * 8 + 2 * tig)       = make_float2(ac1[n][0], ac1[n][1]);
        *(float2*)(lg1 + (gid + 8) * LG_PAD + n * 8 + 2 * tig) = make_float2(ac1[n][2], ac1[n][3]);
    }
}

__device__ __forceinline__ float att_pool_reg(const float* __restrict__ lg_s,
                                              const float* __restrict__ vals, int ch)
{
    float l[KNN];
    float m = -1e30f;
    #pragma unroll
    for (int k = 0; k < KNN; k++) { l[k] = lg_s[k * LG_PAD + ch]; m = fmaxf(m, l[k]); }
    float s = 0.f, a = 0.f;
    #pragma unroll
    for (int k = 0; k < KNN; k++) {
        float e = __expf(l[k] - m);
        s += e;
        a += e * vals[k];
    }
    return __fdividef(a, s);
}

__device__ __forceinline__ float att_pool_h(const float* __restrict__ lg_s,
                                            const __half2* __restrict__ fs_h, int lane)
{
    const int ch = 32 + lane;
    float vals[KNN];
    #pragma unroll
    for (int k = 0; k < KNN; k++) {
        __half2 h = fs_h[k * FS_H2 + 16 + (lane >> 1)];
        vals[k] = (lane & 1) ? __high2float(h) : __low2float(h);
    }
    return att_pool_reg(lg_s, vals, ch);
}

// relpos row for this lane (krow = lane&15, point = p0 or p1 by lane half)
__device__ __forceinline__ void write_relpos(__half2* rp, int krow,
                                             float cx, float cy, float cz,
                                             float nx, float ny, float nz)
{
    float rx = cx - nx, ry = cy - ny, rz = cz - nz;
    float d = sqrtf(rx * rx + ry * ry + rz * rz);
    __half2 z = __floats2half2_rn(0.f, 0.f);
    rp[krow * RP2 + 0] = __floats2half2_rn(d, rx);
    rp[krow * RP2 + 1] = __floats2half2_rn(ry, rz);
    rp[krow * RP2 + 2] = __floats2half2_rn(cx, cy);
    rp[krow * RP2 + 3] = __floats2half2_rn(cz, nx);
    rp[krow * RP2 + 4] = __floats2half2_rn(ny, nz);
    rp[krow * RP2 + 5] = z;
    rp[krow * RP2 + 6] = z;
    rp[krow * RP2 + 7] = z;
}

// lfa1 (f16, shared B) for two points: rp tiles -> fs cols 16..31 (ch 32..63)
__device__ __forceinline__ void lfa1_x2(const unsigned* __restrict__ rp0w,
                                        const unsigned* __restrict__ rp1w,
                                        __half2* __restrict__ fs0_h,
                                        __half2* __restrict__ fs1_h,
                                        const uint2* __restrict__ wl1p,
                                        const float* __restrict__ bias, int lane)
{
    const int gid = lane >> 2, tig = lane & 3;
    unsigned a00 = rp0w[gid * RP2 + tig];
    unsigned a01 = rp0w[(gid + 8) * RP2 + tig];
    unsigned a02 = rp0w[gid * RP2 + tig + 4];
    unsigned a03 = rp0w[(gid + 8) * RP2 + tig + 4];
    unsigned a10 = rp1w[gid * RP2 + tig];
    unsigned a11 = rp1w[(gid + 8) * RP2 + tig];
    unsigned a12 = rp1w[gid * RP2 + tig + 4];
    unsigned a13 = rp1w[(gid + 8) * RP2 + tig + 4];
    float ac0[4][4], ac1[4][4];
    #pragma unroll
    for (int n = 0; n < 4; n++)
        #pragma unroll
        for (int j = 0; j < 4; j++) { ac0[n][j] = 0.f; ac1[n][j] = 0.f; }
    const uint2* br = wl1p + tig * WH32 + gid;
    #pragma unroll
    for (int n = 0; n < 4; n++) {
        uint2 bb = br[8 * n];
        mma_f16(ac0[n], a00, a01, a02, a03, bb.x, bb.y);
        mma_f16(ac1[n], a10, a11, a12, a13, bb.x, bb.y);
    }
    #pragma unroll
    for (int n = 0; n < 4; n++) {
        int c0 = n * 8 + 2 * tig;
        float b0 = bias[c0], b1 = bias[c0 + 1];
        fs0_h[gid * FS_H2 + 16 + n * 4 + tig] =
            __floats2half2_rn(fmaxf(ac0[n][0] + b0, 0.f), fmaxf(ac0[n][1] + b1, 0.f));
        fs0_h[(gid + 8) * FS_H2 + 16 + n * 4 + tig] =
            __floats2half2_rn(fmaxf(ac0[n][2] + b0, 0.f), fmaxf(ac0[n][3] + b1, 0.f));
        fs1_h[gid * FS_H2 + 16 + n * 4 + tig] =
            __floats2half2_rn(fmaxf(ac1[n][0] + b0, 0.f), fmaxf(ac1[n][1] + b1, 0.f));
        fs1_h[(gid + 8) * FS_H2 + 16 + n * 4 + tig] =
            __floats2half2_rn(fmaxf(ac1[n][2] + b0, 0.f), fmaxf(ac1[n][3] + b1, 0.f));
    }
}

// ---------------------------------------------------------------------------
// Kernel 1: f_pc = ReLU((feature @ w_mlp1) * s + b)
// ---------------------------------------------------------------------------
__global__ __launch_bounds__(256) void kern_mlp1(
    const float* __restrict__ feature,
    const float* __restrict__ w, const float* __restrict__ s, const float* __restrict__ b)
{
    __shared__ float ws[1024];
    __shared__ float sv[32], bv[32];
    __shared__ float xs[8][32];

    for (int i = threadIdx.x; i < 1024; i += blockDim.x) ws[i] = w[i];
    if (threadIdx.x < 32) { sv[threadIdx.x] = s[threadIdx.x]; bv[threadIdx.x] = b[threadIdx.x]; }
    __syncthreads();

    const int lane = threadIdx.x & 31;
    const int warp = threadIdx.x >> 5;
    const int nwarps = (gridDim.x * blockDim.x) >> 5;
    int gw = (blockIdx.x * blockDim.x + threadIdx.x) >> 5;

    for (int p = gw; p < P_TOTAL; p += nwarps) {
        xs[warp][lane] = feature[(size_t)p * 32 + lane];
        __syncwarp();
        float acc = 0.f;
        #pragma unroll
        for (int j4 = 0; j4 < 32; j4 += 4) {
            float4 f = *(const float4*)(&xs[warp][j4]);
            acc += f.x * ws[(j4 + 0) * 32 + lane];
            acc += f.y * ws[(j4 + 1) * 32 + lane];
            acc += f.z * ws[(j4 + 2) * 32 + lane];
            acc += f.w * ws[(j4 + 3) * 32 + lane];
        }
        g_f_pc[(size_t)p * 32 + lane] = fmaxf(acc * sv[lane] + bv[lane], 0.f);
        __syncwarp();
    }
}

// ---------------------------------------------------------------------------
// Kernel 2: TWO points per warp. rel_pos + lfa1(f16) + gather + logits(f16) +
//           pool + f_agg.  (NO lfa2 / fx2 write anymore.)
// per warp floats: fs0 576 + fs1 576 + lg0 1056 + lg1 1056 + agg 128 = 3392
// ---------------------------------------------------------------------------
#define K2_WARP_FLOATS 3392
#define K2_BASE_FLOATS 4608
#define K2_WARPS 14
#define K2_SMEM_BYTES ((K2_BASE_FLOATS + K2_WARPS * K2_WARP_FLOATS) * 4)

__global__ __launch_bounds__(448) void kern_att1(
    const float* __restrict__ xyz, const int* __restrict__ neigh,
    const float* __restrict__ wlfa1, const float* __restrict__ slfa1, const float* __restrict__ blfa1,
    const float* __restrict__ wfc1,
    const float* __restrict__ wam1, const float* __restrict__ sam1, const float* __restrict__ bam1)
{
    extern __shared__ float sm[];
    uint2*  s_wfcp = (uint2*)sm;              // [16][68] uint2 = 2176 floats
    float2* s_wamp = (float2*)(sm + 2176);    // [32][32] float2 = 2048 floats
    uint2*  s_wl1p = (uint2*)(sm + 4224);     // [4][36] uint2 = 288 floats
    float*  s_vec  = sm + 4512;               // 96: blfa1[32], bam1[32]
    float*  s_wrp  = sm + K2_BASE_FLOATS;

    for (int i = threadIdx.x; i < 1024; i += blockDim.x) {
        int r = i >> 6, c = i & 63;
        int q = r >> 2, t = r & 3;
        int k0 = 16 * q + 2 * t;
        s_wfcp[r * WH64 + c] = make_uint2(
            f2_to_u(wfc1[k0 * 64 + c], wfc1[(k0 + 1) * 64 + c]),
            f2_to_u(wfc1[(k0 + 8) * 64 + c], wfc1[(k0 + 9) * 64 + c]));
    }
    for (int i = threadIdx.x; i < 1024; i += blockDim.x) {
        int r = i >> 5, c = i & 31;
        s_wamp[r * 32 + c] = make_float2(wam1[(2 * r) * 32 + c] * sam1[c],
                                         wam1[(2 * r + 1) * 32 + c] * sam1[c]);
    }
    for (int i = threadIdx.x; i < 128; i += blockDim.x) {
        int t = i >> 5, c = i & 31;
        int k0 = 2 * t, k1 = 2 * t + 8;
        float w00 = wlfa1[k0 * 32 + c] * slfa1[c];
        float w01 = wlfa1[(k0 + 1) * 32 + c] * slfa1[c];
        float w10 = (k1 < 10) ? wlfa1[k1 * 32 + c] * slfa1[c] : 0.f;
        float w11 = (k1 + 1 < 10) ? wlfa1[(k1 + 1) * 32 + c] * slfa1[c] : 0.f;
        s_wl1p[t * WH32 + c] = make_uint2(f2_to_u(w00, w01), f2_to_u(w10, w11));
    }
    if (threadIdx.x < 32) {
        int l = threadIdx.x;
        s_vec[l]      = blfa1[l];
        s_vec[32 + l] = bam1[l];
    }
    __syncthreads();

    const int lane = threadIdx.x & 31;
    const int warp = threadIdx.x >> 5;
    float* wbase = s_wrp + warp * K2_WARP_FLOATS;
    __half2*  fs0_h = (__half2*)wbase;            // [16][36] half2
    __half2*  fs1_h = (__half2*)(wbase + 576);
    unsigned* fsw0  = (unsigned*)fs0_h;
    unsigned* fsw1  = (unsigned*)fs1_h;
    float* lg0  = wbase + 1152;                   // [16][66]
    float* lg1  = wbase + 2208;
    __half2* rp0 = (__half2*)lg0;                 // aliases lg (dead before logits)
    __half2* rp1 = (__half2*)lg1;
    float* agg_s = wbase + 3264;                  // [128]

    const int nwarps = (gridDim.x * blockDim.x) >> 5;
    int gw = (blockIdx.x * blockDim.x + threadIdx.x) >> 5;

    for (int pp = gw; pp < P_TOTAL / 2; pp += nwarps) {
        const int p0 = 2 * pp, p1 = p0 + 1;
        const int b = p0 / NPTS;
        const size_t bbase = (size_t)b * NPTS;

        int idx = neigh[(size_t)p0 * KNN + lane];

        float gv0[KNN], gv1[KNN];
        #pragma unroll
        for (int k = 0; k < KNN; k++) {
            int nb = __shfl_sync(0xffffffffu, idx, k);
            gv0[k] = g_f_pc[(bbase + (size_t)nb) * 32 + lane];
        }
        #pragma unroll
        for (int k = 0; k < KNN; k++) {
            int nb = __shfl_sync(0xffffffffu, idx, 16 + k);
            gv1[k] = g_f_pc[(bbase + (size_t)nb) * 32 + lane];
        }

        {
            const int myp = (lane < 16) ? p0 : p1;
            size_t nb = bbase + (size_t)idx;
            float cx = xyz[(size_t)myp * 3 + 0];
            float cy = xyz[(size_t)myp * 3 + 1];
            float cz = xyz[(size_t)myp * 3 + 2];
            float nx = xyz[nb * 3 + 0], ny = xyz[nb * 3 + 1], nz = xyz[nb * 3 + 2];
            write_relpos((lane < 16) ? rp0 : rp1, lane & 15, cx, cy, cz, nx, ny, nz);
        }
        __syncwarp();

        lfa1_x2((unsigned*)rp0, (unsigned*)rp1, fs0_h, fs1_h, s_wl1p, s_vec, lane);

        // gathered f_pc -> fs half2 cols 0..15
        #pragma unroll
        for (int k = 0; k < KNN; k++) {
            float v0 = gv0[k];
            float v1 = __shfl_xor_sync(0xffffffffu, v0, 1);
            if (!(lane & 1))
                fs0_h[k * FS_H2 + (lane >> 1)] = __floats2half2_rn(v0, v1);
        }
        #pragma unroll
        for (int k = 0; k < KNN; k++) {
            float v0 = gv1[k];
            float v1 = __shfl_xor_sync(0xffffffffu, v0, 1);
            if (!(lane & 1))
                fs1_h[k * FS_H2 + (lane >> 1)] = __floats2half2_rn(v0, v1);
        }
        __syncwarp();

        logits_f16_x2(fsw0, fsw1, lg0, lg1, s_wfcp, lane);
        __syncwarp();
        agg_s[lane]       = att_pool_reg(lg0, gv0, lane);
        agg_s[32 + lane]  = att_pool_h(lg0, fs0_h, lane);
        agg_s[64 + lane]  = att_pool_reg(lg1, gv1, lane);
        agg_s[96 + lane]  = att_pool_h(lg1, fs1_h, lane);
        __syncwarp();

        // f_agg for both points, wam read once
        {
            float acc0 = 0.f, acc1 = 0.f;
            #pragma unroll
            for (int d2 = 0; d2 < 32; d2 += 2) {
                float4 a0 = *(const float4*)(agg_s + 2 * d2);
                float4 a1 = *(const float4*)(agg_s + 64 + 2 * d2);
                float2 w0 = s_wamp[d2 * 32 + lane];
                float2 w1 = s_wamp[(d2 + 1) * 32 + lane];
                acc0 += a0.x * w0.x + a0.y * w0.y + a0.z * w1.x + a0.w * w1.y;
                acc1 += a1.x * w0.x + a1.y * w0.y + a1.z * w1.x + a1.w * w1.y;
            }
            float bb = s_vec[32 + lane];
            g_f_agg[(size_t)p0 * 32 + lane] = fmaxf(acc0 + bb, 0.f);
            g_f_agg[(size_t)p1 * 32 + lane] = fmaxf(acc1 + bb, 0.f);
        }
        __syncwarp();
    }
}

// ---------------------------------------------------------------------------
// Kernel 3: TWO points per warp. Recomputes relpos + lfa1 + lfa2 (no fx2
//           scratch), gathers f_agg, logits + pools -> g_agg2.
// per warp floats: fs0 576 + fs1 576 + lg0 1056 + lg1 1056 = 3264
// ---------------------------------------------------------------------------
#define K3_WARP_FLOATS 3264
#define K3_BASE_FLOATS 3104
#define K3_WARPS 14
#define K3_SMEM_BYTES ((K3_BASE_FLOATS + K3_WARPS * K3_WARP_FLOATS) * 4)

__global__ __launch_bounds__(448) void kern_att2(
    const float* __restrict__ xyz, const int* __restrict__ neigh,
    const float* __restrict__ wlfa1, const float* __restrict__ slfa1, const float* __restrict__ blfa1,
    const float* __restrict__ wlfa2, const float* __restrict__ slfa2, const float* __restrict__ blfa2,
    const float* __restrict__ wfc2)
{
    extern __shared__ float sm[];
    uint2* s_wfcp = (uint2*)sm;               // [16][68] uint2 = 2176 floats
    uint2* s_wl1p = (uint2*)(sm + 2176);      // [4][36] uint2 = 288 floats
    uint2* s_wl2p = (uint2*)(sm + 2464);      // [8][36] uint2 = 576 floats
    float* s_vec  = sm + 3040;                // 64: blfa1[32], blfa2[32]
    float* s_wrp  = sm + K3_BASE_FLOATS;

    for (int i = threadIdx.x; i < 1024; i += blockDim.x) {
        int r = i >> 6, c = i & 63;
        int q = r >> 2, t = r & 3;
        int k0 = 16 * q + 2 * t;
        s_wfcp[r * WH64 + c] = make_uint2(
            f2_to_u(wfc2[k0 * 64 + c], wfc2[(k0 + 1) * 64 + c]),
            f2_to_u(wfc2[(k0 + 8) * 64 + c], wfc2[(k0 + 9) * 64 + c]));
    }
    for (int i = threadIdx.x; i < 128; i += blockDim.x) {
        int t = i >> 5, c = i & 31;
        int k0 = 2 * t, k1 = 2 * t + 8;
        float w00 = wlfa1[k0 * 32 + c] * slfa1[c];
        float w01 = wlfa1[(k0 + 1) * 32 + c] * slfa1[c];
        float w10 = (k1 < 10) ? wlfa1[k1 * 32 + c] * slfa1[c] : 0.f;
        float w11 = (k1 + 1 < 10) ? wlfa1[(k1 + 1) * 32 + c] * slfa1[c] : 0.f;
        s_wl1p[t * WH32 + c] = make_uint2(f2_to_u(w00, w01), f2_to_u(w10, w11));
    }
    for (int i = threadIdx.x; i < 256; i += blockDim.x) {
        int r = i >> 5, c = i & 31;
        int q = r >> 2, t = r & 3;
        int k0 = 16 * q + 2 * t;
        s_wl2p[r * WH32 + c] = make_uint2(
            f2_to_u(wlfa2[k0 * 32 + c] * slfa2[c], wlfa2[(k0 + 1) * 32 + c] * slfa2[c]),
            f2_to_u(wlfa2[(k0 + 8) * 32 + c] * slfa2[c], wlfa2[(k0 + 9) * 32 + c] * slfa2[c]));
    }
    if (threadIdx.x < 32) {
        int l = threadIdx.x;
        s_vec[l]      = blfa1[l];
        s_vec[32 + l] = blfa2[l];
    }
    __syncthreads();

    const int lane = threadIdx.x & 31;
    const int warp = threadIdx.x >> 5;
    const int gid = lane >> 2, tig = lane & 3;
    float* wbase = s_wrp + warp * K3_WARP_FLOATS;
    __half2*  fs0_h = (__half2*)wbase;
    __half2*  fs1_h = (__half2*)(wbase + 576);
    unsigned* fsw0  = (unsigned*)fs0_h;
    unsigned* fsw1  = (unsigned*)fs1_h;
    float* lg0 = wbase + 1152;
    float* lg1 = wbase + 2208;
    __half2* rp0 = (__half2*)lg0;
    __half2* rp1 = (__half2*)lg1;

    const int nwarps = (gridDim.x * blockDim.x) >> 5;
    int gw = (blockIdx.x * blockDim.x + threadIdx.x) >> 5;

    for (int pp = gw; pp < P_TOTAL / 2; pp += nwarps) {
        const int p0 = 2 * pp, p1 = p0 + 1;
        const int b = p0 / NPTS;
        const size_t bbase = (size_t)b * NPTS;

        int idx = neigh[(size_t)p0 * KNN + lane];

        float gv0[KNN], gv1[KNN];
        #pragma unroll
        for (int k = 0; k < KNN; k++) {
            int nb = __shfl_sync(0xffffffffu, idx, k);
            gv0[k] = g_f_agg[(bbase + (size_t)nb) * 32 + lane];
        }
        #pragma unroll
        for (int k = 0; k < KNN; k++) {
            int nb = __shfl_sync(0xffffffffu, idx, 16 + k);
            gv1[k] = g_f_agg[(bbase + (size_t)nb) * 32 + lane];
        }

        // relpos (recomputed; fx2 scratch eliminated)
        {
            const int myp = (lane < 16) ? p0 : p1;
            size_t nb = bbase + (size_t)idx;
            float cx = xyz[(size_t)myp * 3 + 0];
            float cy = xyz[(size_t)myp * 3 + 1];
            float cz = xyz[(size_t)myp * 3 + 2];
            float nx = xyz[nb * 3 + 0], ny = xyz[nb * 3 + 1], nz = xyz[nb * 3 + 2];
            write_relpos((lane < 16) ? rp0 : rp1, lane & 15, cx, cy, cz, nx, ny, nz);
        }
        __syncwarp();

        // lfa1: f_xyz -> fs cols 16..31
        lfa1_x2((unsigned*)rp0, (unsigned*)rp1, fs0_h, fs1_h, s_wl1p, s_vec, lane);
        __syncwarp();

        // lfa2 in-place: load ALL A-frags (f_xyz), sync, then overwrite fs cols 16..31
        {
            unsigned af[16];
            #pragma unroll
            for (int q = 0; q < 2; q++) {
                af[q * 4 + 0] = fsw0[gid * FS_H2 + 16 + q * 8 + tig];
                af[q * 4 + 1] = fsw0[(gid + 8) * FS_H2 + 16 + q * 8 + tig];
                af[q * 4 + 2] = fsw0[gid * FS_H2 + 16 + q * 8 + tig + 4];
                af[q * 4 + 3] = fsw0[(gid + 8) * FS_H2 + 16 + q * 8 + tig + 4];
                af[8 + q * 4 + 0] = fsw1[gid * FS_H2 + 16 + q * 8 + tig];
                af[8 + q * 4 + 1] = fsw1[(gid + 8) * FS_H2 + 16 + q * 8 + tig];
                af[8 + q * 4 + 2] = fsw1[gid * FS_H2 + 16 + q * 8 + tig + 4];
                af[8 + q * 4 + 3] = fsw1[(gid + 8) * FS_H2 + 16 + q * 8 + tig + 4];
            }
            __syncwarp();

            float ac0[4][4], ac1[4][4];
            #pragma unroll
            for (int n = 0; n < 4; n++)
                #pragma unroll
                for (int j = 0; j < 4; j++) { ac0[n][j] = 0.f; ac1[n][j] = 0.f; }
            #pragma unroll
            for (int q = 0; q < 2; q++) {
                const uint2* br = s_wl2p + (q * 4 + tig) * WH32 + gid;
                #pragma unroll
                for (int n = 0; n < 4; n++) {
                    uint2 bb = br[8 * n];
                    mma_f16(ac0[n], af[q*4+0], af[q*4+1], af[q*4+2], af[q*4+3], bb.x, bb.y);
                    mma_f16(ac1[n], af[8+q*4+0], af[8+q*4+1], af[8+q*4+2], af[8+q*4+3], bb.x, bb.y);
                }
            }
            #pragma unroll
            for (int n = 0; n < 4; n++) {
                int c0 = n * 8 + 2 * tig;
                float b0 = s_vec[32 + c0], b1 = s_vec[32 + c0 + 1];
                fs0_h[gid * FS_H2 + 16 + n * 4 + tig] =
                    __floats2half2_rn(fmaxf(ac0[n][0] + b0, 0.f), fmaxf(ac0[n][1] + b1, 0.f));
                fs0_h[(gid + 8) * FS_H2 + 16 + n * 4 + tig] =
                    __floats2half2_rn(fmaxf(ac0[n][2] + b0, 0.f), fmaxf(ac0[n][3] + b1, 0.f));
                fs1_h[gid * FS_H2 + 16 + n * 4 + tig] =
                    __floats2half2_rn(fmaxf(ac1[n][0] + b0, 0.f), fmaxf(ac1[n][1] + b1, 0.f));
                fs1_h[(gid + 8) * FS_H2 + 16 + n * 4 + tig] =
                    __floats2half2_rn(fmaxf(ac1[n][2] + b0, 0.f), fmaxf(ac1[n][3] + b1, 0.f));
            }
        }

        // gathered f_agg -> fs cols 0..15
        #pragma unroll
        for (int k = 0; k < KNN; k++) {
            float v0 = gv0[k];
            float v1 = __shfl_xor_sync(0xffffffffu, v0, 1);
            if (!(lane & 1))
                fs0_h[k * FS_H2 + (lane >> 1)] = __floats2half2_rn(v0, v1);
        }
        #pragma unroll
        for (int k = 0; k < KNN; k++) {
            float v0 = gv1[k];
            float v1 = __shfl_xor_sync(0xffffffffu, v0, 1);
            if (!(lane & 1))
                fs1_h[k * FS_H2 + (lane >> 1)] = __floats2half2_rn(v0, v1);
        }
        __syncwarp();

        logits_f16_x2(fsw0, fsw1, lg0, lg1, s_wfcp, lane);
        __syncwarp();

        g_agg2[(size_t)p0 * 64 + lane]      = att_pool_reg(lg0, gv0, lane);
        g_agg2[(size_t)p0 * 64 + 32 + lane] = att_pool_h(lg0, fs0_h, lane);
        g_agg2[(size_t)p1 * 64 + lane]      = att_pool_reg(lg1, gv1, lane);
        g_agg2[(size_t)p1 * 64 + 32 + lane] = att_pool_h(lg1, fs1_h, lane);
        __syncwarp();
    }
}

// ---------------------------------------------------------------------------
// Kernel 4: 16-point tiles: pc2 = relu(agg2@w1+b1) into combined [pc2;feat]
//           K=96 A tile; out = leaky(A @ w23 + b2).  3xTF32 packed float4 B.
// ---------------------------------------------------------------------------
#define OUT_WARPS 12
#define OUT_BASE_FLOATS 33600
#define OUT_WARP_FLOATS 1600
#define OUT_SMEM_BYTES ((OUT_BASE_FLOATS + OUT_WARPS * OUT_WARP_FLOATS) * 4)

__global__ __launch_bounds__(384) void kern_out(
    const float* __restrict__ feature,
    const float* __restrict__ wam2, const float* __restrict__ sam2, const float* __restrict__ bam2,
    const float* __restrict__ wmlp2, const float* __restrict__ smlp2, const float* __restrict__ bmlp2,
    const float* __restrict__ wsc, const float* __restrict__ ssc, const float* __restrict__ bsc,
    float* __restrict__ out)
{
    extern __shared__ float sm[];
    float4* w1p  = (float4*)sm;              // [32][66] float4 = 8448 floats
    float4* w23p = (float4*)(sm + 8448);     // [48][130] float4 = 24960 floats
    float*  b1   = sm + 33408;               // [64]
    float*  b2   = sm + 33472;               // [128]
    float*  wrp  = sm + OUT_BASE_FLOATS;

    for (int i = threadIdx.x; i < 2048; i += blockDim.x) {
        int r = i >> 6, c = i & 63;
        int k0 = (r >> 2) * 8 + (r & 3), k1 = k0 + 4;
        float v0 = wam2[k0 * 64 + c] * sam2[c];
        float v1 = wam2[k1 * 64 + c] * sam2[c];
        float h0 = to_tf32(v0), h1 = to_tf32(v1);
        w1p[r * P4_64 + c] = make_float4(h0, h1, to_tf32(v0 - h0), to_tf32(v1 - h1));
    }
    for (int i = threadIdx.x; i < 6144; i += blockDim.x) {
        int r = i >> 7, c = i & 127;
        int k0 = (r >> 2) * 8 + (r & 3), k1 = k0 + 4;
        float v0 = (k0 < 64) ? wmlp2[k0 * 128 + c] * smlp2[c] : wsc[(k0 - 64) * 128 + c] * ssc[c];
        float v1 = (k1 < 64) ? wmlp2[k1 * 128 + c] * smlp2[c] : wsc[(k1 - 64) * 128 + c] * ssc[c];
        float h0 = to_tf32(v0), h1 = to_tf32(v1);
        w23p[r * P4_128 + c] = make_float4(h0, h1, to_tf32(v0 - h0), to_tf32(v1 - h1));
    }
    if (threadIdx.x < 64)  b1[threadIdx.x] = bam2[threadIdx.x];
    if (threadIdx.x < 128) b2[threadIdx.x] = bmlp2[threadIdx.x] + bsc[threadIdx.x];
    __syncthreads();

    const int lane = threadIdx.x & 31;
    const int warp = threadIdx.x >> 5;
    const int gid = lane >> 2, tig = lane & 3;
    float* A1 = wrp + warp * OUT_WARP_FLOATS;  // [16][100]

    const int nwarps = (gridDim.x * blockDim.x) >> 5;
    int gw = (blockIdx.x * blockDim.x + threadIdx.x) >> 5;
    const int ntiles = P_TOTAL / 16;

    for (int t = gw; t < ntiles; t += nwarps) {
        const int p0 = t * 16;

        #pragma unroll
        for (int r = 0; r < 16; r++) {
            A1[r * OA_PAD + lane]      = g_agg2[(size_t)(p0 + r) * 64 + lane];
            A1[r * OA_PAD + 32 + lane] = g_agg2[(size_t)(p0 + r) * 64 + 32 + lane];
            A1[r * OA_PAD + 64 + lane] = feature[(size_t)(p0 + r) * 32 + lane];
        }
        __syncwarp();

        // GEMM1: pc2 = relu(agg @ w1 + b1), written back into A cols 0..63
        {
            float acc[8][4];
            #pragma unroll
            for (int n = 0; n < 8; n++) { acc[n][0]=0.f; acc[n][1]=0.f; acc[n][2]=0.f; acc[n][3]=0.f; }
            #pragma unroll
            for (int q = 0; q < 8; q++) {
                unsigned ah0, al0, ah1, al1, ah2, al2, ah3, al3;
                tf32_split(A1[gid * OA_PAD + q * 8 + tig],           ah0, al0);
                tf32_split(A1[(gid + 8) * OA_PAD + q * 8 + tig],     ah1, al1);
                tf32_split(A1[gid * OA_PAD + q * 8 + tig + 4],       ah2, al2);
                tf32_split(A1[(gid + 8) * OA_PAD + q * 8 + tig + 4], ah3, al3);
                const float4* br = w1p + (q * 4 + tig) * P4_64 + gid;
                #pragma unroll
                for (int n = 0; n < 8; n++)
                    mma3_pk(acc[n], br[8 * n], ah0, ah1, ah2, ah3, al0, al1, al2, al3);
            }
            __syncwarp();
            #pragma unroll
            for (int n = 0; n < 8; n++) {
                int c0 = n * 8 + 2 * tig;
                float bb0 = b1[c0], bb1 = b1[c0 + 1];
                *(float2*)(A1 + gid * OA_PAD + c0) =
                    make_float2(fmaxf(acc[n][0] + bb0, 0.f), fmaxf(acc[n][1] + bb1, 0.f));
                *(float2*)(A1 + (gid + 8) * OA_PAD + c0) =
                    make_float2(fmaxf(acc[n][2] + bb0, 0.f), fmaxf(acc[n][3] + bb1, 0.f));
            }
        }
        __syncwarp();

        // GEMM2: out = leaky(A[16][96] @ w23 + b2), n in two halves of 64
        #pragma unroll
        for (int h = 0; h < 2; h++) {
            float acc[8][4];
            #pragma unroll
            for (int n = 0; n < 8; n++) { acc[n][0]=0.f; acc[n][1]=0.f; acc[n][2]=0.f; acc[n][3]=0.f; }
            #pragma unroll
            for (int q = 0; q < 12; q++) {
                unsigned ah0, al0, ah1, al1, ah2, al2, ah3, al3;
                tf32_split(A1[gid * OA_PAD + q * 8 + tig],           ah0, al0);
                tf32_split(A1[(gid + 8) * OA_PAD + q * 8 + tig],     ah1, al1);
                tf32_split(A1[gid * OA_PAD + q * 8 + tig + 4],       ah2, al2);
                tf32_split(A1[(gid + 8) * OA_PAD + q * 8 + tig + 4], ah3, al3);
                const float4* br = w23p + (q * 4 + tig) * P4_128 + h * 64 + gid;
                #pragma unroll
                for (int n = 0; n < 8; n++)
                    mma3_pk(acc[n], br[8 * n], ah0, ah1, ah2, ah3, al0, al1, al2, al3);
            }
            #pragma unroll
            for (int n = 0; n < 8; n++) {
                int c0 = h * 64 + n * 8 + 2 * tig;
                float bb0 = b2[c0], bb1 = b2[c0 + 1];
                float v0 = acc[n][0] + bb0; v0 = (v0 < 0.f) ? 0.2f * v0 : v0;
                float v1 = acc[n][1] + bb1; v1 = (v1 < 0.f) ? 0.2f * v1 : v1;
                float v2 = acc[n][2] + bb0; v2 = (v2 < 0.f) ? 0.2f * v2 : v2;
                float v3 = acc[n][3] + bb1; v3 = (v3 < 0.f) ? 0.2f * v3 : v3;
                *(float2*)(&out[(size_t)(p0 + gid) * 128 + c0])     = make_float2(v0, v1);
                *(float2*)(&out[(size_t)(p0 + gid + 8) * 128 + c0]) = make_float2(v2, v3);
            }
        }
        __syncwarp();
    }
}

// ---------------------------------------------------------------------------
extern "C" void kernel_launch(void* const* d_in, const int* in_sizes, int n_in,
                              void* d_out, int out_size)
{
    const float* feature = (const float*)d_in[0];
    const float* xyz     = (const float*)d_in[1];
    const int*   neigh   = (const int*)  d_in[2];
    const float* w_mlp1  = (const float*)d_in[3];
    const float* s_mlp1  = (const float*)d_in[4];
    const float* b_mlp1  = (const float*)d_in[5];
    const float* w_lfa1  = (const float*)d_in[6];
    const float* s_lfa1  = (const float*)d_in[7];
    const float* b_lfa1  = (const float*)d_in[8];
    const float* w_fc1   = (const float*)d_in[9];
    const float* w_am1   = (const float*)d_in[10];
    const float* s_am1   = (const float*)d_in[11];
    const float* b_am1   = (const float*)d_in[12];
    const float* w_lfa2  = (const float*)d_in[13];
    const float* s_lfa2  = (const float*)d_in[14];
    const float* b_lfa2  = (const float*)d_in[15];
    const float* w_fc2   = (const float*)d_in[16];
    const float* w_am2   = (const float*)d_in[17];
    const float* s_am2   = (const float*)d_in[18];
    const float* b_am2   = (const float*)d_in[19];
    const float* w_mlp2  = (const float*)d_in[20];
    const float* s_mlp2  = (const float*)d_in[21];
    const float* b_mlp2  = (const float*)d_in[22];
    const float* w_sc    = (const float*)d_in[23];
    const float* s_sc    = (const float*)d_in[24];
    const float* b_sc    = (const float*)d_in[25];
    float* out = (float*)d_out;

    cudaFuncSetAttribute(kern_att1, cudaFuncAttributeMaxDynamicSharedMemorySize, K2_SMEM_BYTES);
    cudaFuncSetAttribute(kern_att2, cudaFuncAttributeMaxDynamicSharedMemorySize, K3_SMEM_BYTES);
    cudaFuncSetAttribute(kern_out,  cudaFuncAttributeMaxDynamicSharedMemorySize, OUT_SMEM_BYTES);

    kern_mlp1<<<2048, 256>>>(feature, w_mlp1, s_mlp1, b_mlp1);

    kern_att1<<<148, 448, K2_SMEM_BYTES>>>(
        xyz, neigh,
        w_lfa1, s_lfa1, b_lfa1,
        w_fc1,
        w_am1, s_am1, b_am1);

    kern_att2<<<148, 448, K3_SMEM_BYTES>>>(
        xyz, neigh,
        w_lfa1, s_lfa1, b_lfa1,
        w_lfa2, s_lfa2, b_lfa2,
        w_fc2);

    kern_out<<<148, 384, OUT_SMEM_BYTES>>>(
        feature,
        w_am2, s_am2, b_am2,
        w_mlp2, s_mlp2, b_mlp2,
        w_sc, s_sc, b_sc,
        out);
}

// round 11
// speedup vs baseline: 1.1146x; 1.1146x over previous
#include <cuda_runtime.h>
#include <cuda_fp16.h>
#include <math.h>

#define BATCH 4
#define NPTS  40960
#define KNN   16
#define P_TOTAL (BATCH * NPTS)   // 163840

#define FS_H2  36    // fs tile row stride in half2 units (4 mod 32)
#define LG_PAD 66    // logits tile row stride (floats)
#define WH64   68    // fp16 B-tile stride, 64 cols, uint2 units
#define WH32   36    // fp16 B-tile stride, 32 cols, uint2 units
#define P2F64  68    // float2 B-tile stride, 64 cols (4 mod 16)
#define P2F128 132   // float2 B-tile stride, 128 cols (4 mod 16)
#define RP2    12    // relpos tile stride in half2 units
#define OA_PAD 100   // kern_out A tile stride (4 mod 32)

// Scratch (device globals)
__device__ float   g_f_pc [P_TOTAL * 32];                    // 21 MB
__device__ float   g_f_agg[P_TOTAL * 32];                    // 21 MB
__device__ float   g_agg2 [(size_t)P_TOTAL * 64];            // 42 MB
__device__ __half2 g_fx2  [(size_t)P_TOTAL * KNN * 16];      // 168 MB

__device__ __forceinline__ float to_tf32(float x) {
    float r;
    asm("cvt.rna.tf32.f32 %0, %1;" : "=f"(r) : "f"(x));
    return r;
}
__device__ __forceinline__ unsigned f2_to_u(float a, float b) {
    __half2 h = __floats2half2_rn(a, b);
    return *(unsigned*)&h;
}

__device__ __forceinline__ void mma_tf32(float* c,
                                         unsigned a0, unsigned a1, unsigned a2, unsigned a3,
                                         unsigned b0, unsigned b1) {
    asm("mma.sync.aligned.m16n8k8.row.col.f32.tf32.tf32.f32 "
        "{%0,%1,%2,%3}, {%4,%5,%6,%7}, {%8,%9}, {%0,%1,%2,%3};"
        : "+f"(c[0]), "+f"(c[1]), "+f"(c[2]), "+f"(c[3])
        : "r"(a0), "r"(a1), "r"(a2), "r"(a3), "r"(b0), "r"(b1));
}
__device__ __forceinline__ void mma_f16(float* c,
                                        unsigned a0, unsigned a1, unsigned a2, unsigned a3,
                                        unsigned b0, unsigned b1) {
    asm("mma.sync.aligned.m16n8k16.row.col.f32.f16.f16.f32 "
        "{%0,%1,%2,%3}, {%4,%5,%6,%7}, {%8,%9}, {%0,%1,%2,%3};"
        : "+f"(c[0]), "+f"(c[1]), "+f"(c[2]), "+f"(c[3])
        : "r"(a0), "r"(a1), "r"(a2), "r"(a3), "r"(b0), "r"(b1));
}

// dual-point logits: fs0/fs1 fp16 tiles share the B reads
__device__ __forceinline__ void logits_f16_x2(const unsigned* __restrict__ fsw0,
                                              const unsigned* __restrict__ fsw1,
                                              float* __restrict__ lg0,
                                              float* __restrict__ lg1,
                                              const uint2* __restrict__ wfc, int lane)
{
    const int gid = lane >> 2;
    const int tig = lane & 3;
    float ac0[8][4], ac1[8][4];
    #pragma unroll
    for (int n = 0; n < 8; n++)
        #pragma unroll
        for (int j = 0; j < 4; j++) { ac0[n][j] = 0.f; ac1[n][j] = 0.f; }
    #pragma unroll
    for (int q = 0; q < 4; q++) {
        unsigned a00 = fsw0[gid * FS_H2 + q * 8 + tig];
        unsigned a01 = fsw0[(gid + 8) * FS_H2 + q * 8 + tig];
        unsigned a02 = fsw0[gid * FS_H2 + q * 8 + tig + 4];
        unsigned a03 = fsw0[(gid + 8) * FS_H2 + q * 8 + tig + 4];
        unsigned a10 = fsw1[gid * FS_H2 + q * 8 + tig];
        unsigned a11 = fsw1[(gid + 8) * FS_H2 + q * 8 + tig];
        unsigned a12 = fsw1[gid * FS_H2 + q * 8 + tig + 4];
        unsigned a13 = fsw1[(gid + 8) * FS_H2 + q * 8 + tig + 4];
        const uint2* br = wfc + (q * 4 + tig) * WH64 + gid;
        #pragma unroll
        for (int n = 0; n < 8; n++) {
            uint2 b = br[8 * n];
            mma_f16(ac0[n], a00, a01, a02, a03, b.x, b.y);
            mma_f16(ac1[n], a10, a11, a12, a13, b.x, b.y);
        }
    }
    #pragma unroll
    for (int n = 0; n < 8; n++) {
        *(float2*)(lg0 + gid * LG_PAD + n * 8 + 2 * tig)       = make_float2(ac0[n][0], ac0[n][1]);
        *(float2*)(lg0 + (gid + 8) * LG_PAD + n * 8 + 2 * tig) = make_float2(ac0[n][2], ac0[n][3]);
        *(float2*)(lg1 + gid * LG_PAD + n * 8 + 2 * tig)       = make_float2(ac1[n][0], ac1[n][1]);
        *(float2*)(lg1 + (gid + 8) * LG_PAD + n * 8 + 2 * tig) = make_float2(ac1[n][2], ac1[n][3]);
    }
}

__device__ __forceinline__ float att_pool_reg(const float* __restrict__ lg_s,
                                              const float* __restrict__ vals, int ch)
{
    float l[KNN];
    float m = -1e30f;
    #pragma unroll
    for (int k = 0; k < KNN; k++) { l[k] = lg_s[k * LG_PAD + ch]; m = fmaxf(m, l[k]); }
    float s = 0.f, a = 0.f;
    #pragma unroll
    for (int k = 0; k < KNN; k++) {
        float e = __expf(l[k] - m);
        s += e;
        a += e * vals[k];
    }
    return __fdividef(a, s);
}

__device__ __forceinline__ float att_pool_h(const float* __restrict__ lg_s,
                                            const __half2* __restrict__ fs_h, int lane)
{
    const int ch = 32 + lane;
    float vals[KNN];
    #pragma unroll
    for (int k = 0; k < KNN; k++) {
        __half2 h = fs_h[k * FS_H2 + 16 + (lane >> 1)];
        vals[k] = (lane & 1) ? __high2float(h) : __low2float(h);
    }
    return att_pool_reg(lg_s, vals, ch);
}

// ---------------------------------------------------------------------------
// Kernel 1: f_pc = ReLU((feature @ w_mlp1) * s + b)
// weight column held in registers (loop-invariant per lane)
// ---------------------------------------------------------------------------
__global__ __launch_bounds__(256) void kern_mlp1(
    const float* __restrict__ feature,
    const float* __restrict__ w, const float* __restrict__ s, const float* __restrict__ b)
{
    __shared__ float xs[8][32];

    const int lane = threadIdx.x & 31;
    const int warp = threadIdx.x >> 5;

    float wcol[32];
    #pragma unroll
    for (int j = 0; j < 32; j++) wcol[j] = w[j * 32 + lane];
    const float sv = s[lane];
    const float bv = b[lane];

    const int nwarps = (gridDim.x * blockDim.x) >> 5;
    int gw = (blockIdx.x * blockDim.x + threadIdx.x) >> 5;

    for (int p = gw; p < P_TOTAL; p += nwarps) {
        xs[warp][lane] = feature[(size_t)p * 32 + lane];
        __syncwarp();
        float acc = 0.f;
        #pragma unroll
        for (int j4 = 0; j4 < 32; j4 += 4) {
            float4 f = *(const float4*)(&xs[warp][j4]);
            acc += f.x * wcol[j4] + f.y * wcol[j4 + 1]
                 + f.z * wcol[j4 + 2] + f.w * wcol[j4 + 3];
        }
        g_f_pc[(size_t)p * 32 + lane] = fmaxf(acc * sv + bv, 0.f);
        __syncwarp();
    }
}

// ---------------------------------------------------------------------------
// Kernel 2 (Round-9 version): TWO points per warp. rel_pos + lfa1(f16) +
//           gather + logits(f16) + pool + f_agg ; lfa2(f16) -> g_fx2
// ---------------------------------------------------------------------------
#define K2_WARP_FLOATS 3392
#define K2_BASE_FLOATS 5216
#define K2_WARPS 12
#define K2_SMEM_BYTES ((K2_BASE_FLOATS + K2_WARPS * K2_WARP_FLOATS) * 4)

__global__ __launch_bounds__(384) void kern_att1(
    const float* __restrict__ xyz, const int* __restrict__ neigh,
    const float* __restrict__ wlfa1, const float* __restrict__ slfa1, const float* __restrict__ blfa1,
    const float* __restrict__ wfc1,
    const float* __restrict__ wam1, const float* __restrict__ sam1, const float* __restrict__ bam1,
    const float* __restrict__ wlfa2, const float* __restrict__ slfa2, const float* __restrict__ blfa2)
{
    extern __shared__ float sm[];
    uint2*  s_wfcp = (uint2*)sm;              // [16][68] uint2 = 2176 floats
    float2* s_wamp = (float2*)(sm + 2176);    // [32][32] float2 = 2048 floats
    uint2*  s_wl1p = (uint2*)(sm + 4224);     // [4][36] uint2 = 288 floats
    uint2*  s_wl2p = (uint2*)(sm + 4512);     // [8][36] uint2 = 576 floats
    float*  s_vec  = sm + 5088;               // 128: blfa1, blfa2, bam1
    float*  s_wrp  = sm + K2_BASE_FLOATS;

    for (int i = threadIdx.x; i < 1024; i += blockDim.x) {
        int r = i >> 6, c = i & 63;
        int q = r >> 2, t = r & 3;
        int k0 = 16 * q + 2 * t;
        s_wfcp[r * WH64 + c] = make_uint2(
            f2_to_u(wfc1[k0 * 64 + c], wfc1[(k0 + 1) * 64 + c]),
            f2_to_u(wfc1[(k0 + 8) * 64 + c], wfc1[(k0 + 9) * 64 + c]));
    }
    for (int i = threadIdx.x; i < 1024; i += blockDim.x) {
        int r = i >> 5, c = i & 31;
        s_wamp[r * 32 + c] = make_float2(wam1[(2 * r) * 32 + c] * sam1[c],
                                         wam1[(2 * r + 1) * 32 + c] * sam1[c]);
    }
    for (int i = threadIdx.x; i < 128; i += blockDim.x) {
        int t = i >> 5, c = i & 31;
        int k0 = 2 * t, k1 = 2 * t + 8;
        float w00 = wlfa1[k0 * 32 + c] * slfa1[c];
        float w01 = wlfa1[(k0 + 1) * 32 + c] * slfa1[c];
        float w10 = (k1 < 10) ? wlfa1[k1 * 32 + c] * slfa1[c] : 0.f;
        float w11 = (k1 + 1 < 10) ? wlfa1[(k1 + 1) * 32 + c] * slfa1[c] : 0.f;
        s_wl1p[t * WH32 + c] = make_uint2(f2_to_u(w00, w01), f2_to_u(w10, w11));
    }
    for (int i = threadIdx.x; i < 256; i += blockDim.x) {
        int r = i >> 5, c = i & 31;
        int q = r >> 2, t = r & 3;
        int k0 = 16 * q + 2 * t;
        s_wl2p[r * WH32 + c] = make_uint2(
            f2_to_u(wlfa2[k0 * 32 + c] * slfa2[c], wlfa2[(k0 + 1) * 32 + c] * slfa2[c]),
            f2_to_u(wlfa2[(k0 + 8) * 32 + c] * slfa2[c], wlfa2[(k0 + 9) * 32 + c] * slfa2[c]));
    }
    if (threadIdx.x < 32) {
        int l = threadIdx.x;
        s_vec[l]      = blfa1[l];
        s_vec[32 + l] = blfa2[l];
        s_vec[64 + l] = bam1[l];
    }
    __syncthreads();

    const int lane = threadIdx.x & 31;
    const int warp = threadIdx.x >> 5;
    const int gid = lane >> 2, tig = lane & 3;
    float* wbase = s_wrp + warp * K2_WARP_FLOATS;
    __half2*  fs0_h = (__half2*)wbase;            // [16][36] half2
    __half2*  fs1_h = (__half2*)(wbase + 576);
    unsigned* fsw0  = (unsigned*)fs0_h;
    unsigned* fsw1  = (unsigned*)fs1_h;
    float* lg0  = wbase + 1152;                   // [16][66]
    float* lg1  = wbase + 2208;
    __half2* rp0 = (__half2*)lg0;                 // aliases lg (dead before logits)
    __half2* rp1 = (__half2*)lg1;
    unsigned* rp0w = (unsigned*)rp0;
    unsigned* rp1w = (unsigned*)rp1;
    float* agg_s = wbase + 3264;                  // [128]

    const int nwarps = (gridDim.x * blockDim.x) >> 5;
    int gw = (blockIdx.x * blockDim.x + threadIdx.x) >> 5;

    for (int pp = gw; pp < P_TOTAL / 2; pp += nwarps) {
        const int p0 = 2 * pp, p1 = p0 + 1;
        const int b = p0 / NPTS;
        const size_t bbase = (size_t)b * NPTS;

        int idx = neigh[(size_t)p0 * KNN + lane];

        float gv0[KNN], gv1[KNN];
        #pragma unroll
        for (int k = 0; k < KNN; k++) {
            int nb = __shfl_sync(0xffffffffu, idx, k);
            gv0[k] = g_f_pc[(bbase + (size_t)nb) * 32 + lane];
        }
        #pragma unroll
        for (int k = 0; k < KNN; k++) {
            int nb = __shfl_sync(0xffffffffu, idx, 16 + k);
            gv1[k] = g_f_pc[(bbase + (size_t)nb) * 32 + lane];
        }

        {
            const int myp = (lane < 16) ? p0 : p1;
            const int krow = lane & 15;
            float cx = xyz[(size_t)myp * 3 + 0];
            float cy = xyz[(size_t)myp * 3 + 1];
            float cz = xyz[(size_t)myp * 3 + 2];
            size_t nb = bbase + (size_t)idx;
            float nx = xyz[nb * 3 + 0], ny = xyz[nb * 3 + 1], nz = xyz[nb * 3 + 2];
            float rx = cx - nx, ry = cy - ny, rz = cz - nz;
            float d = sqrtf(rx * rx + ry * ry + rz * rz);
            __half2* rp = (lane < 16) ? rp0 : rp1;
            __half2 z = __floats2half2_rn(0.f, 0.f);
            rp[krow * RP2 + 0] = __floats2half2_rn(d, rx);
            rp[krow * RP2 + 1] = __floats2half2_rn(ry, rz);
            rp[krow * RP2 + 2] = __floats2half2_rn(cx, cy);
            rp[krow * RP2 + 3] = __floats2half2_rn(cz, nx);
            rp[krow * RP2 + 4] = __floats2half2_rn(ny, nz);
            rp[krow * RP2 + 5] = z;
            rp[krow * RP2 + 6] = z;
            rp[krow * RP2 + 7] = z;
        }
        __syncwarp();

        // lfa1 via f16 mma (K=16 covers all 10 rows), B shared
        {
            unsigned a00 = rp0w[gid * RP2 + tig];
            unsigned a01 = rp0w[(gid + 8) * RP2 + tig];
            unsigned a02 = rp0w[gid * RP2 + tig + 4];
            unsigned a03 = rp0w[(gid + 8) * RP2 + tig + 4];
            unsigned a10 = rp1w[gid * RP2 + tig];
            unsigned a11 = rp1w[(gid + 8) * RP2 + tig];
            unsigned a12 = rp1w[gid * RP2 + tig + 4];
            unsigned a13 = rp1w[(gid + 8) * RP2 + tig + 4];
            float ac0[4][4], ac1[4][4];
            #pragma unroll
            for (int n = 0; n < 4; n++)
                #pragma unroll
                for (int j = 0; j < 4; j++) { ac0[n][j] = 0.f; ac1[n][j] = 0.f; }
            const uint2* br = s_wl1p + tig * WH32 + gid;
            #pragma unroll
            for (int n = 0; n < 4; n++) {
                uint2 bb = br[8 * n];
                mma_f16(ac0[n], a00, a01, a02, a03, bb.x, bb.y);
                mma_f16(ac1[n], a10, a11, a12, a13, bb.x, bb.y);
            }
            #pragma unroll
            for (int n = 0; n < 4; n++) {
                int c0 = n * 8 + 2 * tig;
                float b0 = s_vec[c0], b1 = s_vec[c0 + 1];
                fs0_h[gid * FS_H2 + 16 + n * 4 + tig] =
                    __floats2half2_rn(fmaxf(ac0[n][0] + b0, 0.f), fmaxf(ac0[n][1] + b1, 0.f));
                fs0_h[(gid + 8) * FS_H2 + 16 + n * 4 + tig] =
                    __floats2half2_rn(fmaxf(ac0[n][2] + b0, 0.f), fmaxf(ac0[n][3] + b1, 0.f));
                fs1_h[gid * FS_H2 + 16 + n * 4 + tig] =
                    __floats2half2_rn(fmaxf(ac1[n][0] + b0, 0.f), fmaxf(ac1[n][1] + b1, 0.f));
                fs1_h[(gid + 8) * FS_H2 + 16 + n * 4 + tig] =
                    __floats2half2_rn(fmaxf(ac1[n][2] + b0, 0.f), fmaxf(ac1[n][3] + b1, 0.f));
            }
        }

        #pragma unroll
        for (int k = 0; k < KNN; k++) {
            float v0 = gv0[k];
            float v1 = __shfl_xor_sync(0xffffffffu, v0, 1);
            if (!(lane & 1))
                fs0_h[k * FS_H2 + (lane >> 1)] = __floats2half2_rn(v0, v1);
        }
        #pragma unroll
        for (int k = 0; k < KNN; k++) {
            float v0 = gv1[k];
            float v1 = __shfl_xor_sync(0xffffffffu, v0, 1);
            if (!(lane & 1))
                fs1_h[k * FS_H2 + (lane >> 1)] = __floats2half2_rn(v0, v1);
        }
        __syncwarp();

        logits_f16_x2(fsw0, fsw1, lg0, lg1, s_wfcp, lane);
        __syncwarp();
        agg_s[lane]       = att_pool_reg(lg0, gv0, lane);
        agg_s[32 + lane]  = att_pool_h(lg0, fs0_h, lane);
        agg_s[64 + lane]  = att_pool_reg(lg1, gv1, lane);
        agg_s[96 + lane]  = att_pool_h(lg1, fs1_h, lane);
        __syncwarp();

        // f_agg for both points, wam read once
        {
            float acc0 = 0.f, acc1 = 0.f;
            #pragma unroll
            for (int d2 = 0; d2 < 32; d2 += 2) {
                float4 a0 = *(const float4*)(agg_s + 2 * d2);
                float4 a1 = *(const float4*)(agg_s + 64 + 2 * d2);
                float2 w0 = s_wamp[d2 * 32 + lane];
                float2 w1 = s_wamp[(d2 + 1) * 32 + lane];
                acc0 += a0.x * w0.x + a0.y * w0.y + a0.z * w1.x + a0.w * w1.y;
                acc1 += a1.x * w0.x + a1.y * w0.y + a1.z * w1.x + a1.w * w1.y;
            }
            float bb = s_vec[64 + lane];
            g_f_agg[(size_t)p0 * 32 + lane] = fmaxf(acc0 + bb, 0.f);
            g_f_agg[(size_t)p1 * 32 + lane] = fmaxf(acc1 + bb, 0.f);
        }

        // lfa2 via f16 mma, B shared -> g_fx2
        {
            float ac0[4][4], ac1[4][4];
            #pragma unroll
            for (int n = 0; n < 4; n++)
                #pragma unroll
                for (int j = 0; j < 4; j++) { ac0[n][j] = 0.f; ac1[n][j] = 0.f; }
            #pragma unroll
            for (int q = 0; q < 2; q++) {
                unsigned a00 = fsw0[gid * FS_H2 + 16 + q * 8 + tig];
                unsigned a01 = fsw0[(gid + 8) * FS_H2 + 16 + q * 8 + tig];
                unsigned a02 = fsw0[gid * FS_H2 + 16 + q * 8 + tig + 4];
                unsigned a03 = fsw0[(gid + 8) * FS_H2 + 16 + q * 8 + tig + 4];
                unsigned a10 = fsw1[gid * FS_H2 + 16 + q * 8 + tig];
                unsigned a11 = fsw1[(gid + 8) * FS_H2 + 16 + q * 8 + tig];
                unsigned a12 = fsw1[gid * FS_H2 + 16 + q * 8 + tig + 4];
                unsigned a13 = fsw1[(gid + 8) * FS_H2 + 16 + q * 8 + tig + 4];
                const uint2* br = s_wl2p + (q * 4 + tig) * WH32 + gid;
                #pragma unroll
                for (int n = 0; n < 4; n++) {
                    uint2 bb = br[8 * n];
                    mma_f16(ac0[n], a00, a01, a02, a03, bb.x, bb.y);
                    mma_f16(ac1[n], a10, a11, a12, a13, bb.x, bb.y);
                }
            }
            #pragma unroll
            for (int n = 0; n < 4; n++) {
                int c0 = n * 8 + 2 * tig;
                float b0 = s_vec[32 + c0], b1 = s_vec[32 + c0 + 1];
                g_fx2[((size_t)p0 * KNN + gid) * 16 + (c0 >> 1)] =
                    __floats2half2_rn(fmaxf(ac0[n][0] + b0, 0.f), fmaxf(ac0[n][1] + b1, 0.f));
                g_fx2[((size_t)p0 * KNN + gid + 8) * 16 + (c0 >> 1)] =
                    __floats2half2_rn(fmaxf(ac0[n][2] + b0, 0.f), fmaxf(ac0[n][3] + b1, 0.f));
                g_fx2[((size_t)p1 * KNN + gid) * 16 + (c0 >> 1)] =
                    __floats2half2_rn(fmaxf(ac1[n][0] + b0, 0.f), fmaxf(ac1[n][1] + b1, 0.f));
                g_fx2[((size_t)p1 * KNN + gid + 8) * 16 + (c0 >> 1)] =
                    __floats2half2_rn(fmaxf(ac1[n][2] + b0, 0.f), fmaxf(ac1[n][3] + b1, 0.f));
            }
        }
        __syncwarp();
    }
}

// ---------------------------------------------------------------------------
// Kernel 3 (Round-9 version): TWO points per warp: gather(f_agg) + fx2 +
//           logits(shared B) + pools -> g_agg2
// ---------------------------------------------------------------------------
#define K3_WARP_FLOATS 3264
#define K3_BASE_FLOATS 2176
#define K3_WARPS 14
#define K3_SMEM_BYTES ((K3_BASE_FLOATS + K3_WARPS * K3_WARP_FLOATS) * 4)

__global__ __launch_bounds__(448) void kern_att2(
    const int* __restrict__ neigh,
    const float* __restrict__ wfc2)
{
    extern __shared__ float sm[];
    uint2* s_wfcp = (uint2*)sm;               // [16][68] uint2
    float* s_wrp  = sm + K3_BASE_FLOATS;

    for (int i = threadIdx.x; i < 1024; i += blockDim.x) {
        int r = i >> 6, c = i & 63;
        int q = r >> 2, t = r & 3;
        int k0 = 16 * q + 2 * t;
        s_wfcp[r * WH64 + c] = make_uint2(
            f2_to_u(wfc2[k0 * 64 + c], wfc2[(k0 + 1) * 64 + c]),
            f2_to_u(wfc2[(k0 + 8) * 64 + c], wfc2[(k0 + 9) * 64 + c]));
    }
    __syncthreads();

    const int lane = threadIdx.x & 31;
    const int warp = threadIdx.x >> 5;
    float* wbase = s_wrp + warp * K3_WARP_FLOATS;
    __half2*  fs0_h = (__half2*)wbase;
    __half2*  fs1_h = (__half2*)(wbase + 576);
    unsigned* fsw0  = (unsigned*)fs0_h;
    unsigned* fsw1  = (unsigned*)fs1_h;
    float* lg0 = wbase + 1152;
    float* lg1 = wbase + 2208;

    const int kk = lane >> 4;
    const int jj = lane & 15;

    const int nwarps = (gridDim.x * blockDim.x) >> 5;
    int gw = (blockIdx.x * blockDim.x + threadIdx.x) >> 5;

    for (int pp = gw; pp < P_TOTAL / 2; pp += nwarps) {
        const int p0 = 2 * pp, p1 = p0 + 1;
        const int b = p0 / NPTS;
        const size_t bbase = (size_t)b * NPTS;

        int idx = neigh[(size_t)p0 * KNN + lane];

        float gv0[KNN], gv1[KNN];
        #pragma unroll
        for (int k = 0; k < KNN; k++) {
            int nb = __shfl_sync(0xffffffffu, idx, k);
            gv0[k] = g_f_agg[(bbase + (size_t)nb) * 32 + lane];
        }
        #pragma unroll
        for (int k = 0; k < KNN; k++) {
            int nb = __shfl_sync(0xffffffffu, idx, 16 + k);
            gv1[k] = g_f_agg[(bbase + (size_t)nb) * 32 + lane];
        }
        #pragma unroll
        for (int k = 0; k < KNN; k++) {
            float v0 = gv0[k];
            float v1 = __shfl_xor_sync(0xffffffffu, v0, 1);
            if (!(lane & 1))
                fs0_h[k * FS_H2 + (lane >> 1)] = __floats2half2_rn(v0, v1);
        }
        #pragma unroll
        for (int k = 0; k < KNN; k++) {
            float v0 = gv1[k];
            float v1 = __shfl_xor_sync(0xffffffffu, v0, 1);
            if (!(lane & 1))
                fs1_h[k * FS_H2 + (lane >> 1)] = __floats2half2_rn(v0, v1);
        }
        const unsigned* src0 = (const unsigned*)(g_fx2 + (size_t)p0 * KNN * 16);
        const unsigned* src1 = (const unsigned*)(g_fx2 + (size_t)p1 * KNN * 16);
        #pragma unroll
        for (int k = 0; k < KNN; k += 2) {
            fsw0[(k + kk) * FS_H2 + 16 + jj] = src0[(k + kk) * 16 + jj];
            fsw1[(k + kk) * FS_H2 + 16 + jj] = src1[(k + kk) * 16 + jj];
        }
        __syncwarp();

        logits_f16_x2(fsw0, fsw1, lg0, lg1, s_wfcp, lane);
        __syncwarp();

        g_agg2[(size_t)p0 * 64 + lane]      = att_pool_reg(lg0, gv0, lane);
        g_agg2[(size_t)p0 * 64 + 32 + lane] = att_pool_h(lg0, fs0_h, lane);
        g_agg2[(size_t)p1 * 64 + lane]      = att_pool_reg(lg1, gv1, lane);
        g_agg2[(size_t)p1 * 64 + 32 + lane] = att_pool_h(lg1, fs1_h, lane);
        __syncwarp();
    }
}

// ---------------------------------------------------------------------------
// Kernel 4: 16-point tiles, SINGLE TF32 GEMMs with float2-packed B.
//           pc2 = relu(agg2@w1+b1) into combined [pc2;feat] K=96 A tile;
//           out = leaky(A @ w23 + b2).
// ---------------------------------------------------------------------------
#define OUT_WARPS 16
#define OUT_BASE_FLOATS 17216  // w1p 4352 + w23p 12672 + b1 64 + b2 128
#define OUT_WARP_FLOATS 1600   // A [16][100]
#define OUT_SMEM_BYTES ((OUT_BASE_FLOATS + OUT_WARPS * OUT_WARP_FLOATS) * 4)

__global__ __launch_bounds__(512) void kern_out(
    const float* __restrict__ feature,
    const float* __restrict__ wam2, const float* __restrict__ sam2, const float* __restrict__ bam2,
    const float* __restrict__ wmlp2, const float* __restrict__ smlp2, const float* __restrict__ bmlp2,
    const float* __restrict__ wsc, const float* __restrict__ ssc, const float* __restrict__ bsc,
    float* __restrict__ out)
{
    extern __shared__ float sm[];
    float2* w1p  = (float2*)sm;              // [32][68] float2 = 4352 floats
    float2* w23p = (float2*)(sm + 4352);     // [48][132] float2 = 12672 floats
    float*  b1   = sm + 17024;               // [64]
    float*  b2   = sm + 17088;               // [128]
    float*  wrp  = sm + OUT_BASE_FLOATS;

    for (int i = threadIdx.x; i < 2048; i += blockDim.x) {
        int r = i >> 6, c = i & 63;
        int k0 = (r >> 2) * 8 + (r & 3), k1 = k0 + 4;
        w1p[r * P2F64 + c] = make_float2(to_tf32(wam2[k0 * 64 + c] * sam2[c]),
                                         to_tf32(wam2[k1 * 64 + c] * sam2[c]));
    }
    for (int i = threadIdx.x; i < 6144; i += blockDim.x) {
        int r = i >> 7, c = i & 127;
        int k0 = (r >> 2) * 8 + (r & 3), k1 = k0 + 4;
        float v0 = (k0 < 64) ? wmlp2[k0 * 128 + c] * smlp2[c] : wsc[(k0 - 64) * 128 + c] * ssc[c];
        float v1 = (k1 < 64) ? wmlp2[k1 * 128 + c] * smlp2[c] : wsc[(k1 - 64) * 128 + c] * ssc[c];
        w23p[r * P2F128 + c] = make_float2(to_tf32(v0), to_tf32(v1));
    }
    if (threadIdx.x < 64)  b1[threadIdx.x] = bam2[threadIdx.x];
    if (threadIdx.x < 128) b2[threadIdx.x] = bmlp2[threadIdx.x] + bsc[threadIdx.x];
    __syncthreads();

    const int lane = threadIdx.x & 31;
    const int warp = threadIdx.x >> 5;
    const int gid = lane >> 2, tig = lane & 3;
    float* A1 = wrp + warp * OUT_WARP_FLOATS;  // [16][100]

    const int nwarps = (gridDim.x * blockDim.x) >> 5;
    int gw = (blockIdx.x * blockDim.x + threadIdx.x) >> 5;
    const int ntiles = P_TOTAL / 16;

    for (int t = gw; t < ntiles; t += nwarps) {
        const int p0 = t * 16;

        #pragma unroll
        for (int r = 0; r < 16; r++) {
            A1[r * OA_PAD + lane]      = g_agg2[(size_t)(p0 + r) * 64 + lane];
            A1[r * OA_PAD + 32 + lane] = g_agg2[(size_t)(p0 + r) * 64 + 32 + lane];
            A1[r * OA_PAD + 64 + lane] = feature[(size_t)(p0 + r) * 32 + lane];
        }
        __syncwarp();

        // GEMM1 (single tf32): pc2 = relu(agg @ w1 + b1) -> A cols 0..63
        {
            float acc[8][4];
            #pragma unroll
            for (int n = 0; n < 8; n++) { acc[n][0]=0.f; acc[n][1]=0.f; acc[n][2]=0.f; acc[n][3]=0.f; }
            #pragma unroll
            for (int q = 0; q < 8; q++) {
                unsigned a0 = __float_as_uint(to_tf32(A1[gid * OA_PAD + q * 8 + tig]));
                unsigned a1 = __float_as_uint(to_tf32(A1[(gid + 8) * OA_PAD + q * 8 + tig]));
                unsigned a2 = __float_as_uint(to_tf32(A1[gid * OA_PAD + q * 8 + tig + 4]));
                unsigned a3 = __float_as_uint(to_tf32(A1[(gid + 8) * OA_PAD + q * 8 + tig + 4]));
                const float2* br = w1p + (q * 4 + tig) * P2F64 + gid;
                #pragma unroll
                for (int n = 0; n < 8; n++) {
                    float2 b = br[8 * n];
                    mma_tf32(acc[n], a0, a1, a2, a3,
                             __float_as_uint(b.x), __float_as_uint(b.y));
                }
            }
            __syncwarp();
            #pragma unroll
            for (int n = 0; n < 8; n++) {
                int c0 = n * 8 + 2 * tig;
                float bb0 = b1[c0], bb1 = b1[c0 + 1];
                *(float2*)(A1 + gid * OA_PAD + c0) =
                    make_float2(fmaxf(acc[n][0] + bb0, 0.f), fmaxf(acc[n][1] + bb1, 0.f));
                *(float2*)(A1 + (gid + 8) * OA_PAD + c0) =
                    make_float2(fmaxf(acc[n][2] + bb0, 0.f), fmaxf(acc[n][3] + bb1, 0.f));
            }
        }
        __syncwarp();

        // GEMM2 (single tf32): out = leaky(A[16][96] @ w23 + b2), two n-halves
        #pragma unroll
        for (int h = 0; h < 2; h++) {
            float acc[8][4];
            #pragma unroll
            for (int n = 0; n < 8; n++) { acc[n][0]=0.f; acc[n][1]=0.f; acc[n][2]=0.f; acc[n][3]=0.f; }
            #pragma unroll
            for (int q = 0; q < 12; q++) {
                unsigned a0 = __float_as_uint(to_tf32(A1[gid * OA_PAD + q * 8 + tig]));
                unsigned a1 = __float_as_uint(to_tf32(A1[(gid + 8) * OA_PAD + q * 8 + tig]));
                unsigned a2 = __float_as_uint(to_tf32(A1[gid * OA_PAD + q * 8 + tig + 4]));
                unsigned a3 = __float_as_uint(to_tf32(A1[(gid + 8) * OA_PAD + q * 8 + tig + 4]));
                const float2* br = w23p + (q * 4 + tig) * P2F128 + h * 64 + gid;
                #pragma unroll
                for (int n = 0; n < 8; n++) {
                    float2 b = br[8 * n];
                    mma_tf32(acc[n], a0, a1, a2, a3,
                             __float_as_uint(b.x), __float_as_uint(b.y));
                }
            }
            #pragma unroll
            for (int n = 0; n < 8; n++) {
                int c0 = h * 64 + n * 8 + 2 * tig;
                float bb0 = b2[c0], bb1 = b2[c0 + 1];
                float v0 = acc[n][0] + bb0; v0 = (v0 < 0.f) ? 0.2f * v0 : v0;
                float v1 = acc[n][1] + bb1; v1 = (v1 < 0.f) ? 0.2f * v1 : v1;
                float v2 = acc[n][2] + bb0; v2 = (v2 < 0.f) ? 0.2f * v2 : v2;
                float v3 = acc[n][3] + bb1; v3 = (v3 < 0.f) ? 0.2f * v3 : v3;
                *(float2*)(&out[(size_t)(p0 + gid) * 128 + c0])     = make_float2(v0, v1);
                *(float2*)(&out[(size_t)(p0 + gid + 8) * 128 + c0]) = make_float2(v2, v3);
            }
        }
        __syncwarp();
    }
}

// ---------------------------------------------------------------------------
extern "C" void kernel_launch(void* const* d_in, const int* in_sizes, int n_in,
                              void* d_out, int out_size)
{
    const float* feature = (const float*)d_in[0];
    const float* xyz     = (const float*)d_in[1];
    const int*   neigh   = (const int*)  d_in[2];
    const float* w_mlp1  = (const float*)d_in[3];
    const float* s_mlp1  = (const float*)d_in[4];
    const float* b_mlp1  = (const float*)d_in[5];
    const float* w_lfa1  = (const float*)d_in[6];
    const float* s_lfa1  = (const float*)d_in[7];
    const float* b_lfa1  = (const float*)d_in[8];
    const float* w_fc1   = (const float*)d_in[9];
    const float* w_am1   = (const float*)d_in[10];
    const float* s_am1   = (const float*)d_in[11];
    const float* b_am1   = (const float*)d_in[12];
    const float* w_lfa2  = (const float*)d_in[13];
    const float* s_lfa2  = (const float*)d_in[14];
    const float* b_lfa2  = (const float*)d_in[15];
    const float* w_fc2   = (const float*)d_in[16];
    const float* w_am2   = (const float*)d_in[17];
    const float* s_am2   = (const float*)d_in[18];
    const float* b_am2   = (const float*)d_in[19];
    const float* w_mlp2  = (const float*)d_in[20];
    const float* s_mlp2  = (const float*)d_in[21];
    const float* b_mlp2  = (const float*)d_in[22];
    const float* w_sc    = (const float*)d_in[23];
    const float* s_sc    = (const float*)d_in[24];
    const float* b_sc    = (const float*)d_in[25];
    float* out = (float*)d_out;

    cudaFuncSetAttribute(kern_att1, cudaFuncAttributeMaxDynamicSharedMemorySize, K2_SMEM_BYTES);
    cudaFuncSetAttribute(kern_att2, cudaFuncAttributeMaxDynamicSharedMemorySize, K3_SMEM_BYTES);
    cudaFuncSetAttribute(kern_out,  cudaFuncAttributeMaxDynamicSharedMemorySize, OUT_SMEM_BYTES);

    kern_mlp1<<<2048, 256>>>(feature, w_mlp1, s_mlp1, b_mlp1);

    kern_att1<<<148, 384, K2_SMEM_BYTES>>>(
        xyz, neigh,
        w_lfa1, s_lfa1, b_lfa1,
        w_fc1,
        w_am1, s_am1, b_am1,
        w_lfa2, s_lfa2, b_lfa2);

    kern_att2<<<148, 448, K3_SMEM_BYTES>>>(neigh, w_fc2);

    kern_out<<<148, 512, OUT_SMEM_BYTES>>>(
        feature,
        w_am2, s_am2, b_am2,
        w_mlp2, s_mlp2, b_mlp2,
        w_sc, s_sc, b_sc,
        out);
}

// round 12
// speedup vs baseline: 1.1161x; 1.0014x over previous
#include <cuda_runtime.h>
#include <cuda_fp16.h>
#include <math.h>

#define BATCH 4
#define NPTS  40960
#define KNN   16
#define P_TOTAL (BATCH * NPTS)   // 163840

#define FS_H2  36    // fs tile row stride in half2 units (4 mod 32)
#define LG_PAD 66    // logits tile row stride (floats)
#define WH64   68    // fp16 B-tile stride, 64 cols, uint2 units
#define WH32   36    // fp16 B-tile stride, 32 cols, uint2 units
#define P2F64  68    // float2 B-tile stride, 64 cols (4 mod 16)
#define P2F128 132   // float2 B-tile stride, 128 cols (4 mod 16)
#define RP2    12    // relpos tile stride in half2 units
#define OA_PAD 100   // kern_out A tile stride (4 mod 32)

// Scratch (device globals)
__device__ float   g_f_pc [P_TOTAL * 32];                    // 21 MB
__device__ float   g_f_agg[P_TOTAL * 32];                    // 21 MB
__device__ float   g_agg2 [(size_t)P_TOTAL * 64];            // 42 MB
__device__ __half2 g_fx2  [(size_t)P_TOTAL * KNN * 16];      // 168 MB

__device__ __forceinline__ float to_tf32(float x) {
    float r;
    asm("cvt.rna.tf32.f32 %0, %1;" : "=f"(r) : "f"(x));
    return r;
}
__device__ __forceinline__ unsigned f2_to_u(float a, float b) {
    __half2 h = __floats2half2_rn(a, b);
    return *(unsigned*)&h;
}

__device__ __forceinline__ void mma_tf32(float* c,
                                         unsigned a0, unsigned a1, unsigned a2, unsigned a3,
                                         unsigned b0, unsigned b1) {
    asm("mma.sync.aligned.m16n8k8.row.col.f32.tf32.tf32.f32 "
        "{%0,%1,%2,%3}, {%4,%5,%6,%7}, {%8,%9}, {%0,%1,%2,%3};"
        : "+f"(c[0]), "+f"(c[1]), "+f"(c[2]), "+f"(c[3])
        : "r"(a0), "r"(a1), "r"(a2), "r"(a3), "r"(b0), "r"(b1));
}
__device__ __forceinline__ void mma_f16(float* c,
                                        unsigned a0, unsigned a1, unsigned a2, unsigned a3,
                                        unsigned b0, unsigned b1) {
    asm("mma.sync.aligned.m16n8k16.row.col.f32.f16.f16.f32 "
        "{%0,%1,%2,%3}, {%4,%5,%6,%7}, {%8,%9}, {%0,%1,%2,%3};"
        : "+f"(c[0]), "+f"(c[1]), "+f"(c[2]), "+f"(c[3])
        : "r"(a0), "r"(a1), "r"(a2), "r"(a3), "r"(b0), "r"(b1));
}

// dual-point logits: fs0/fs1 fp16 tiles share the B reads
__device__ __forceinline__ void logits_f16_x2(const unsigned* __restrict__ fsw0,
                                              const unsigned* __restrict__ fsw1,
                                              float* __restrict__ lg0,
                                              float* __restrict__ lg1,
                                              const uint2* __restrict__ wfc, int lane)
{
    const int gid = lane >> 2;
    const int tig = lane & 3;
    float ac0[8][4], ac1[8][4];
    #pragma unroll
    for (int n = 0; n < 8; n++)
        #pragma unroll
        for (int j = 0; j < 4; j++) { ac0[n][j] = 0.f; ac1[n][j] = 0.f; }
    #pragma unroll
    for (int q = 0; q < 4; q++) {
        unsigned a00 = fsw0[gid * FS_H2 + q * 8 + tig];
        unsigned a01 = fsw0[(gid + 8) * FS_H2 + q * 8 + tig];
        unsigned a02 = fsw0[gid * FS_H2 + q * 8 + tig + 4];
        unsigned a03 = fsw0[(gid + 8) * FS_H2 + q * 8 + tig + 4];
        unsigned a10 = fsw1[gid * FS_H2 + q * 8 + tig];
        unsigned a11 = fsw1[(gid + 8) * FS_H2 + q * 8 + tig];
        unsigned a12 = fsw1[gid * FS_H2 + q * 8 + tig + 4];
        unsigned a13 = fsw1[(gid + 8) * FS_H2 + q * 8 + tig + 4];
        const uint2* br = wfc + (q * 4 + tig) * WH64 + gid;
        #pragma unroll
        for (int n = 0; n < 8; n++) {
            uint2 b = br[8 * n];
            mma_f16(ac0[n], a00, a01, a02, a03, b.x, b.y);
            mma_f16(ac1[n], a10, a11, a12, a13, b.x, b.y);
        }
    }
    #pragma unroll
    for (int n = 0; n < 8; n++) {
        *(float2*)(lg0 + gid * LG_PAD + n * 8 + 2 * tig)       = make_float2(ac0[n][0], ac0[n][1]);
        *(float2*)(lg0 + (gid + 8) * LG_PAD + n * 8 + 2 * tig) = make_float2(ac0[n][2], ac0[n][3]);
        *(float2*)(lg1 + gid * LG_PAD + n * 8 + 2 * tig)       = make_float2(ac1[n][0], ac1[n][1]);
        *(float2*)(lg1 + (gid + 8) * LG_PAD + n * 8 + 2 * tig) = make_float2(ac1[n][2], ac1[n][3]);
    }
}

// softmax pool over K for channel ch, logits fp32 smem, values fp16 fs smem.
// No max-subtraction: softmax is shift-invariant and logits are O(10) max,
// so exp() is safe in fp32; removes the serial 16-load->16-max chain.
__device__ __forceinline__ float att_pool_fs(const float* __restrict__ lg_s,
                                             const __half2* __restrict__ fs_h, int ch)
{
    const int hidx = ch >> 1;
    float s = 0.f, a = 0.f;
    #pragma unroll
    for (int k = 0; k < KNN; k++) {
        float e = __expf(lg_s[k * LG_PAD + ch]);
        __half2 h = fs_h[k * FS_H2 + hidx];
        float v = (ch & 1) ? __high2float(h) : __low2float(h);
        s += e;
        a += e * v;
    }
    return __fdividef(a, s);
}

// ---------------------------------------------------------------------------
// Kernel 1: f_pc = ReLU((feature @ w_mlp1) * s + b)
// weight column held in registers (loop-invariant per lane)
// ---------------------------------------------------------------------------
__global__ __launch_bounds__(256) void kern_mlp1(
    const float* __restrict__ feature,
    const float* __restrict__ w, const float* __restrict__ s, const float* __restrict__ b)
{
    __shared__ float xs[8][32];

    const int lane = threadIdx.x & 31;
    const int warp = threadIdx.x >> 5;

    float wcol[32];
    #pragma unroll
    for (int j = 0; j < 32; j++) wcol[j] = w[j * 32 + lane];
    const float sv = s[lane];
    const float bv = b[lane];

    const int nwarps = (gridDim.x * blockDim.x) >> 5;
    int gw = (blockIdx.x * blockDim.x + threadIdx.x) >> 5;

    for (int p = gw; p < P_TOTAL; p += nwarps) {
        xs[warp][lane] = feature[(size_t)p * 32 + lane];
        __syncwarp();
        float acc = 0.f;
        #pragma unroll
        for (int j4 = 0; j4 < 32; j4 += 4) {
            float4 f = *(const float4*)(&xs[warp][j4]);
            acc += f.x * wcol[j4] + f.y * wcol[j4 + 1]
                 + f.z * wcol[j4 + 2] + f.w * wcol[j4 + 3];
        }
        g_f_pc[(size_t)p * 32 + lane] = fmaxf(acc * sv + bv, 0.f);
        __syncwarp();
    }
}

// ---------------------------------------------------------------------------
// Kernel 2: TWO points per warp. rel_pos + lfa1(f16) + gather + logits(f16) +
//           pool(fs-smem) + f_agg ; lfa2(f16) -> g_fx2.  14 warps.
// ---------------------------------------------------------------------------
#define K2_WARP_FLOATS 3392
#define K2_BASE_FLOATS 5216
#define K2_WARPS 14
#define K2_SMEM_BYTES ((K2_BASE_FLOATS + K2_WARPS * K2_WARP_FLOATS) * 4)

__global__ __launch_bounds__(448) void kern_att1(
    const float* __restrict__ xyz, const int* __restrict__ neigh,
    const float* __restrict__ wlfa1, const float* __restrict__ slfa1, const float* __restrict__ blfa1,
    const float* __restrict__ wfc1,
    const float* __restrict__ wam1, const float* __restrict__ sam1, const float* __restrict__ bam1,
    const float* __restrict__ wlfa2, const float* __restrict__ slfa2, const float* __restrict__ blfa2)
{
    extern __shared__ float sm[];
    uint2*  s_wfcp = (uint2*)sm;              // [16][68] uint2 = 2176 floats
    float2* s_wamp = (float2*)(sm + 2176);    // [32][32] float2 = 2048 floats
    uint2*  s_wl1p = (uint2*)(sm + 4224);     // [4][36] uint2 = 288 floats
    uint2*  s_wl2p = (uint2*)(sm + 4512);     // [8][36] uint2 = 576 floats
    float*  s_vec  = sm + 5088;               // 128: blfa1, blfa2, bam1
    float*  s_wrp  = sm + K2_BASE_FLOATS;

    for (int i = threadIdx.x; i < 1024; i += blockDim.x) {
        int r = i >> 6, c = i & 63;
        int q = r >> 2, t = r & 3;
        int k0 = 16 * q + 2 * t;
        s_wfcp[r * WH64 + c] = make_uint2(
            f2_to_u(wfc1[k0 * 64 + c], wfc1[(k0 + 1) * 64 + c]),
            f2_to_u(wfc1[(k0 + 8) * 64 + c], wfc1[(k0 + 9) * 64 + c]));
    }
    for (int i = threadIdx.x; i < 1024; i += blockDim.x) {
        int r = i >> 5, c = i & 31;
        s_wamp[r * 32 + c] = make_float2(wam1[(2 * r) * 32 + c] * sam1[c],
                                         wam1[(2 * r + 1) * 32 + c] * sam1[c]);
    }
    for (int i = threadIdx.x; i < 128; i += blockDim.x) {
        int t = i >> 5, c = i & 31;
        int k0 = 2 * t, k1 = 2 * t + 8;
        float w00 = wlfa1[k0 * 32 + c] * slfa1[c];
        float w01 = wlfa1[(k0 + 1) * 32 + c] * slfa1[c];
        float w10 = (k1 < 10) ? wlfa1[k1 * 32 + c] * slfa1[c] : 0.f;
        float w11 = (k1 + 1 < 10) ? wlfa1[(k1 + 1) * 32 + c] * slfa1[c] : 0.f;
        s_wl1p[t * WH32 + c] = make_uint2(f2_to_u(w00, w01), f2_to_u(w10, w11));
    }
    for (int i = threadIdx.x; i < 256; i += blockDim.x) {
        int r = i >> 5, c = i & 31;
        int q = r >> 2, t = r & 3;
        int k0 = 16 * q + 2 * t;
        s_wl2p[r * WH32 + c] = make_uint2(
            f2_to_u(wlfa2[k0 * 32 + c] * slfa2[c], wlfa2[(k0 + 1) * 32 + c] * slfa2[c]),
            f2_to_u(wlfa2[(k0 + 8) * 32 + c] * slfa2[c], wlfa2[(k0 + 9) * 32 + c] * slfa2[c]));
    }
    if (threadIdx.x < 32) {
        int l = threadIdx.x;
        s_vec[l]      = blfa1[l];
        s_vec[32 + l] = blfa2[l];
        s_vec[64 + l] = bam1[l];
    }
    __syncthreads();

    const int lane = threadIdx.x & 31;
    const int warp = threadIdx.x >> 5;
    const int gid = lane >> 2, tig = lane & 3;
    float* wbase = s_wrp + warp * K2_WARP_FLOATS;
    __half2*  fs0_h = (__half2*)wbase;            // [16][36] half2
    __half2*  fs1_h = (__half2*)(wbase + 576);
    unsigned* fsw0  = (unsigned*)fs0_h;
    unsigned* fsw1  = (unsigned*)fs1_h;
    float* lg0  = wbase + 1152;                   // [16][66]
    float* lg1  = wbase + 2208;
    __half2* rp0 = (__half2*)lg0;                 // aliases lg (dead before logits)
    __half2* rp1 = (__half2*)lg1;
    unsigned* rp0w = (unsigned*)rp0;
    unsigned* rp1w = (unsigned*)rp1;
    float* agg_s = wbase + 3264;                  // [128]

    const int nwarps = (gridDim.x * blockDim.x) >> 5;
    int gw = (blockIdx.x * blockDim.x + threadIdx.x) >> 5;

    for (int pp = gw; pp < P_TOTAL / 2; pp += nwarps) {
        const int p0 = 2 * pp, p1 = p0 + 1;
        const int b = p0 / NPTS;
        const size_t bbase = (size_t)b * NPTS;

        int idx = neigh[(size_t)p0 * KNN + lane];

        // gather both points' neighbor features; gv dies after the fp16 pack
        {
            float gv0[KNN], gv1[KNN];
            #pragma unroll
            for (int k = 0; k < KNN; k++) {
                int nb = __shfl_sync(0xffffffffu, idx, k);
                gv0[k] = g_f_pc[(bbase + (size_t)nb) * 32 + lane];
            }
            #pragma unroll
            for (int k = 0; k < KNN; k++) {
                int nb = __shfl_sync(0xffffffffu, idx, 16 + k);
                gv1[k] = g_f_pc[(bbase + (size_t)nb) * 32 + lane];
            }
            #pragma unroll
            for (int k = 0; k < KNN; k++) {
                float v0 = gv0[k];
                float v1 = __shfl_xor_sync(0xffffffffu, v0, 1);
                if (!(lane & 1))
                    fs0_h[k * FS_H2 + (lane >> 1)] = __floats2half2_rn(v0, v1);
            }
            #pragma unroll
            for (int k = 0; k < KNN; k++) {
                float v0 = gv1[k];
                float v1 = __shfl_xor_sync(0xffffffffu, v0, 1);
                if (!(lane & 1))
                    fs1_h[k * FS_H2 + (lane >> 1)] = __floats2half2_rn(v0, v1);
            }
        }

        {
            const int myp = (lane < 16) ? p0 : p1;
            const int krow = lane & 15;
            float cx = xyz[(size_t)myp * 3 + 0];
            float cy = xyz[(size_t)myp * 3 + 1];
            float cz = xyz[(size_t)myp * 3 + 2];
            size_t nb = bbase + (size_t)idx;
            float nx = xyz[nb * 3 + 0], ny = xyz[nb * 3 + 1], nz = xyz[nb * 3 + 2];
            float rx = cx - nx, ry = cy - ny, rz = cz - nz;
            float d = sqrtf(rx * rx + ry * ry + rz * rz);
            __half2* rp = (lane < 16) ? rp0 : rp1;
            __half2 z = __floats2half2_rn(0.f, 0.f);
            rp[krow * RP2 + 0] = __floats2half2_rn(d, rx);
            rp[krow * RP2 + 1] = __floats2half2_rn(ry, rz);
            rp[krow * RP2 + 2] = __floats2half2_rn(cx, cy);
            rp[krow * RP2 + 3] = __floats2half2_rn(cz, nx);
            rp[krow * RP2 + 4] = __floats2half2_rn(ny, nz);
            rp[krow * RP2 + 5] = z;
            rp[krow * RP2 + 6] = z;
            rp[krow * RP2 + 7] = z;
        }
        __syncwarp();

        // lfa1 via f16 mma (K=16 covers all 10 rows), B shared
        {
            unsigned a00 = rp0w[gid * RP2 + tig];
            unsigned a01 = rp0w[(gid + 8) * RP2 + tig];
            unsigned a02 = rp0w[gid * RP2 + tig + 4];
            unsigned a03 = rp0w[(gid + 8) * RP2 + tig + 4];
            unsigned a10 = rp1w[gid * RP2 + tig];
            unsigned a11 = rp1w[(gid + 8) * RP2 + tig];
            unsigned a12 = rp1w[gid * RP2 + tig + 4];
            unsigned a13 = rp1w[(gid + 8) * RP2 + tig + 4];
            float ac0[4][4], ac1[4][4];
            #pragma unroll
            for (int n = 0; n < 4; n++)
                #pragma unroll
                for (int j = 0; j < 4; j++) { ac0[n][j] = 0.f; ac1[n][j] = 0.f; }
            const uint2* br = s_wl1p + tig * WH32 + gid;
            #pragma unroll
            for (int n = 0; n < 4; n++) {
                uint2 bb = br[8 * n];
                mma_f16(ac0[n], a00, a01, a02, a03, bb.x, bb.y);
                mma_f16(ac1[n], a10, a11, a12, a13, bb.x, bb.y);
            }
            #pragma unroll
            for (int n = 0; n < 4; n++) {
                int c0 = n * 8 + 2 * tig;
                float b0 = s_vec[c0], b1 = s_vec[c0 + 1];
                fs0_h[gid * FS_H2 + 16 + n * 4 + tig] =
                    __floats2half2_rn(fmaxf(ac0[n][0] + b0, 0.f), fmaxf(ac0[n][1] + b1, 0.f));
                fs0_h[(gid + 8) * FS_H2 + 16 + n * 4 + tig] =
                    __floats2half2_rn(fmaxf(ac0[n][2] + b0, 0.f), fmaxf(ac0[n][3] + b1, 0.f));
                fs1_h[gid * FS_H2 + 16 + n * 4 + tig] =
                    __floats2half2_rn(fmaxf(ac1[n][0] + b0, 0.f), fmaxf(ac1[n][1] + b1, 0.f));
                fs1_h[(gid + 8) * FS_H2 + 16 + n * 4 + tig] =
                    __floats2half2_rn(fmaxf(ac1[n][2] + b0, 0.f), fmaxf(ac1[n][3] + b1, 0.f));
            }
        }
        __syncwarp();

        logits_f16_x2(fsw0, fsw1, lg0, lg1, s_wfcp, lane);
        __syncwarp();
        agg_s[lane]       = att_pool_fs(lg0, fs0_h, lane);
        agg_s[32 + lane]  = att_pool_fs(lg0, fs0_h, 32 + lane);
        agg_s[64 + lane]  = att_pool_fs(lg1, fs1_h, lane);
        agg_s[96 + lane]  = att_pool_fs(lg1, fs1_h, 32 + lane);
        __syncwarp();

        // f_agg for both points, wam read once
        {
            float acc0 = 0.f, acc1 = 0.f;
            #pragma unroll
            for (int d2 = 0; d2 < 32; d2 += 2) {
                float4 a0 = *(const float4*)(agg_s + 2 * d2);
                float4 a1 = *(const float4*)(agg_s + 64 + 2 * d2);
                float2 w0 = s_wamp[d2 * 32 + lane];
                float2 w1 = s_wamp[(d2 + 1) * 32 + lane];
                acc0 += a0.x * w0.x + a0.y * w0.y + a0.z * w1.x + a0.w * w1.y;
                acc1 += a1.x * w0.x + a1.y * w0.y + a1.z * w1.x + a1.w * w1.y;
            }
            float bb = s_vec[64 + lane];
            g_f_agg[(size_t)p0 * 32 + lane] = fmaxf(acc0 + bb, 0.f);
            g_f_agg[(size_t)p1 * 32 + lane] = fmaxf(acc1 + bb, 0.f);
        }

        // lfa2 via f16 mma, B shared -> g_fx2
        {
            float ac0[4][4], ac1[4][4];
            #pragma unroll
            for (int n = 0; n < 4; n++)
                #pragma unroll
                for (int j = 0; j < 4; j++) { ac0[n][j] = 0.f; ac1[n][j] = 0.f; }
            #pragma unroll
            for (int q = 0; q < 2; q++) {
                unsigned a00 = fsw0[gid * FS_H2 + 16 + q * 8 + tig];
                unsigned a01 = fsw0[(gid + 8) * FS_H2 + 16 + q * 8 + tig];
                unsigned a02 = fsw0[gid * FS_H2 + 16 + q * 8 + tig + 4];
                unsigned a03 = fsw0[(gid + 8) * FS_H2 + 16 + q * 8 + tig + 4];
                unsigned a10 = fsw1[gid * FS_H2 + 16 + q * 8 + tig];
                unsigned a11 = fsw1[(gid + 8) * FS_H2 + 16 + q * 8 + tig];
                unsigned a12 = fsw1[gid * FS_H2 + 16 + q * 8 + tig + 4];
                unsigned a13 = fsw1[(gid + 8) * FS_H2 + 16 + q * 8 + tig + 4];
                const uint2* br = s_wl2p + (q * 4 + tig) * WH32 + gid;
                #pragma unroll
                for (int n = 0; n < 4; n++) {
                    uint2 bb = br[8 * n];
                    mma_f16(ac0[n], a00, a01, a02, a03, bb.x, bb.y);
                    mma_f16(ac1[n], a10, a11, a12, a13, bb.x, bb.y);
                }
            }
            #pragma unroll
            for (int n = 0; n < 4; n++) {
                int c0 = n * 8 + 2 * tig;
                float b0 = s_vec[32 + c0], b1 = s_vec[32 + c0 + 1];
                g_fx2[((size_t)p0 * KNN + gid) * 16 + (c0 >> 1)] =
                    __floats2half2_rn(fmaxf(ac0[n][0] + b0, 0.f), fmaxf(ac0[n][1] + b1, 0.f));
                g_fx2[((size_t)p0 * KNN + gid + 8) * 16 + (c0 >> 1)] =
                    __floats2half2_rn(fmaxf(ac0[n][2] + b0, 0.f), fmaxf(ac0[n][3] + b1, 0.f));
                g_fx2[((size_t)p1 * KNN + gid) * 16 + (c0 >> 1)] =
                    __floats2half2_rn(fmaxf(ac1[n][0] + b0, 0.f), fmaxf(ac1[n][1] + b1, 0.f));
                g_fx2[((size_t)p1 * KNN + gid + 8) * 16 + (c0 >> 1)] =
                    __floats2half2_rn(fmaxf(ac1[n][2] + b0, 0.f), fmaxf(ac1[n][3] + b1, 0.f));
            }
        }
        __syncwarp();
    }
}

// ---------------------------------------------------------------------------
// Kernel 3: TWO points per warp: gather(f_agg) + fx2 + logits(shared B) +
//           pools(fs-smem) -> g_agg2.  16 warps.
// ---------------------------------------------------------------------------
#define K3_WARP_FLOATS 3264
#define K3_BASE_FLOATS 2176
#define K3_WARPS 16
#define K3_SMEM_BYTES ((K3_BASE_FLOATS + K3_WARPS * K3_WARP_FLOATS) * 4)

__global__ __launch_bounds__(512) void kern_att2(
    const int* __restrict__ neigh,
    const float* __restrict__ wfc2)
{
    extern __shared__ float sm[];
    uint2* s_wfcp = (uint2*)sm;               // [16][68] uint2
    float* s_wrp  = sm + K3_BASE_FLOATS;

    for (int i = threadIdx.x; i < 1024; i += blockDim.x) {
        int r = i >> 6, c = i & 63;
        int q = r >> 2, t = r & 3;
        int k0 = 16 * q + 2 * t;
        s_wfcp[r * WH64 + c] = make_uint2(
            f2_to_u(wfc2[k0 * 64 + c], wfc2[(k0 + 1) * 64 + c]),
            f2_to_u(wfc2[(k0 + 8) * 64 + c], wfc2[(k0 + 9) * 64 + c]));
    }
    __syncthreads();

    const int lane = threadIdx.x & 31;
    const int warp = threadIdx.x >> 5;
    float* wbase = s_wrp + warp * K3_WARP_FLOATS;
    __half2*  fs0_h = (__half2*)wbase;
    __half2*  fs1_h = (__half2*)(wbase + 576);
    unsigned* fsw0  = (unsigned*)fs0_h;
    unsigned* fsw1  = (unsigned*)fs1_h;
    float* lg0 = wbase + 1152;
    float* lg1 = wbase + 2208;

    const int kk = lane >> 4;
    const int jj = lane & 15;

    const int nwarps = (gridDim.x * blockDim.x) >> 5;
    int gw = (blockIdx.x * blockDim.x + threadIdx.x) >> 5;

    for (int pp = gw; pp < P_TOTAL / 2; pp += nwarps) {
        const int p0 = 2 * pp, p1 = p0 + 1;
        const int b = p0 / NPTS;
        const size_t bbase = (size_t)b * NPTS;

        int idx = neigh[(size_t)p0 * KNN + lane];

        {
            float gv0[KNN], gv1[KNN];
            #pragma unroll
            for (int k = 0; k < KNN; k++) {
                int nb = __shfl_sync(0xffffffffu, idx, k);
                gv0[k] = g_f_agg[(bbase + (size_t)nb) * 32 + lane];
            }
            #pragma unroll
            for (int k = 0; k < KNN; k++) {
                int nb = __shfl_sync(0xffffffffu, idx, 16 + k);
                gv1[k] = g_f_agg[(bbase + (size_t)nb) * 32 + lane];
            }
            #pragma unroll
            for (int k = 0; k < KNN; k++) {
                float v0 = gv0[k];
                float v1 = __shfl_xor_sync(0xffffffffu, v0, 1);
                if (!(lane & 1))
                    fs0_h[k * FS_H2 + (lane >> 1)] = __floats2half2_rn(v0, v1);
            }
            #pragma unroll
            for (int k = 0; k < KNN; k++) {
                float v0 = gv1[k];
                float v1 = __shfl_xor_sync(0xffffffffu, v0, 1);
                if (!(lane & 1))
                    fs1_h[k * FS_H2 + (lane >> 1)] = __floats2half2_rn(v0, v1);
            }
        }
        const unsigned* src0 = (const unsigned*)(g_fx2 + (size_t)p0 * KNN * 16);
        const unsigned* src1 = (const unsigned*)(g_fx2 + (size_t)p1 * KNN * 16);
        #pragma unroll
        for (int k = 0; k < KNN; k += 2) {
            fsw0[(k + kk) * FS_H2 + 16 + jj] = src0[(k + kk) * 16 + jj];
            fsw1[(k + kk) * FS_H2 + 16 + jj] = src1[(k + kk) * 16 + jj];
        }
        __syncwarp();

        logits_f16_x2(fsw0, fsw1, lg0, lg1, s_wfcp, lane);
        __syncwarp();

        g_agg2[(size_t)p0 * 64 + lane]      = att_pool_fs(lg0, fs0_h, lane);
        g_agg2[(size_t)p0 * 64 + 32 + lane] = att_pool_fs(lg0, fs0_h, 32 + lane);
        g_agg2[(size_t)p1 * 64 + lane]      = att_pool_fs(lg1, fs1_h, lane);
        g_agg2[(size_t)p1 * 64 + 32 + lane] = att_pool_fs(lg1, fs1_h, 32 + lane);
        __syncwarp();
    }
}

// ---------------------------------------------------------------------------
// Kernel 4: 16-point tiles, SINGLE TF32 GEMMs with float2-packed B.
// ---------------------------------------------------------------------------
#define OUT_WARPS 16
#define OUT_BASE_FLOATS 17216
#define OUT_WARP_FLOATS 1600
#define OUT_SMEM_BYTES ((OUT_BASE_FLOATS + OUT_WARPS * OUT_WARP_FLOATS) * 4)

__global__ __launch_bounds__(512) void kern_out(
    const float* __restrict__ feature,
    const float* __restrict__ wam2, const float* __restrict__ sam2, const float* __restrict__ bam2,
    const float* __restrict__ wmlp2, const float* __restrict__ smlp2, const float* __restrict__ bmlp2,
    const float* __restrict__ wsc, const float* __restrict__ ssc, const float* __restrict__ bsc,
    float* __restrict__ out)
{
    extern __shared__ float sm[];
    float2* w1p  = (float2*)sm;              // [32][68] float2 = 4352 floats
    float2* w23p = (float2*)(sm + 4352);     // [48][132] float2 = 12672 floats
    float*  b1   = sm + 17024;               // [64]
    float*  b2   = sm + 17088;               // [128]
    float*  wrp  = sm + OUT_BASE_FLOATS;

    for (int i = threadIdx.x; i < 2048; i += blockDim.x) {
        int r = i >> 6, c = i & 63;
        int k0 = (r >> 2) * 8 + (r & 3), k1 = k0 + 4;
        w1p[r * P2F64 + c] = make_float2(to_tf32(wam2[k0 * 64 + c] * sam2[c]),
                                         to_tf32(wam2[k1 * 64 + c] * sam2[c]));
    }
    for (int i = threadIdx.x; i < 6144; i += blockDim.x) {
        int r = i >> 7, c = i & 127;
        int k0 = (r >> 2) * 8 + (r & 3), k1 = k0 + 4;
        float v0 = (k0 < 64) ? wmlp2[k0 * 128 + c] * smlp2[c] : wsc[(k0 - 64) * 128 + c] * ssc[c];
        float v1 = (k1 < 64) ? wmlp2[k1 * 128 + c] * smlp2[c] : wsc[(k1 - 64) * 128 + c] * ssc[c];
        w23p[r * P2F128 + c] = make_float2(to_tf32(v0), to_tf32(v1));
    }
    if (threadIdx.x < 64)  b1[threadIdx.x] = bam2[threadIdx.x];
    if (threadIdx.x < 128) b2[threadIdx.x] = bmlp2[threadIdx.x] + bsc[threadIdx.x];
    __syncthreads();

    const int lane = threadIdx.x & 31;
    const int warp = threadIdx.x >> 5;
    const int gid = lane >> 2, tig = lane & 3;
    float* A1 = wrp + warp * OUT_WARP_FLOATS;  // [16][100]

    const int nwarps = (gridDim.x * blockDim.x) >> 5;
    int gw = (blockIdx.x * blockDim.x + threadIdx.x) >> 5;
    const int ntiles = P_TOTAL / 16;

    for (int t = gw; t < ntiles; t += nwarps) {
        const int p0 = t * 16;

        #pragma unroll
        for (int r = 0; r < 16; r++) {
            A1[r * OA_PAD + lane]      = g_agg2[(size_t)(p0 + r) * 64 + lane];
            A1[r * OA_PAD + 32 + lane] = g_agg2[(size_t)(p0 + r) * 64 + 32 + lane];
            A1[r * OA_PAD + 64 + lane] = feature[(size_t)(p0 + r) * 32 + lane];
        }
        __syncwarp();

        // GEMM1 (single tf32): pc2 = relu(agg @ w1 + b1) -> A cols 0..63
        {
            float acc[8][4];
            #pragma unroll
            for (int n = 0; n < 8; n++) { acc[n][0]=0.f; acc[n][1]=0.f; acc[n][2]=0.f; acc[n][3]=0.f; }
            #pragma unroll
            for (int q = 0; q < 8; q++) {
                unsigned a0 = __float_as_uint(to_tf32(A1[gid * OA_PAD + q * 8 + tig]));
                unsigned a1 = __float_as_uint(to_tf32(A1[(gid + 8) * OA_PAD + q * 8 + tig]));
                unsigned a2 = __float_as_uint(to_tf32(A1[gid * OA_PAD + q * 8 + tig + 4]));
                unsigned a3 = __float_as_uint(to_tf32(A1[(gid + 8) * OA_PAD + q * 8 + tig + 4]));
                const float2* br = w1p + (q * 4 + tig) * P2F64 + gid;
                #pragma unroll
                for (int n = 0; n < 8; n++) {
                    float2 b = br[8 * n];
                    mma_tf32(acc[n], a0, a1, a2, a3,
                             __float_as_uint(b.x), __float_as_uint(b.y));
                }
            }
            __syncwarp();
            #pragma unroll
            for (int n = 0; n < 8; n++) {
                int c0 = n * 8 + 2 * tig;
                float bb0 = b1[c0], bb1 = b1[c0 + 1];
                *(float2*)(A1 + gid * OA_PAD + c0) =
                    make_float2(fmaxf(acc[n][0] + bb0, 0.f), fmaxf(acc[n][1] + bb1, 0.f));
                *(float2*)(A1 + (gid + 8) * OA_PAD + c0) =
                    make_float2(fmaxf(acc[n][2] + bb0, 0.f), fmaxf(acc[n][3] + bb1, 0.f));
            }
        }
        __syncwarp();

        // GEMM2 (single tf32): out = leaky(A[16][96] @ w23 + b2), two n-halves
        #pragma unroll
        for (int h = 0; h < 2; h++) {
            float acc[8][4];
            #pragma unroll
            for (int n = 0; n < 8; n++) { acc[n][0]=0.f; acc[n][1]=0.f; acc[n][2]=0.f; acc[n][3]=0.f; }
            #pragma unroll
            for (int q = 0; q < 12; q++) {
                unsigned a0 = __float_as_uint(to_tf32(A1[gid * OA_PAD + q * 8 + tig]));
                unsigned a1 = __float_as_uint(to_tf32(A1[(gid + 8) * OA_PAD + q * 8 + tig]));
                unsigned a2 = __float_as_uint(to_tf32(A1[gid * OA_PAD + q * 8 + tig + 4]));
                unsigned a3 = __float_as_uint(to_tf32(A1[(gid + 8) * OA_PAD + q * 8 + tig + 4]));
                const float2* br = w23p + (q * 4 + tig) * P2F128 + h * 64 + gid;
                #pragma unroll
                for (int n = 0; n < 8; n++) {
                    float2 b = br[8 * n];
                    mma_tf32(acc[n], a0, a1, a2, a3,
                             __float_as_uint(b.x), __float_as_uint(b.y));
                }
            }
            #pragma unroll
            for (int n = 0; n < 8; n++) {
                int c0 = h * 64 + n * 8 + 2 * tig;
                float bb0 = b2[c0], bb1 = b2[c0 + 1];
                float v0 = acc[n][0] + bb0; v0 = (v0 < 0.f) ? 0.2f * v0 : v0;
                float v1 = acc[n][1] + bb1; v1 = (v1 < 0.f) ? 0.2f * v1 : v1;
                float v2 = acc[n][2] + bb0; v2 = (v2 < 0.f) ? 0.2f * v2 : v2;
                float v3 = acc[n][3] + bb1; v3 = (v3 < 0.f) ? 0.2f * v3 : v3;
                *(float2*)(&out[(size_t)(p0 + gid) * 128 + c0])     = make_float2(v0, v1);
                *(float2*)(&out[(size_t)(p0 + gid + 8) * 128 + c0]) = make_float2(v2, v3);
            }
        }
        __syncwarp();
    }
}

// ---------------------------------------------------------------------------
extern "C" void kernel_launch(void* const* d_in, const int* in_sizes, int n_in,
                              void* d_out, int out_size)
{
    const float* feature = (const float*)d_in[0];
    const float* xyz     = (const float*)d_in[1];
    const int*   neigh   = (const int*)  d_in[2];
    const float* w_mlp1  = (const float*)d_in[3];
    const float* s_mlp1  = (const float*)d_in[4];
    const float* b_mlp1  = (const float*)d_in[5];
    const float* w_lfa1  = (const float*)d_in[6];
    const float* s_lfa1  = (const float*)d_in[7];
    const float* b_lfa1  = (const float*)d_in[8];
    const float* w_fc1   = (const float*)d_in[9];
    const float* w_am1   = (const float*)d_in[10];
    const float* s_am1   = (const float*)d_in[11];
    const float* b_am1   = (const float*)d_in[12];
    const float* w_lfa2  = (const float*)d_in[13];
    const float* s_lfa2  = (const float*)d_in[14];
    const float* b_lfa2  = (const float*)d_in[15];
    const float* w_fc2   = (const float*)d_in[16];
    const float* w_am2   = (const float*)d_in[17];
    const float* s_am2   = (const float*)d_in[18];
    const float* b_am2   = (const float*)d_in[19];
    const float* w_mlp2  = (const float*)d_in[20];
    const float* s_mlp2  = (const float*)d_in[21];
    const float* b_mlp2  = (const float*)d_in[22];
    const float* w_sc    = (const float*)d_in[23];
    const float* s_sc    = (const float*)d_in[24];
    const float* b_sc    = (const float*)d_in[25];
    float* out = (float*)d_out;

    cudaFuncSetAttribute(kern_att1, cudaFuncAttributeMaxDynamicSharedMemorySize, K2_SMEM_BYTES);
    cudaFuncSetAttribute(kern_att2, cudaFuncAttributeMaxDynamicSharedMemorySize, K3_SMEM_BYTES);
    cudaFuncSetAttribute(kern_out,  cudaFuncAttributeMaxDynamicSharedMemorySize, OUT_SMEM_BYTES);

    kern_mlp1<<<2048, 256>>>(feature, w_mlp1, s_mlp1, b_mlp1);

    kern_att1<<<148, 448, K2_SMEM_BYTES>>>(
        xyz, neigh,
        w_lfa1, s_lfa1, b_lfa1,
        w_fc1,
        w_am1, s_am1, b_am1,
        w_lfa2, s_lfa2, b_lfa2);

    kern_att2<<<148, 512, K3_SMEM_BYTES>>>(neigh, w_fc2);

    kern_out<<<148, 512, OUT_SMEM_BYTES>>>(
        feature,
        w_am2, s_am2, b_am2,
        w_mlp2, s_mlp2, b_mlp2,
        w_sc, s_sc, b_sc,
        out);
}

// round 13
// speedup vs baseline: 1.3225x; 1.1849x over previous
#include <cuda_runtime.h>
#include <cuda_fp16.h>
#include <math.h>

#define BATCH 4
#define NPTS  40960
#define KNN   16
#define P_TOTAL (BATCH * NPTS)   // 163840

#define FS_H2  36    // fs/elg tile row stride in half2 units (4 mod 32)
#define WH64   68    // fp16 B-tile stride, 64 cols, uint2 units
#define WH32   36    // fp16 B-tile stride, 32 cols, uint2 units
#define P2F64  68    // float2 B-tile stride, 64 cols (4 mod 16)
#define P2F128 132   // float2 B-tile stride, 128 cols (4 mod 16)
#define RP2    12    // relpos tile stride in half2 units
#define OA_PAD 100   // kern_out A tile stride (4 mod 32)

// Scratch (device globals)
__device__ float   g_f_pc [P_TOTAL * 32];                    // 21 MB
__device__ float   g_f_agg[P_TOTAL * 32];                    // 21 MB
__device__ float   g_agg2 [(size_t)P_TOTAL * 64];            // 42 MB
__device__ __half2 g_fx2  [(size_t)P_TOTAL * KNN * 16];      // 168 MB

__device__ __forceinline__ float to_tf32(float x) {
    float r;
    asm("cvt.rna.tf32.f32 %0, %1;" : "=f"(r) : "f"(x));
    return r;
}
__device__ __forceinline__ unsigned f2_to_u(float a, float b) {
    __half2 h = __floats2half2_rn(a, b);
    return *(unsigned*)&h;
}

__device__ __forceinline__ void mma_tf32(float* c,
                                         unsigned a0, unsigned a1, unsigned a2, unsigned a3,
                                         unsigned b0, unsigned b1) {
    asm("mma.sync.aligned.m16n8k8.row.col.f32.tf32.tf32.f32 "
        "{%0,%1,%2,%3}, {%4,%5,%6,%7}, {%8,%9}, {%0,%1,%2,%3};"
        : "+f"(c[0]), "+f"(c[1]), "+f"(c[2]), "+f"(c[3])
        : "r"(a0), "r"(a1), "r"(a2), "r"(a3), "r"(b0), "r"(b1));
}
__device__ __forceinline__ void mma_f16(float* c,
                                        unsigned a0, unsigned a1, unsigned a2, unsigned a3,
                                        unsigned b0, unsigned b1) {
    asm("mma.sync.aligned.m16n8k16.row.col.f32.f16.f16.f32 "
        "{%0,%1,%2,%3}, {%4,%5,%6,%7}, {%8,%9}, {%0,%1,%2,%3};"
        : "+f"(c[0]), "+f"(c[1]), "+f"(c[2]), "+f"(c[3])
        : "r"(a0), "r"(a1), "r"(a2), "r"(a3), "r"(b0), "r"(b1));
}

// dual-point logits -> exp(logit-8) stored as fp16 weight tiles (elg).
// exp applied in registers (MUFU overlaps mma section); -8 shift is
// softmax-invariant and guards fp16 overflow up to logit 19.
__device__ __forceinline__ void logits_exp_x2(const unsigned* __restrict__ fsw0,
                                              const unsigned* __restrict__ fsw1,
                                              __half2* __restrict__ elg0,
                                              __half2* __restrict__ elg1,
                                              const uint2* __restrict__ wfc, int lane)
{
    const int gid = lane >> 2;
    const int tig = lane & 3;
    float ac0[8][4], ac1[8][4];
    #pragma unroll
    for (int n = 0; n < 8; n++)
        #pragma unroll
        for (int j = 0; j < 4; j++) { ac0[n][j] = 0.f; ac1[n][j] = 0.f; }
    #pragma unroll
    for (int q = 0; q < 4; q++) {
        unsigned a00 = fsw0[gid * FS_H2 + q * 8 + tig];
        unsigned a01 = fsw0[(gid + 8) * FS_H2 + q * 8 + tig];
        unsigned a02 = fsw0[gid * FS_H2 + q * 8 + tig + 4];
        unsigned a03 = fsw0[(gid + 8) * FS_H2 + q * 8 + tig + 4];
        unsigned a10 = fsw1[gid * FS_H2 + q * 8 + tig];
        unsigned a11 = fsw1[(gid + 8) * FS_H2 + q * 8 + tig];
        unsigned a12 = fsw1[gid * FS_H2 + q * 8 + tig + 4];
        unsigned a13 = fsw1[(gid + 8) * FS_H2 + q * 8 + tig + 4];
        const uint2* br = wfc + (q * 4 + tig) * WH64 + gid;
        #pragma unroll
        for (int n = 0; n < 8; n++) {
            uint2 b = br[8 * n];
            mma_f16(ac0[n], a00, a01, a02, a03, b.x, b.y);
            mma_f16(ac1[n], a10, a11, a12, a13, b.x, b.y);
        }
    }
    #pragma unroll
    for (int n = 0; n < 8; n++) {
        elg0[gid * FS_H2 + n * 4 + tig] =
            __floats2half2_rn(__expf(ac0[n][0] - 8.f), __expf(ac0[n][1] - 8.f));
        elg0[(gid + 8) * FS_H2 + n * 4 + tig] =
            __floats2half2_rn(__expf(ac0[n][2] - 8.f), __expf(ac0[n][3] - 8.f));
        elg1[gid * FS_H2 + n * 4 + tig] =
            __floats2half2_rn(__expf(ac1[n][0] - 8.f), __expf(ac1[n][1] - 8.f));
        elg1[(gid + 8) * FS_H2 + n * 4 + tig] =
            __floats2half2_rn(__expf(ac1[n][2] - 8.f), __expf(ac1[n][3] - 8.f));
    }
}

// pool over K for channel ch: weights (exp'd logits) fp16 elg, values fp16 fs.
// two independent accumulation chains.
__device__ __forceinline__ float att_pool_e(const __half2* __restrict__ elg,
                                            const __half2* __restrict__ fs_h, int ch)
{
    const int hidx = ch >> 1;
    const bool hi = (ch & 1);
    float s0 = 0.f, a0 = 0.f, s1 = 0.f, a1 = 0.f;
    #pragma unroll
    for (int k = 0; k < KNN; k += 2) {
        __half2 eh0 = elg[k * FS_H2 + hidx];
        __half2 vh0 = fs_h[k * FS_H2 + hidx];
        __half2 eh1 = elg[(k + 1) * FS_H2 + hidx];
        __half2 vh1 = fs_h[(k + 1) * FS_H2 + hidx];
        float e0 = hi ? __high2float(eh0) : __low2float(eh0);
        float v0 = hi ? __high2float(vh0) : __low2float(vh0);
        float e1 = hi ? __high2float(eh1) : __low2float(eh1);
        float v1 = hi ? __high2float(vh1) : __low2float(vh1);
        s0 += e0; a0 += e0 * v0;
        s1 += e1; a1 += e1 * v1;
    }
    return __fdividef(a0 + a1, s0 + s1);
}

// ---------------------------------------------------------------------------
// Kernel 1: f_pc = ReLU((feature @ w_mlp1) * s + b)
// ---------------------------------------------------------------------------
__global__ __launch_bounds__(256) void kern_mlp1(
    const float* __restrict__ feature,
    const float* __restrict__ w, const float* __restrict__ s, const float* __restrict__ b)
{
    __shared__ float xs[8][32];

    const int lane = threadIdx.x & 31;
    const int warp = threadIdx.x >> 5;

    float wcol[32];
    #pragma unroll
    for (int j = 0; j < 32; j++) wcol[j] = w[j * 32 + lane];
    const float sv = s[lane];
    const float bv = b[lane];

    const int nwarps = (gridDim.x * blockDim.x) >> 5;
    int gw = (blockIdx.x * blockDim.x + threadIdx.x) >> 5;

    for (int p = gw; p < P_TOTAL; p += nwarps) {
        xs[warp][lane] = feature[(size_t)p * 32 + lane];
        __syncwarp();
        float acc = 0.f;
        #pragma unroll
        for (int j4 = 0; j4 < 32; j4 += 4) {
            float4 f = *(const float4*)(&xs[warp][j4]);
            acc += f.x * wcol[j4] + f.y * wcol[j4 + 1]
                 + f.z * wcol[j4 + 2] + f.w * wcol[j4 + 3];
        }
        g_f_pc[(size_t)p * 32 + lane] = fmaxf(acc * sv + bv, 0.f);
        __syncwarp();
    }
}

// ---------------------------------------------------------------------------
// Kernel 2: TWO points per warp. rel_pos + lfa1(f16) + gather + logits->exp +
//           pool(fp16) + f_agg ; lfa2(f16) -> g_fx2.  20 warps.
// per warp floats: fs0 576 + fs1 576 + elg0 576 + elg1 576 + agg 128 = 2432
// ---------------------------------------------------------------------------
#define K2_WARP_FLOATS 2432
#define K2_BASE_FLOATS 5216
#define K2_WARPS 20
#define K2_SMEM_BYTES ((K2_BASE_FLOATS + K2_WARPS * K2_WARP_FLOATS) * 4)

__global__ __launch_bounds__(640) void kern_att1(
    const float* __restrict__ xyz, const int* __restrict__ neigh,
    const float* __restrict__ wlfa1, const float* __restrict__ slfa1, const float* __restrict__ blfa1,
    const float* __restrict__ wfc1,
    const float* __restrict__ wam1, const float* __restrict__ sam1, const float* __restrict__ bam1,
    const float* __restrict__ wlfa2, const float* __restrict__ slfa2, const float* __restrict__ blfa2)
{
    extern __shared__ float sm[];
    uint2*  s_wfcp = (uint2*)sm;              // [16][68] uint2 = 2176 floats
    float2* s_wamp = (float2*)(sm + 2176);    // [32][32] float2 = 2048 floats
    uint2*  s_wl1p = (uint2*)(sm + 4224);     // [4][36] uint2 = 288 floats
    uint2*  s_wl2p = (uint2*)(sm + 4512);     // [8][36] uint2 = 576 floats
    float*  s_vec  = sm + 5088;               // 128: blfa1, blfa2, bam1
    float*  s_wrp  = sm + K2_BASE_FLOATS;

    for (int i = threadIdx.x; i < 1024; i += blockDim.x) {
        int r = i >> 6, c = i & 63;
        int q = r >> 2, t = r & 3;
        int k0 = 16 * q + 2 * t;
        s_wfcp[r * WH64 + c] = make_uint2(
            f2_to_u(wfc1[k0 * 64 + c], wfc1[(k0 + 1) * 64 + c]),
            f2_to_u(wfc1[(k0 + 8) * 64 + c], wfc1[(k0 + 9) * 64 + c]));
    }
    for (int i = threadIdx.x; i < 1024; i += blockDim.x) {
        int r = i >> 5, c = i & 31;
        s_wamp[r * 32 + c] = make_float2(wam1[(2 * r) * 32 + c] * sam1[c],
                                         wam1[(2 * r + 1) * 32 + c] * sam1[c]);
    }
    for (int i = threadIdx.x; i < 128; i += blockDim.x) {
        int t = i >> 5, c = i & 31;
        int k0 = 2 * t, k1 = 2 * t + 8;
        float w00 = wlfa1[k0 * 32 + c] * slfa1[c];
        float w01 = wlfa1[(k0 + 1) * 32 + c] * slfa1[c];
        float w10 = (k1 < 10) ? wlfa1[k1 * 32 + c] * slfa1[c] : 0.f;
        float w11 = (k1 + 1 < 10) ? wlfa1[(k1 + 1) * 32 + c] * slfa1[c] : 0.f;
        s_wl1p[t * WH32 + c] = make_uint2(f2_to_u(w00, w01), f2_to_u(w10, w11));
    }
    for (int i = threadIdx.x; i < 256; i += blockDim.x) {
        int r = i >> 5, c = i & 31;
        int q = r >> 2, t = r & 3;
        int k0 = 16 * q + 2 * t;
        s_wl2p[r * WH32 + c] = make_uint2(
            f2_to_u(wlfa2[k0 * 32 + c] * slfa2[c], wlfa2[(k0 + 1) * 32 + c] * slfa2[c]),
            f2_to_u(wlfa2[(k0 + 8) * 32 + c] * slfa2[c], wlfa2[(k0 + 9) * 32 + c] * slfa2[c]));
    }
    if (threadIdx.x < 32) {
        int l = threadIdx.x;
        s_vec[l]      = blfa1[l];
        s_vec[32 + l] = blfa2[l];
        s_vec[64 + l] = bam1[l];
    }
    __syncthreads();

    const int lane = threadIdx.x & 31;
    const int warp = threadIdx.x >> 5;
    const int gid = lane >> 2, tig = lane & 3;
    float* wbase = s_wrp + warp * K2_WARP_FLOATS;
    __half2*  fs0_h = (__half2*)wbase;            // [16][36] half2
    __half2*  fs1_h = (__half2*)(wbase + 576);
    unsigned* fsw0  = (unsigned*)fs0_h;
    unsigned* fsw1  = (unsigned*)fs1_h;
    __half2*  elg0  = (__half2*)(wbase + 1152);   // [16][36] half2 (weights)
    __half2*  elg1  = (__half2*)(wbase + 1728);
    __half2*  rp0   = elg0;                       // relpos aliases elg (dead)
    __half2*  rp1   = elg1;
    unsigned* rp0w  = (unsigned*)rp0;
    unsigned* rp1w  = (unsigned*)rp1;
    float* agg_s = wbase + 2304;                  // [128]

    const int nwarps = (gridDim.x * blockDim.x) >> 5;
    int gw = (blockIdx.x * blockDim.x + threadIdx.x) >> 5;

    for (int pp = gw; pp < P_TOTAL / 2; pp += nwarps) {
        const int p0 = 2 * pp, p1 = p0 + 1;
        const int b = p0 / NPTS;
        const size_t bbase = (size_t)b * NPTS;

        int idx = neigh[(size_t)p0 * KNN + lane];

        // gather both points' neighbor features; gv dies after the fp16 pack
        {
            float gv0[KNN], gv1[KNN];
            #pragma unroll
            for (int k = 0; k < KNN; k++) {
                int nb = __shfl_sync(0xffffffffu, idx, k);
                gv0[k] = g_f_pc[(bbase + (size_t)nb) * 32 + lane];
            }
            #pragma unroll
            for (int k = 0; k < KNN; k++) {
                int nb = __shfl_sync(0xffffffffu, idx, 16 + k);
                gv1[k] = g_f_pc[(bbase + (size_t)nb) * 32 + lane];
            }
            #pragma unroll
            for (int k = 0; k < KNN; k++) {
                float v0 = gv0[k];
                float v1 = __shfl_xor_sync(0xffffffffu, v0, 1);
                if (!(lane & 1))
                    fs0_h[k * FS_H2 + (lane >> 1)] = __floats2half2_rn(v0, v1);
            }
            #pragma unroll
            for (int k = 0; k < KNN; k++) {
                float v0 = gv1[k];
                float v1 = __shfl_xor_sync(0xffffffffu, v0, 1);
                if (!(lane & 1))
                    fs1_h[k * FS_H2 + (lane >> 1)] = __floats2half2_rn(v0, v1);
            }
        }

        {
            const int myp = (lane < 16) ? p0 : p1;
            const int krow = lane & 15;
            float cx = xyz[(size_t)myp * 3 + 0];
            float cy = xyz[(size_t)myp * 3 + 1];
            float cz = xyz[(size_t)myp * 3 + 2];
            size_t nb = bbase + (size_t)idx;
            float nx = xyz[nb * 3 + 0], ny = xyz[nb * 3 + 1], nz = xyz[nb * 3 + 2];
            float rx = cx - nx, ry = cy - ny, rz = cz - nz;
            float d = sqrtf(rx * rx + ry * ry + rz * rz);
            __half2* rp = (lane < 16) ? rp0 : rp1;
            __half2 z = __floats2half2_rn(0.f, 0.f);
            rp[krow * RP2 + 0] = __floats2half2_rn(d, rx);
            rp[krow * RP2 + 1] = __floats2half2_rn(ry, rz);
            rp[krow * RP2 + 2] = __floats2half2_rn(cx, cy);
            rp[krow * RP2 + 3] = __floats2half2_rn(cz, nx);
            rp[krow * RP2 + 4] = __floats2half2_rn(ny, nz);
            rp[krow * RP2 + 5] = z;
            rp[krow * RP2 + 6] = z;
            rp[krow * RP2 + 7] = z;
        }
        __syncwarp();

        // lfa1 via f16 mma (K=16 covers all 10 rows), B shared
        {
            unsigned a00 = rp0w[gid * RP2 + tig];
            unsigned a01 = rp0w[(gid + 8) * RP2 + tig];
            unsigned a02 = rp0w[gid * RP2 + tig + 4];
            unsigned a03 = rp0w[(gid + 8) * RP2 + tig + 4];
            unsigned a10 = rp1w[gid * RP2 + tig];
            unsigned a11 = rp1w[(gid + 8) * RP2 + tig];
            unsigned a12 = rp1w[gid * RP2 + tig + 4];
            unsigned a13 = rp1w[(gid + 8) * RP2 + tig + 4];
            float ac0[4][4], ac1[4][4];
            #pragma unroll
            for (int n = 0; n < 4; n++)
                #pragma unroll
                for (int j = 0; j < 4; j++) { ac0[n][j] = 0.f; ac1[n][j] = 0.f; }
            const uint2* br = s_wl1p + tig * WH32 + gid;
            #pragma unroll
            for (int n = 0; n < 4; n++) {
                uint2 bb = br[8 * n];
                mma_f16(ac0[n], a00, a01, a02, a03, bb.x, bb.y);
                mma_f16(ac1[n], a10, a11, a12, a13, bb.x, bb.y);
            }
            #pragma unroll
            for (int n = 0; n < 4; n++) {
                int c0 = n * 8 + 2 * tig;
                float b0 = s_vec[c0], b1 = s_vec[c0 + 1];
                fs0_h[gid * FS_H2 + 16 + n * 4 + tig] =
                    __floats2half2_rn(fmaxf(ac0[n][0] + b0, 0.f), fmaxf(ac0[n][1] + b1, 0.f));
                fs0_h[(gid + 8) * FS_H2 + 16 + n * 4 + tig] =
                    __floats2half2_rn(fmaxf(ac0[n][2] + b0, 0.f), fmaxf(ac0[n][3] + b1, 0.f));
                fs1_h[gid * FS_H2 + 16 + n * 4 + tig] =
                    __floats2half2_rn(fmaxf(ac1[n][0] + b0, 0.f), fmaxf(ac1[n][1] + b1, 0.f));
                fs1_h[(gid + 8) * FS_H2 + 16 + n * 4 + tig] =
                    __floats2half2_rn(fmaxf(ac1[n][2] + b0, 0.f), fmaxf(ac1[n][3] + b1, 0.f));
            }
        }
        __syncwarp();

        // logits mma -> exp -> fp16 weight tiles (overwrites rp -- dead)
        logits_exp_x2(fsw0, fsw1, elg0, elg1, s_wfcp, lane);
        __syncwarp();
        agg_s[lane]       = att_pool_e(elg0, fs0_h, lane);
        agg_s[32 + lane]  = att_pool_e(elg0, fs0_h, 32 + lane);
        agg_s[64 + lane]  = att_pool_e(elg1, fs1_h, lane);
        agg_s[96 + lane]  = att_pool_e(elg1, fs1_h, 32 + lane);
        __syncwarp();

        // f_agg for both points, wam read once
        {
            float acc0 = 0.f, acc1 = 0.f;
            #pragma unroll
            for (int d2 = 0; d2 < 32; d2 += 2) {
                float4 a0 = *(const float4*)(agg_s + 2 * d2);
                float4 a1 = *(const float4*)(agg_s + 64 + 2 * d2);
                float2 w0 = s_wamp[d2 * 32 + lane];
                float2 w1 = s_wamp[(d2 + 1) * 32 + lane];
                acc0 += a0.x * w0.x + a0.y * w0.y + a0.z * w1.x + a0.w * w1.y;
                acc1 += a1.x * w0.x + a1.y * w0.y + a1.z * w1.x + a1.w * w1.y;
            }
            float bb = s_vec[64 + lane];
            g_f_agg[(size_t)p0 * 32 + lane] = fmaxf(acc0 + bb, 0.f);
            g_f_agg[(size_t)p1 * 32 + lane] = fmaxf(acc1 + bb, 0.f);
        }

        // lfa2 via f16 mma, B shared -> g_fx2
        {
            float ac0[4][4], ac1[4][4];
            #pragma unroll
            for (int n = 0; n < 4; n++)
                #pragma unroll
                for (int j = 0; j < 4; j++) { ac0[n][j] = 0.f; ac1[n][j] = 0.f; }
            #pragma unroll
            for (int q = 0; q < 2; q++) {
                unsigned a00 = fsw0[gid * FS_H2 + 16 + q * 8 + tig];
                unsigned a01 = fsw0[(gid + 8) * FS_H2 + 16 + q * 8 + tig];
                unsigned a02 = fsw0[gid * FS_H2 + 16 + q * 8 + tig + 4];
                unsigned a03 = fsw0[(gid + 8) * FS_H2 + 16 + q * 8 + tig + 4];
                unsigned a10 = fsw1[gid * FS_H2 + 16 + q * 8 + tig];
                unsigned a11 = fsw1[(gid + 8) * FS_H2 + 16 + q * 8 + tig];
                unsigned a12 = fsw1[gid * FS_H2 + 16 + q * 8 + tig + 4];
                unsigned a13 = fsw1[(gid + 8) * FS_H2 + 16 + q * 8 + tig + 4];
                const uint2* br = s_wl2p + (q * 4 + tig) * WH32 + gid;
                #pragma unroll
                for (int n = 0; n < 4; n++) {
                    uint2 bb = br[8 * n];
                    mma_f16(ac0[n], a00, a01, a02, a03, bb.x, bb.y);
                    mma_f16(ac1[n], a10, a11, a12, a13, bb.x, bb.y);
                }
            }
            #pragma unroll
            for (int n = 0; n < 4; n++) {
                int c0 = n * 8 + 2 * tig;
                float b0 = s_vec[32 + c0], b1 = s_vec[32 + c0 + 1];
                g_fx2[((size_t)p0 * KNN + gid) * 16 + (c0 >> 1)] =
                    __floats2half2_rn(fmaxf(ac0[n][0] + b0, 0.f), fmaxf(ac0[n][1] + b1, 0.f));
                g_fx2[((size_t)p0 * KNN + gid + 8) * 16 + (c0 >> 1)] =
                    __floats2half2_rn(fmaxf(ac0[n][2] + b0, 0.f), fmaxf(ac0[n][3] + b1, 0.f));
                g_fx2[((size_t)p1 * KNN + gid) * 16 + (c0 >> 1)] =
                    __floats2half2_rn(fmaxf(ac1[n][0] + b0, 0.f), fmaxf(ac1[n][1] + b1, 0.f));
                g_fx2[((size_t)p1 * KNN + gid + 8) * 16 + (c0 >> 1)] =
                    __floats2half2_rn(fmaxf(ac1[n][2] + b0, 0.f), fmaxf(ac1[n][3] + b1, 0.f));
            }
        }
        __syncwarp();
    }
}

// ---------------------------------------------------------------------------
// Kernel 3: TWO points per warp: gather(f_agg) + fx2 + logits->exp +
//           pools(fp16) -> g_agg2.  23 warps.
// per warp floats: fs0 576 + fs1 576 + elg0 576 + elg1 576 = 2304
// ---------------------------------------------------------------------------
#define K3_WARP_FLOATS 2304
#define K3_BASE_FLOATS 2176
#define K3_WARPS 23
#define K3_SMEM_BYTES ((K3_BASE_FLOATS + K3_WARPS * K3_WARP_FLOATS) * 4)

__global__ __launch_bounds__(736) void kern_att2(
    const int* __restrict__ neigh,
    const float* __restrict__ wfc2)
{
    extern __shared__ float sm[];
    uint2* s_wfcp = (uint2*)sm;               // [16][68] uint2
    float* s_wrp  = sm + K3_BASE_FLOATS;

    for (int i = threadIdx.x; i < 1024; i += blockDim.x) {
        int r = i >> 6, c = i & 63;
        int q = r >> 2, t = r & 3;
        int k0 = 16 * q + 2 * t;
        s_wfcp[r * WH64 + c] = make_uint2(
            f2_to_u(wfc2[k0 * 64 + c], wfc2[(k0 + 1) * 64 + c]),
            f2_to_u(wfc2[(k0 + 8) * 64 + c], wfc2[(k0 + 9) * 64 + c]));
    }
    __syncthreads();

    const int lane = threadIdx.x & 31;
    const int warp = threadIdx.x >> 5;
    float* wbase = s_wrp + warp * K3_WARP_FLOATS;
    __half2*  fs0_h = (__half2*)wbase;
    __half2*  fs1_h = (__half2*)(wbase + 576);
    unsigned* fsw0  = (unsigned*)fs0_h;
    unsigned* fsw1  = (unsigned*)fs1_h;
    __half2*  elg0  = (__half2*)(wbase + 1152);
    __half2*  elg1  = (__half2*)(wbase + 1728);

    const int kk = lane >> 4;
    const int jj = lane & 15;

    const int nwarps = (gridDim.x * blockDim.x) >> 5;
    int gw = (blockIdx.x * blockDim.x + threadIdx.x) >> 5;

    for (int pp = gw; pp < P_TOTAL / 2; pp += nwarps) {
        const int p0 = 2 * pp, p1 = p0 + 1;
        const int b = p0 / NPTS;
        const size_t bbase = (size_t)b * NPTS;

        int idx = neigh[(size_t)p0 * KNN + lane];

        {
            float gv0[KNN], gv1[KNN];
            #pragma unroll
            for (int k = 0; k < KNN; k++) {
                int nb = __shfl_sync(0xffffffffu, idx, k);
                gv0[k] = g_f_agg[(bbase + (size_t)nb) * 32 + lane];
            }
            #pragma unroll
            for (int k = 0; k < KNN; k++) {
                int nb = __shfl_sync(0xffffffffu, idx, 16 + k);
                gv1[k] = g_f_agg[(bbase + (size_t)nb) * 32 + lane];
            }
            #pragma unroll
            for (int k = 0; k < KNN; k++) {
                float v0 = gv0[k];
                float v1 = __shfl_xor_sync(0xffffffffu, v0, 1);
                if (!(lane & 1))
                    fs0_h[k * FS_H2 + (lane >> 1)] = __floats2half2_rn(v0, v1);
            }
            #pragma unroll
            for (int k = 0; k < KNN; k++) {
                float v0 = gv1[k];
                float v1 = __shfl_xor_sync(0xffffffffu, v0, 1);
                if (!(lane & 1))
                    fs1_h[k * FS_H2 + (lane >> 1)] = __floats2half2_rn(v0, v1);
            }
        }
        const unsigned* src0 = (const unsigned*)(g_fx2 + (size_t)p0 * KNN * 16);
        const unsigned* src1 = (const unsigned*)(g_fx2 + (size_t)p1 * KNN * 16);
        #pragma unroll
        for (int k = 0; k < KNN; k += 2) {
            fsw0[(k + kk) * FS_H2 + 16 + jj] = src0[(k + kk) * 16 + jj];
            fsw1[(k + kk) * FS_H2 + 16 + jj] = src1[(k + kk) * 16 + jj];
        }
        __syncwarp();

        logits_exp_x2(fsw0, fsw1, elg0, elg1, s_wfcp, lane);
        __syncwarp();

        g_agg2[(size_t)p0 * 64 + lane]      = att_pool_e(elg0, fs0_h, lane);
        g_agg2[(size_t)p0 * 64 + 32 + lane] = att_pool_e(elg0, fs0_h, 32 + lane);
        g_agg2[(size_t)p1 * 64 + lane]      = att_pool_e(elg1, fs1_h, lane);
        g_agg2[(size_t)p1 * 64 + 32 + lane] = att_pool_e(elg1, fs1_h, 32 + lane);
        __syncwarp();
    }
}

// ---------------------------------------------------------------------------
// Kernel 4: 16-point tiles, SINGLE TF32 GEMMs with float2-packed B.
// ---------------------------------------------------------------------------
#define OUT_WARPS 16
#define OUT_BASE_FLOATS 17216
#define OUT_WARP_FLOATS 1600
#define OUT_SMEM_BYTES ((OUT_BASE_FLOATS + OUT_WARPS * OUT_WARP_FLOATS) * 4)

__global__ __launch_bounds__(512) void kern_out(
    const float* __restrict__ feature,
    const float* __restrict__ wam2, const float* __restrict__ sam2, const float* __restrict__ bam2,
    const float* __restrict__ wmlp2, const float* __restrict__ smlp2, const float* __restrict__ bmlp2,
    const float* __restrict__ wsc, const float* __restrict__ ssc, const float* __restrict__ bsc,
    float* __restrict__ out)
{
    extern __shared__ float sm[];
    float2* w1p  = (float2*)sm;              // [32][68] float2 = 4352 floats
    float2* w23p = (float2*)(sm + 4352);     // [48][132] float2 = 12672 floats
    float*  b1   = sm + 17024;               // [64]
    float*  b2   = sm + 17088;               // [128]
    float*  wrp  = sm + OUT_BASE_FLOATS;

    for (int i = threadIdx.x; i < 2048; i += blockDim.x) {
        int r = i >> 6, c = i & 63;
        int k0 = (r >> 2) * 8 + (r & 3), k1 = k0 + 4;
        w1p[r * P2F64 + c] = make_float2(to_tf32(wam2[k0 * 64 + c] * sam2[c]),
                                         to_tf32(wam2[k1 * 64 + c] * sam2[c]));
    }
    for (int i = threadIdx.x; i < 6144; i += blockDim.x) {
        int r = i >> 7, c = i & 127;
        int k0 = (r >> 2) * 8 + (r & 3), k1 = k0 + 4;
        float v0 = (k0 < 64) ? wmlp2[k0 * 128 + c] * smlp2[c] : wsc[(k0 - 64) * 128 + c] * ssc[c];
        float v1 = (k1 < 64) ? wmlp2[k1 * 128 + c] * smlp2[c] : wsc[(k1 - 64) * 128 + c] * ssc[c];
        w23p[r * P2F128 + c] = make_float2(to_tf32(v0), to_tf32(v1));
    }
    if (threadIdx.x < 64)  b1[threadIdx.x] = bam2[threadIdx.x];
    if (threadIdx.x < 128) b2[threadIdx.x] = bmlp2[threadIdx.x] + bsc[threadIdx.x];
    __syncthreads();

    const int lane = threadIdx.x & 31;
    const int warp = threadIdx.x >> 5;
    const int gid = lane >> 2, tig = lane & 3;
    float* A1 = wrp + warp * OUT_WARP_FLOATS;  // [16][100]

    const int nwarps = (gridDim.x * blockDim.x) >> 5;
    int gw = (blockIdx.x * blockDim.x + threadIdx.x) >> 5;
    const int ntiles = P_TOTAL / 16;

    for (int t = gw; t < ntiles; t += nwarps) {
        const int p0 = t * 16;

        #pragma unroll
        for (int r = 0; r < 16; r++) {
            A1[r * OA_PAD + lane]      = g_agg2[(size_t)(p0 + r) * 64 + lane];
            A1[r * OA_PAD + 32 + lane] = g_agg2[(size_t)(p0 + r) * 64 + 32 + lane];
            A1[r * OA_PAD + 64 + lane] = feature[(size_t)(p0 + r) * 32 + lane];
        }
        __syncwarp();

        // GEMM1 (single tf32): pc2 = relu(agg @ w1 + b1) -> A cols 0..63
        {
            float acc[8][4];
            #pragma unroll
            for (int n = 0; n < 8; n++) { acc[n][0]=0.f; acc[n][1]=0.f; acc[n][2]=0.f; acc[n][3]=0.f; }
            #pragma unroll
            for (int q = 0; q < 8; q++) {
                unsigned a0 = __float_as_uint(to_tf32(A1[gid * OA_PAD + q * 8 + tig]));
                unsigned a1 = __float_as_uint(to_tf32(A1[(gid + 8) * OA_PAD + q * 8 + tig]));
                unsigned a2 = __float_as_uint(to_tf32(A1[gid * OA_PAD + q * 8 + tig + 4]));
                unsigned a3 = __float_as_uint(to_tf32(A1[(gid + 8) * OA_PAD + q * 8 + tig + 4]));
                const float2* br = w1p + (q * 4 + tig) * P2F64 + gid;
                #pragma unroll
                for (int n = 0; n < 8; n++) {
                    float2 b = br[8 * n];
                    mma_tf32(acc[n], a0, a1, a2, a3,
                             __float_as_uint(b.x), __float_as_uint(b.y));
                }
            }
            __syncwarp();
            #pragma unroll
            for (int n = 0; n < 8; n++) {
                int c0 = n * 8 + 2 * tig;
                float bb0 = b1[c0], bb1 = b1[c0 + 1];
                *(float2*)(A1 + gid * OA_PAD + c0) =
                    make_float2(fmaxf(acc[n][0] + bb0, 0.f), fmaxf(acc[n][1] + bb1, 0.f));
                *(float2*)(A1 + (gid + 8) * OA_PAD + c0) =
                    make_float2(fmaxf(acc[n][2] + bb0, 0.f), fmaxf(acc[n][3] + bb1, 0.f));
            }
        }
        __syncwarp();

        // GEMM2 (single tf32): out = leaky(A[16][96] @ w23 + b2), two n-halves
        #pragma unroll
        for (int h = 0; h < 2; h++) {
            float acc[8][4];
            #pragma unroll
            for (int n = 0; n < 8; n++) { acc[n][0]=0.f; acc[n][1]=0.f; acc[n][2]=0.f; acc[n][3]=0.f; }
            #pragma unroll
            for (int q = 0; q < 12; q++) {
                unsigned a0 = __float_as_uint(to_tf32(A1[gid * OA_PAD + q * 8 + tig]));
                unsigned a1 = __float_as_uint(to_tf32(A1[(gid + 8) * OA_PAD + q * 8 + tig]));
                unsigned a2 = __float_as_uint(to_tf32(A1[gid * OA_PAD + q * 8 + tig + 4]));
                unsigned a3 = __float_as_uint(to_tf32(A1[(gid + 8) * OA_PAD + q * 8 + tig + 4]));
                const float2* br = w23p + (q * 4 + tig) * P2F128 + h * 64 + gid;
                #pragma unroll
                for (int n = 0; n < 8; n++) {
                    float2 b = br[8 * n];
                    mma_tf32(acc[n], a0, a1, a2, a3,
                             __float_as_uint(b.x), __float_as_uint(b.y));
                }
            }
            #pragma unroll
            for (int n = 0; n < 8; n++) {
                int c0 = h * 64 + n * 8 + 2 * tig;
                float bb0 = b2[c0], bb1 = b2[c0 + 1];
                float v0 = acc[n][0] + bb0; v0 = (v0 < 0.f) ? 0.2f * v0 : v0;
                float v1 = acc[n][1] + bb1; v1 = (v1 < 0.f) ? 0.2f * v1 : v1;
                float v2 = acc[n][2] + bb0; v2 = (v2 < 0.f) ? 0.2f * v2 : v2;
                float v3 = acc[n][3] + bb1; v3 = (v3 < 0.f) ? 0.2f * v3 : v3;
                *(float2*)(&out[(size_t)(p0 + gid) * 128 + c0])     = make_float2(v0, v1);
                *(float2*)(&out[(size_t)(p0 + gid + 8) * 128 + c0]) = make_float2(v2, v3);
            }
        }
        __syncwarp();
    }
}

// ---------------------------------------------------------------------------
extern "C" void kernel_launch(void* const* d_in, const int* in_sizes, int n_in,
                              void* d_out, int out_size)
{
    const float* feature = (const float*)d_in[0];
    const float* xyz     = (const float*)d_in[1];
    const int*   neigh   = (const int*)  d_in[2];
    const float* w_mlp1  = (const float*)d_in[3];
    const float* s_mlp1  = (const float*)d_in[4];
    const float* b_mlp1  = (const float*)d_in[5];
    const float* w_lfa1  = (const float*)d_in[6];
    const float* s_lfa1  = (const float*)d_in[7];
    const float* b_lfa1  = (const float*)d_in[8];
    const float* w_fc1   = (const float*)d_in[9];
    const float* w_am1   = (const float*)d_in[10];
    const float* s_am1   = (const float*)d_in[11];
    const float* b_am1   = (const float*)d_in[12];
    const float* w_lfa2  = (const float*)d_in[13];
    const float* s_lfa2  = (const float*)d_in[14];
    const float* b_lfa2  = (const float*)d_in[15];
    const float* w_fc2   = (const float*)d_in[16];
    const float* w_am2   = (const float*)d_in[17];
    const float* s_am2   = (const float*)d_in[18];
    const float* b_am2   = (const float*)d_in[19];
    const float* w_mlp2  = (const float*)d_in[20];
    const float* s_mlp2  = (const float*)d_in[21];
    const float* b_mlp2  = (const float*)d_in[22];
    const float* w_sc    = (const float*)d_in[23];
    const float* s_sc    = (const float*)d_in[24];
    const float* b_sc    = (const float*)d_in[25];
    float* out = (float*)d_out;

    cudaFuncSetAttribute(kern_att1, cudaFuncAttributeMaxDynamicSharedMemorySize, K2_SMEM_BYTES);
    cudaFuncSetAttribute(kern_att2, cudaFuncAttributeMaxDynamicSharedMemorySize, K3_SMEM_BYTES);
    cudaFuncSetAttribute(kern_out,  cudaFuncAttributeMaxDynamicSharedMemorySize, OUT_SMEM_BYTES);

    kern_mlp1<<<2048, 256>>>(feature, w_mlp1, s_mlp1, b_mlp1);

    kern_att1<<<148, 640, K2_SMEM_BYTES>>>(
        xyz, neigh,
        w_lfa1, s_lfa1, b_lfa1,
        w_fc1,
        w_am1, s_am1, b_am1,
        w_lfa2, s_lfa2, b_lfa2);

    kern_att2<<<148, 736, K3_SMEM_BYTES>>>(neigh, w_fc2);

    kern_out<<<148, 512, OUT_SMEM_BYTES>>>(
        feature,
        w_am2, s_am2, b_am2,
        w_mlp2, s_mlp2, b_mlp2,
        w_sc, s_sc, b_sc,
        out);
}

// round 14
// speedup vs baseline: 1.4394x; 1.0884x over previous
#include <cuda_runtime.h>
#include <cuda_fp16.h>
#include <math.h>

#define BATCH 4
#define NPTS  40960
#define KNN   16
#define P_TOTAL (BATCH * NPTS)   // 163840

#define FS_H2  36    // fs/elg tile row stride in half2 units (4 mod 32)
#define WH64   68    // fp16 B-tile stride, 64 cols, uint2 units
#define WH32   36    // fp16 B-tile stride, 32 cols, uint2 units
#define P2F64  68    // float2 B-tile stride, 64 cols (4 mod 16)
#define P2F128 132   // float2 B-tile stride, 128 cols (4 mod 16)
#define RP2    12    // relpos tile stride in half2 units
#define OA_PAD 100   // kern_out A tile stride (4 mod 32)

// Scratch (device globals)
__device__ float   g_f_pc [P_TOTAL * 32];                    // 21 MB
__device__ float   g_f_agg[P_TOTAL * 32];                    // 21 MB
__device__ float   g_agg2 [(size_t)P_TOTAL * 64];            // 42 MB
__device__ __half2 g_fx2  [(size_t)P_TOTAL * KNN * 16];      // 168 MB

__device__ __forceinline__ float to_tf32(float x) {
    float r;
    asm("cvt.rna.tf32.f32 %0, %1;" : "=f"(r) : "f"(x));
    return r;
}
__device__ __forceinline__ unsigned f2_to_u(float a, float b) {
    __half2 h = __floats2half2_rn(a, b);
    return *(unsigned*)&h;
}

__device__ __forceinline__ void mma_tf32(float* c,
                                         unsigned a0, unsigned a1, unsigned a2, unsigned a3,
                                         unsigned b0, unsigned b1) {
    asm("mma.sync.aligned.m16n8k8.row.col.f32.tf32.tf32.f32 "
        "{%0,%1,%2,%3}, {%4,%5,%6,%7}, {%8,%9}, {%0,%1,%2,%3};"
        : "+f"(c[0]), "+f"(c[1]), "+f"(c[2]), "+f"(c[3])
        : "r"(a0), "r"(a1), "r"(a2), "r"(a3), "r"(b0), "r"(b1));
}
__device__ __forceinline__ void mma_f16(float* c,
                                        unsigned a0, unsigned a1, unsigned a2, unsigned a3,
                                        unsigned b0, unsigned b1) {
    asm("mma.sync.aligned.m16n8k16.row.col.f32.f16.f16.f32 "
        "{%0,%1,%2,%3}, {%4,%5,%6,%7}, {%8,%9}, {%0,%1,%2,%3};"
        : "+f"(c[0]), "+f"(c[1]), "+f"(c[2]), "+f"(c[3])
        : "r"(a0), "r"(a1), "r"(a2), "r"(a3), "r"(b0), "r"(b1));
}

// dual-point logits -> exp(logit-8) stored as fp16 weight tiles (elg).
__device__ __forceinline__ void logits_exp_x2(const unsigned* __restrict__ fsw0,
                                              const unsigned* __restrict__ fsw1,
                                              __half2* __restrict__ elg0,
                                              __half2* __restrict__ elg1,
                                              const uint2* __restrict__ wfc, int lane)
{
    const int gid = lane >> 2;
    const int tig = lane & 3;
    float ac0[8][4], ac1[8][4];
    #pragma unroll
    for (int n = 0; n < 8; n++)
        #pragma unroll
        for (int j = 0; j < 4; j++) { ac0[n][j] = 0.f; ac1[n][j] = 0.f; }
    #pragma unroll
    for (int q = 0; q < 4; q++) {
        unsigned a00 = fsw0[gid * FS_H2 + q * 8 + tig];
        unsigned a01 = fsw0[(gid + 8) * FS_H2 + q * 8 + tig];
        unsigned a02 = fsw0[gid * FS_H2 + q * 8 + tig + 4];
        unsigned a03 = fsw0[(gid + 8) * FS_H2 + q * 8 + tig + 4];
        unsigned a10 = fsw1[gid * FS_H2 + q * 8 + tig];
        unsigned a11 = fsw1[(gid + 8) * FS_H2 + q * 8 + tig];
        unsigned a12 = fsw1[gid * FS_H2 + q * 8 + tig + 4];
        unsigned a13 = fsw1[(gid + 8) * FS_H2 + q * 8 + tig + 4];
        const uint2* br = wfc + (q * 4 + tig) * WH64 + gid;
        #pragma unroll
        for (int n = 0; n < 8; n++) {
            uint2 b = br[8 * n];
            mma_f16(ac0[n], a00, a01, a02, a03, b.x, b.y);
            mma_f16(ac1[n], a10, a11, a12, a13, b.x, b.y);
        }
    }
    #pragma unroll
    for (int n = 0; n < 8; n++) {
        elg0[gid * FS_H2 + n * 4 + tig] =
            __floats2half2_rn(__expf(ac0[n][0] - 8.f), __expf(ac0[n][1] - 8.f));
        elg0[(gid + 8) * FS_H2 + n * 4 + tig] =
            __floats2half2_rn(__expf(ac0[n][2] - 8.f), __expf(ac0[n][3] - 8.f));
        elg1[gid * FS_H2 + n * 4 + tig] =
            __floats2half2_rn(__expf(ac1[n][0] - 8.f), __expf(ac1[n][1] - 8.f));
        elg1[(gid + 8) * FS_H2 + n * 4 + tig] =
            __floats2half2_rn(__expf(ac1[n][2] - 8.f), __expf(ac1[n][3] - 8.f));
    }
}

// Pool for channel pair (2*lane, 2*lane+1) of one point: lane loads the
// half2 at index `lane` in each row (bank (4k+lane)%32 -- conflict-free),
// keeping two (sum, acc) chains per half (even/odd k, same order as before).
__device__ __forceinline__ float2 att_pool_e2(const __half2* __restrict__ elg,
                                              const __half2* __restrict__ fs_h, int lane)
{
    float sx0 = 0.f, ax0 = 0.f, sx1 = 0.f, ax1 = 0.f;
    float sy0 = 0.f, ay0 = 0.f, sy1 = 0.f, ay1 = 0.f;
    #pragma unroll
    for (int k = 0; k < KNN; k += 2) {
        float2 e0 = __half22float2(elg[k * FS_H2 + lane]);
        float2 v0 = __half22float2(fs_h[k * FS_H2 + lane]);
        float2 e1 = __half22float2(elg[(k + 1) * FS_H2 + lane]);
        float2 v1 = __half22float2(fs_h[(k + 1) * FS_H2 + lane]);
        sx0 += e0.x; ax0 += e0.x * v0.x;
        sy0 += e0.y; ay0 += e0.y * v0.y;
        sx1 += e1.x; ax1 += e1.x * v1.x;
        sy1 += e1.y; ay1 += e1.y * v1.y;
    }
    return make_float2(__fdividef(ax0 + ax1, sx0 + sx1),
                       __fdividef(ay0 + ay1, sy0 + sy1));
}

// ---------------------------------------------------------------------------
// Kernel 1: f_pc = ReLU((feature @ w_mlp1) * s + b)
// ---------------------------------------------------------------------------
__global__ __launch_bounds__(256) void kern_mlp1(
    const float* __restrict__ feature,
    const float* __restrict__ w, const float* __restrict__ s, const float* __restrict__ b)
{
    __shared__ float xs[8][32];

    const int lane = threadIdx.x & 31;
    const int warp = threadIdx.x >> 5;

    float wcol[32];
    #pragma unroll
    for (int j = 0; j < 32; j++) wcol[j] = w[j * 32 + lane];
    const float sv = s[lane];
    const float bv = b[lane];

    const int nwarps = (gridDim.x * blockDim.x) >> 5;
    int gw = (blockIdx.x * blockDim.x + threadIdx.x) >> 5;

    for (int p = gw; p < P_TOTAL; p += nwarps) {
        xs[warp][lane] = feature[(size_t)p * 32 + lane];
        __syncwarp();
        float acc = 0.f;
        #pragma unroll
        for (int j4 = 0; j4 < 32; j4 += 4) {
            float4 f = *(const float4*)(&xs[warp][j4]);
            acc += f.x * wcol[j4] + f.y * wcol[j4 + 1]
                 + f.z * wcol[j4 + 2] + f.w * wcol[j4 + 3];
        }
        g_f_pc[(size_t)p * 32 + lane] = fmaxf(acc * sv + bv, 0.f);
        __syncwarp();
    }
}

// ---------------------------------------------------------------------------
// Kernel 2: TWO points per warp. rel_pos + lfa1(f16) + gather + logits->exp +
//           pool(half2 pairs) + f_agg ; lfa2(f16) -> g_fx2.  20 warps.
// ---------------------------------------------------------------------------
#define K2_WARP_FLOATS 2432
#define K2_BASE_FLOATS 5216
#define K2_WARPS 20
#define K2_SMEM_BYTES ((K2_BASE_FLOATS + K2_WARPS * K2_WARP_FLOATS) * 4)

__global__ __launch_bounds__(640) void kern_att1(
    const float* __restrict__ xyz, const int* __restrict__ neigh,
    const float* __restrict__ wlfa1, const float* __restrict__ slfa1, const float* __restrict__ blfa1,
    const float* __restrict__ wfc1,
    const float* __restrict__ wam1, const float* __restrict__ sam1, const float* __restrict__ bam1,
    const float* __restrict__ wlfa2, const float* __restrict__ slfa2, const float* __restrict__ blfa2)
{
    extern __shared__ float sm[];
    uint2*  s_wfcp = (uint2*)sm;              // [16][68] uint2 = 2176 floats
    float2* s_wamp = (float2*)(sm + 2176);    // [32][32] float2 = 2048 floats
    uint2*  s_wl1p = (uint2*)(sm + 4224);     // [4][36] uint2 = 288 floats
    uint2*  s_wl2p = (uint2*)(sm + 4512);     // [8][36] uint2 = 576 floats
    float*  s_vec  = sm + 5088;               // 128: blfa1, blfa2, bam1
    float*  s_wrp  = sm + K2_BASE_FLOATS;

    for (int i = threadIdx.x; i < 1024; i += blockDim.x) {
        int r = i >> 6, c = i & 63;
        int q = r >> 2, t = r & 3;
        int k0 = 16 * q + 2 * t;
        s_wfcp[r * WH64 + c] = make_uint2(
            f2_to_u(wfc1[k0 * 64 + c], wfc1[(k0 + 1) * 64 + c]),
            f2_to_u(wfc1[(k0 + 8) * 64 + c], wfc1[(k0 + 9) * 64 + c]));
    }
    for (int i = threadIdx.x; i < 1024; i += blockDim.x) {
        int r = i >> 5, c = i & 31;
        s_wamp[r * 32 + c] = make_float2(wam1[(2 * r) * 32 + c] * sam1[c],
                                         wam1[(2 * r + 1) * 32 + c] * sam1[c]);
    }
    for (int i = threadIdx.x; i < 128; i += blockDim.x) {
        int t = i >> 5, c = i & 31;
        int k0 = 2 * t, k1 = 2 * t + 8;
        float w00 = wlfa1[k0 * 32 + c] * slfa1[c];
        float w01 = wlfa1[(k0 + 1) * 32 + c] * slfa1[c];
        float w10 = (k1 < 10) ? wlfa1[k1 * 32 + c] * slfa1[c] : 0.f;
        float w11 = (k1 + 1 < 10) ? wlfa1[(k1 + 1) * 32 + c] * slfa1[c] : 0.f;
        s_wl1p[t * WH32 + c] = make_uint2(f2_to_u(w00, w01), f2_to_u(w10, w11));
    }
    for (int i = threadIdx.x; i < 256; i += blockDim.x) {
        int r = i >> 5, c = i & 31;
        int q = r >> 2, t = r & 3;
        int k0 = 16 * q + 2 * t;
        s_wl2p[r * WH32 + c] = make_uint2(
            f2_to_u(wlfa2[k0 * 32 + c] * slfa2[c], wlfa2[(k0 + 1) * 32 + c] * slfa2[c]),
            f2_to_u(wlfa2[(k0 + 8) * 32 + c] * slfa2[c], wlfa2[(k0 + 9) * 32 + c] * slfa2[c]));
    }
    if (threadIdx.x < 32) {
        int l = threadIdx.x;
        s_vec[l]      = blfa1[l];
        s_vec[32 + l] = blfa2[l];
        s_vec[64 + l] = bam1[l];
    }
    __syncthreads();

    const int lane = threadIdx.x & 31;
    const int warp = threadIdx.x >> 5;
    const int gid = lane >> 2, tig = lane & 3;
    float* wbase = s_wrp + warp * K2_WARP_FLOATS;
    __half2*  fs0_h = (__half2*)wbase;            // [16][36] half2
    __half2*  fs1_h = (__half2*)(wbase + 576);
    unsigned* fsw0  = (unsigned*)fs0_h;
    unsigned* fsw1  = (unsigned*)fs1_h;
    __half2*  elg0  = (__half2*)(wbase + 1152);   // [16][36] half2 (weights)
    __half2*  elg1  = (__half2*)(wbase + 1728);
    __half2*  rp0   = elg0;                       // relpos aliases elg (dead)
    __half2*  rp1   = elg1;
    unsigned* rp0w  = (unsigned*)rp0;
    unsigned* rp1w  = (unsigned*)rp1;
    float* agg_s = wbase + 2304;                  // [128]

    const int nwarps = (gridDim.x * blockDim.x) >> 5;
    int gw = (blockIdx.x * blockDim.x + threadIdx.x) >> 5;

    for (int pp = gw; pp < P_TOTAL / 2; pp += nwarps) {
        const int p0 = 2 * pp, p1 = p0 + 1;
        const int b = p0 / NPTS;
        const size_t bbase = (size_t)b * NPTS;

        int idx = neigh[(size_t)p0 * KNN + lane];

        // gather both points' neighbor features; gv dies after the fp16 pack
        {
            float gv0[KNN], gv1[KNN];
            #pragma unroll
            for (int k = 0; k < KNN; k++) {
                int nb = __shfl_sync(0xffffffffu, idx, k);
                gv0[k] = g_f_pc[(bbase + (size_t)nb) * 32 + lane];
            }
            #pragma unroll
            for (int k = 0; k < KNN; k++) {
                int nb = __shfl_sync(0xffffffffu, idx, 16 + k);
                gv1[k] = g_f_pc[(bbase + (size_t)nb) * 32 + lane];
            }
            #pragma unroll
            for (int k = 0; k < KNN; k++) {
                float v0 = gv0[k];
                float v1 = __shfl_xor_sync(0xffffffffu, v0, 1);
                if (!(lane & 1))
                    fs0_h[k * FS_H2 + (lane >> 1)] = __floats2half2_rn(v0, v1);
            }
            #pragma unroll
            for (int k = 0; k < KNN; k++) {
                float v0 = gv1[k];
                float v1 = __shfl_xor_sync(0xffffffffu, v0, 1);
                if (!(lane & 1))
                    fs1_h[k * FS_H2 + (lane >> 1)] = __floats2half2_rn(v0, v1);
            }
        }

        {
            const int myp = (lane < 16) ? p0 : p1;
            const int krow = lane & 15;
            float cx = xyz[(size_t)myp * 3 + 0];
            float cy = xyz[(size_t)myp * 3 + 1];
            float cz = xyz[(size_t)myp * 3 + 2];
            size_t nb = bbase + (size_t)idx;
            float nx = xyz[nb * 3 + 0], ny = xyz[nb * 3 + 1], nz = xyz[nb * 3 + 2];
            float rx = cx - nx, ry = cy - ny, rz = cz - nz;
            float d = sqrtf(rx * rx + ry * ry + rz * rz);
            __half2* rp = (lane < 16) ? rp0 : rp1;
            __half2 z = __floats2half2_rn(0.f, 0.f);
            rp[krow * RP2 + 0] = __floats2half2_rn(d, rx);
            rp[krow * RP2 + 1] = __floats2half2_rn(ry, rz);
            rp[krow * RP2 + 2] = __floats2half2_rn(cx, cy);
            rp[krow * RP2 + 3] = __floats2half2_rn(cz, nx);
            rp[krow * RP2 + 4] = __floats2half2_rn(ny, nz);
            rp[krow * RP2 + 5] = z;
            rp[krow * RP2 + 6] = z;
            rp[krow * RP2 + 7] = z;
        }
        __syncwarp();

        // lfa1 via f16 mma (K=16 covers all 10 rows), B shared
        {
            unsigned a00 = rp0w[gid * RP2 + tig];
            unsigned a01 = rp0w[(gid + 8) * RP2 + tig];
            unsigned a02 = rp0w[gid * RP2 + tig + 4];
            unsigned a03 = rp0w[(gid + 8) * RP2 + tig + 4];
            unsigned a10 = rp1w[gid * RP2 + tig];
            unsigned a11 = rp1w[(gid + 8) * RP2 + tig];
            unsigned a12 = rp1w[gid * RP2 + tig + 4];
            unsigned a13 = rp1w[(gid + 8) * RP2 + tig + 4];
            float ac0[4][4], ac1[4][4];
            #pragma unroll
            for (int n = 0; n < 4; n++)
                #pragma unroll
                for (int j = 0; j < 4; j++) { ac0[n][j] = 0.f; ac1[n][j] = 0.f; }
            const uint2* br = s_wl1p + tig * WH32 + gid;
            #pragma unroll
            for (int n = 0; n < 4; n++) {
                uint2 bb = br[8 * n];
                mma_f16(ac0[n], a00, a01, a02, a03, bb.x, bb.y);
                mma_f16(ac1[n], a10, a11, a12, a13, bb.x, bb.y);
            }
            #pragma unroll
            for (int n = 0; n < 4; n++) {
                int c0 = n * 8 + 2 * tig;
                float b0 = s_vec[c0], b1 = s_vec[c0 + 1];
                fs0_h[gid * FS_H2 + 16 + n * 4 + tig] =
                    __floats2half2_rn(fmaxf(ac0[n][0] + b0, 0.f), fmaxf(ac0[n][1] + b1, 0.f));
                fs0_h[(gid + 8) * FS_H2 + 16 + n * 4 + tig] =
                    __floats2half2_rn(fmaxf(ac0[n][2] + b0, 0.f), fmaxf(ac0[n][3] + b1, 0.f));
                fs1_h[gid * FS_H2 + 16 + n * 4 + tig] =
                    __floats2half2_rn(fmaxf(ac1[n][0] + b0, 0.f), fmaxf(ac1[n][1] + b1, 0.f));
                fs1_h[(gid + 8) * FS_H2 + 16 + n * 4 + tig] =
                    __floats2half2_rn(fmaxf(ac1[n][2] + b0, 0.f), fmaxf(ac1[n][3] + b1, 0.f));
            }
        }
        __syncwarp();

        // logits mma -> exp -> fp16 weight tiles (overwrites rp -- dead)
        logits_exp_x2(fsw0, fsw1, elg0, elg1, s_wfcp, lane);
        __syncwarp();
        // pools: lane handles channel pair (2*lane, 2*lane+1) per point
        *(float2*)(agg_s + 2 * lane)      = att_pool_e2(elg0, fs0_h, lane);
        *(float2*)(agg_s + 64 + 2 * lane) = att_pool_e2(elg1, fs1_h, lane);
        __syncwarp();

        // f_agg for both points, wam read once
        {
            float acc0 = 0.f, acc1 = 0.f;
            #pragma unroll
            for (int d2 = 0; d2 < 32; d2 += 2) {
                float4 a0 = *(const float4*)(agg_s + 2 * d2);
                float4 a1 = *(const float4*)(agg_s + 64 + 2 * d2);
                float2 w0 = s_wamp[d2 * 32 + lane];
                float2 w1 = s_wamp[(d2 + 1) * 32 + lane];
                acc0 += a0.x * w0.x + a0.y * w0.y + a0.z * w1.x + a0.w * w1.y;
                acc1 += a1.x * w0.x + a1.y * w0.y + a1.z * w1.x + a1.w * w1.y;
            }
            float bb = s_vec[64 + lane];
            g_f_agg[(size_t)p0 * 32 + lane] = fmaxf(acc0 + bb, 0.f);
            g_f_agg[(size_t)p1 * 32 + lane] = fmaxf(acc1 + bb, 0.f);
        }

        // lfa2 via f16 mma, B shared -> g_fx2
        {
            float ac0[4][4], ac1[4][4];
            #pragma unroll
            for (int n = 0; n < 4; n++)
                #pragma unroll
                for (int j = 0; j < 4; j++) { ac0[n][j] = 0.f; ac1[n][j] = 0.f; }
            #pragma unroll
            for (int q = 0; q < 2; q++) {
                unsigned a00 = fsw0[gid * FS_H2 + 16 + q * 8 + tig];
                unsigned a01 = fsw0[(gid + 8) * FS_H2 + 16 + q * 8 + tig];
                unsigned a02 = fsw0[gid * FS_H2 + 16 + q * 8 + tig + 4];
                unsigned a03 = fsw0[(gid + 8) * FS_H2 + 16 + q * 8 + tig + 4];
                unsigned a10 = fsw1[gid * FS_H2 + 16 + q * 8 + tig];
                unsigned a11 = fsw1[(gid + 8) * FS_H2 + 16 + q * 8 + tig];
                unsigned a12 = fsw1[gid * FS_H2 + 16 + q * 8 + tig + 4];
                unsigned a13 = fsw1[(gid + 8) * FS_H2 + 16 + q * 8 + tig + 4];
                const uint2* br = s_wl2p + (q * 4 + tig) * WH32 + gid;
                #pragma unroll
                for (int n = 0; n < 4; n++) {
                    uint2 bb = br[8 * n];
                    mma_f16(ac0[n], a00, a01, a02, a03, bb.x, bb.y);
                    mma_f16(ac1[n], a10, a11, a12, a13, bb.x, bb.y);
                }
            }
            #pragma unroll
            for (int n = 0; n < 4; n++) {
                int c0 = n * 8 + 2 * tig;
                float b0 = s_vec[32 + c0], b1 = s_vec[32 + c0 + 1];
                g_fx2[((size_t)p0 * KNN + gid) * 16 + (c0 >> 1)] =
                    __floats2half2_rn(fmaxf(ac0[n][0] + b0, 0.f), fmaxf(ac0[n][1] + b1, 0.f));
                g_fx2[((size_t)p0 * KNN + gid + 8) * 16 + (c0 >> 1)] =
                    __floats2half2_rn(fmaxf(ac0[n][2] + b0, 0.f), fmaxf(ac0[n][3] + b1, 0.f));
                g_fx2[((size_t)p1 * KNN + gid) * 16 + (c0 >> 1)] =
                    __floats2half2_rn(fmaxf(ac1[n][0] + b0, 0.f), fmaxf(ac1[n][1] + b1, 0.f));
                g_fx2[((size_t)p1 * KNN + gid + 8) * 16 + (c0 >> 1)] =
                    __floats2half2_rn(fmaxf(ac1[n][2] + b0, 0.f), fmaxf(ac1[n][3] + b1, 0.f));
            }
        }
        __syncwarp();
    }
}

// ---------------------------------------------------------------------------
// Kernel 3: TWO points per warp: gather(f_agg) + fx2 + logits->exp +
//           pools(half2 pairs) -> g_agg2.  23 warps.
// ---------------------------------------------------------------------------
#define K3_WARP_FLOATS 2304
#define K3_BASE_FLOATS 2176
#define K3_WARPS 23
#define K3_SMEM_BYTES ((K3_BASE_FLOATS + K3_WARPS * K3_WARP_FLOATS) * 4)

__global__ __launch_bounds__(736) void kern_att2(
    const int* __restrict__ neigh,
    const float* __restrict__ wfc2)
{
    extern __shared__ float sm[];
    uint2* s_wfcp = (uint2*)sm;               // [16][68] uint2
    float* s_wrp  = sm + K3_BASE_FLOATS;

    for (int i = threadIdx.x; i < 1024; i += blockDim.x) {
        int r = i >> 6, c = i & 63;
        int q = r >> 2, t = r & 3;
        int k0 = 16 * q + 2 * t;
        s_wfcp[r * WH64 + c] = make_uint2(
            f2_to_u(wfc2[k0 * 64 + c], wfc2[(k0 + 1) * 64 + c]),
            f2_to_u(wfc2[(k0 + 8) * 64 + c], wfc2[(k0 + 9) * 64 + c]));
    }
    __syncthreads();

    const int lane = threadIdx.x & 31;
    const int warp = threadIdx.x >> 5;
    float* wbase = s_wrp + warp * K3_WARP_FLOATS;
    __half2*  fs0_h = (__half2*)wbase;
    __half2*  fs1_h = (__half2*)(wbase + 576);
    unsigned* fsw0  = (unsigned*)fs0_h;
    unsigned* fsw1  = (unsigned*)fs1_h;
    __half2*  elg0  = (__half2*)(wbase + 1152);
    __half2*  elg1  = (__half2*)(wbase + 1728);

    const int kk = lane >> 4;
    const int jj = lane & 15;

    const int nwarps = (gridDim.x * blockDim.x) >> 5;
    int gw = (blockIdx.x * blockDim.x + threadIdx.x) >> 5;

    for (int pp = gw; pp < P_TOTAL / 2; pp += nwarps) {
        const int p0 = 2 * pp, p1 = p0 + 1;
        const int b = p0 / NPTS;
        const size_t bbase = (size_t)b * NPTS;

        int idx = neigh[(size_t)p0 * KNN + lane];

        {
            float gv0[KNN], gv1[KNN];
            #pragma unroll
            for (int k = 0; k < KNN; k++) {
                int nb = __shfl_sync(0xffffffffu, idx, k);
                gv0[k] = g_f_agg[(bbase + (size_t)nb) * 32 + lane];
            }
            #pragma unroll
            for (int k = 0; k < KNN; k++) {
                int nb = __shfl_sync(0xffffffffu, idx, 16 + k);
                gv1[k] = g_f_agg[(bbase + (size_t)nb) * 32 + lane];
            }
            #pragma unroll
            for (int k = 0; k < KNN; k++) {
                float v0 = gv0[k];
                float v1 = __shfl_xor_sync(0xffffffffu, v0, 1);
                if (!(lane & 1))
                    fs0_h[k * FS_H2 + (lane >> 1)] = __floats2half2_rn(v0, v1);
            }
            #pragma unroll
            for (int k = 0; k < KNN; k++) {
                float v0 = gv1[k];
                float v1 = __shfl_xor_sync(0xffffffffu, v0, 1);
                if (!(lane & 1))
                    fs1_h[k * FS_H2 + (lane >> 1)] = __floats2half2_rn(v0, v1);
            }
        }
        const unsigned* src0 = (const unsigned*)(g_fx2 + (size_t)p0 * KNN * 16);
        const unsigned* src1 = (const unsigned*)(g_fx2 + (size_t)p1 * KNN * 16);
        #pragma unroll
        for (int k = 0; k < KNN; k += 2) {
            fsw0[(k + kk) * FS_H2 + 16 + jj] = src0[(k + kk) * 16 + jj];
            fsw1[(k + kk) * FS_H2 + 16 + jj] = src1[(k + kk) * 16 + jj];
        }
        __syncwarp();

        logits_exp_x2(fsw0, fsw1, elg0, elg1, s_wfcp, lane);
        __syncwarp();

        *(float2*)(&g_agg2[(size_t)p0 * 64 + 2 * lane]) = att_pool_e2(elg0, fs0_h, lane);
        *(float2*)(&g_agg2[(size_t)p1 * 64 + 2 * lane]) = att_pool_e2(elg1, fs1_h, lane);
        __syncwarp();
    }
}

// ---------------------------------------------------------------------------
// Kernel 4: 16-point tiles, SINGLE TF32 GEMMs with float2-packed B. 18 warps.
// ---------------------------------------------------------------------------
#define OUT_WARPS 18
#define OUT_BASE_FLOATS 17216
#define OUT_WARP_FLOATS 1600
#define OUT_SMEM_BYTES ((OUT_BASE_FLOATS + OUT_WARPS * OUT_WARP_FLOATS) * 4)

__global__ __launch_bounds__(576) void kern_out(
    const float* __restrict__ feature,
    const float* __restrict__ wam2, const float* __restrict__ sam2, const float* __restrict__ bam2,
    const float* __restrict__ wmlp2, const float* __restrict__ smlp2, const float* __restrict__ bmlp2,
    const float* __restrict__ wsc, const float* __restrict__ ssc, const float* __restrict__ bsc,
    float* __restrict__ out)
{
    extern __shared__ float sm[];
    float2* w1p  = (float2*)sm;              // [32][68] float2 = 4352 floats
    float2* w23p = (float2*)(sm + 4352);     // [48][132] float2 = 12672 floats
    float*  b1   = sm + 17024;               // [64]
    float*  b2   = sm + 17088;               // [128]
    float*  wrp  = sm + OUT_BASE_FLOATS;

    for (int i = threadIdx.x; i < 2048; i += blockDim.x) {
        int r = i >> 6, c = i & 63;
        int k0 = (r >> 2) * 8 + (r & 3), k1 = k0 + 4;
        w1p[r * P2F64 + c] = make_float2(to_tf32(wam2[k0 * 64 + c] * sam2[c]),
                                         to_tf32(wam2[k1 * 64 + c] * sam2[c]));
    }
    for (int i = threadIdx.x; i < 6144; i += blockDim.x) {
        int r = i >> 7, c = i & 127;
        int k0 = (r >> 2) * 8 + (r & 3), k1 = k0 + 4;
        float v0 = (k0 < 64) ? wmlp2[k0 * 128 + c] * smlp2[c] : wsc[(k0 - 64) * 128 + c] * ssc[c];
        float v1 = (k1 < 64) ? wmlp2[k1 * 128 + c] * smlp2[c] : wsc[(k1 - 64) * 128 + c] * ssc[c];
        w23p[r * P2F128 + c] = make_float2(to_tf32(v0), to_tf32(v1));
    }
    if (threadIdx.x < 64)  b1[threadIdx.x] = bam2[threadIdx.x];
    if (threadIdx.x < 128) b2[threadIdx.x] = bmlp2[threadIdx.x] + bsc[threadIdx.x];
    __syncthreads();

    const int lane = threadIdx.x & 31;
    const int warp = threadIdx.x >> 5;
    const int gid = lane >> 2, tig = lane & 3;
    float* A1 = wrp + warp * OUT_WARP_FLOATS;  // [16][100]

    const int nwarps = (gridDim.x * blockDim.x) >> 5;
    int gw = (blockIdx.x * blockDim.x + threadIdx.x) >> 5;
    const int ntiles = P_TOTAL / 16;

    for (int t = gw; t < ntiles; t += nwarps) {
        const int p0 = t * 16;

        #pragma unroll
        for (int r = 0; r < 16; r++) {
            A1[r * OA_PAD + lane]      = g_agg2[(size_t)(p0 + r) * 64 + lane];
            A1[r * OA_PAD + 32 + lane] = g_agg2[(size_t)(p0 + r) * 64 + 32 + lane];
            A1[r * OA_PAD + 64 + lane] = feature[(size_t)(p0 + r) * 32 + lane];
        }
        __syncwarp();

        // GEMM1 (single tf32): pc2 = relu(agg @ w1 + b1) -> A cols 0..63
        {
            float acc[8][4];
            #pragma unroll
            for (int n = 0; n < 8; n++) { acc[n][0]=0.f; acc[n][1]=0.f; acc[n][2]=0.f; acc[n][3]=0.f; }
            #pragma unroll
            for (int q = 0; q < 8; q++) {
                unsigned a0 = __float_as_uint(to_tf32(A1[gid * OA_PAD + q * 8 + tig]));
                unsigned a1 = __float_as_uint(to_tf32(A1[(gid + 8) * OA_PAD + q * 8 + tig]));
                unsigned a2 = __float_as_uint(to_tf32(A1[gid * OA_PAD + q * 8 + tig + 4]));
                unsigned a3 = __float_as_uint(to_tf32(A1[(gid + 8) * OA_PAD + q * 8 + tig + 4]));
                const float2* br = w1p + (q * 4 + tig) * P2F64 + gid;
                #pragma unroll
                for (int n = 0; n < 8; n++) {
                    float2 b = br[8 * n];
                    mma_tf32(acc[n], a0, a1, a2, a3,
                             __float_as_uint(b.x), __float_as_uint(b.y));
                }
            }
            __syncwarp();
            #pragma unroll
            for (int n = 0; n < 8; n++) {
                int c0 = n * 8 + 2 * tig;
                float bb0 = b1[c0], bb1 = b1[c0 + 1];
                *(float2*)(A1 + gid * OA_PAD + c0) =
                    make_float2(fmaxf(acc[n][0] + bb0, 0.f), fmaxf(acc[n][1] + bb1, 0.f));
                *(float2*)(A1 + (gid + 8) * OA_PAD + c0) =
                    make_float2(fmaxf(acc[n][2] + bb0, 0.f), fmaxf(acc[n][3] + bb1, 0.f));
            }
        }
        __syncwarp();

        // GEMM2 (single tf32): out = leaky(A[16][96] @ w23 + b2), two n-halves
        #pragma unroll
        for (int h = 0; h < 2; h++) {
            float acc[8][4];
            #pragma unroll
            for (int n = 0; n < 8; n++) { acc[n][0]=0.f; acc[n][1]=0.f; acc[n][2]=0.f; acc[n][3]=0.f; }
            #pragma unroll
            for (int q = 0; q < 12; q++) {
                unsigned a0 = __float_as_uint(to_tf32(A1[gid * OA_PAD + q * 8 + tig]));
                unsigned a1 = __float_as_uint(to_tf32(A1[(gid + 8) * OA_PAD + q * 8 + tig]));
                unsigned a2 = __float_as_uint(to_tf32(A1[gid * OA_PAD + q * 8 + tig + 4]));
                unsigned a3 = __float_as_uint(to_tf32(A1[(gid + 8) * OA_PAD + q * 8 + tig + 4]));
                const float2* br = w23p + (q * 4 + tig) * P2F128 + h * 64 + gid;
                #pragma unroll
                for (int n = 0; n < 8; n++) {
                    float2 b = br[8 * n];
                    mma_tf32(acc[n], a0, a1, a2, a3,
                             __float_as_uint(b.x), __float_as_uint(b.y));
                }
            }
            #pragma unroll
            for (int n = 0; n < 8; n++) {
                int c0 = h * 64 + n * 8 + 2 * tig;
                float bb0 = b2[c0], bb1 = b2[c0 + 1];
                float v0 = acc[n][0] + bb0; v0 = (v0 < 0.f) ? 0.2f * v0 : v0;
                float v1 = acc[n][1] + bb1; v1 = (v1 < 0.f) ? 0.2f * v1 : v1;
                float v2 = acc[n][2] + bb0; v2 = (v2 < 0.f) ? 0.2f * v2 : v2;
                float v3 = acc[n][3] + bb1; v3 = (v3 < 0.f) ? 0.2f * v3 : v3;
                *(float2*)(&out[(size_t)(p0 + gid) * 128 + c0])     = make_float2(v0, v1);
                *(float2*)(&out[(size_t)(p0 + gid + 8) * 128 + c0]) = make_float2(v2, v3);
            }
        }
        __syncwarp();
    }
}

// ---------------------------------------------------------------------------
extern "C" void kernel_launch(void* const* d_in, const int* in_sizes, int n_in,
                              void* d_out, int out_size)
{
    const float* feature = (const float*)d_in[0];
    const float* xyz     = (const float*)d_in[1];
    const int*   neigh   = (const int*)  d_in[2];
    const float* w_mlp1  = (const float*)d_in[3];
    const float* s_mlp1  = (const float*)d_in[4];
    const float* b_mlp1  = (const float*)d_in[5];
    const float* w_lfa1  = (const float*)d_in[6];
    const float* s_lfa1  = (const float*)d_in[7];
    const float* b_lfa1  = (const float*)d_in[8];
    const float* w_fc1   = (const float*)d_in[9];
    const float* w_am1   = (const float*)d_in[10];
    const float* s_am1   = (const float*)d_in[11];
    const float* b_am1   = (const float*)d_in[12];
    const float* w_lfa2  = (const float*)d_in[13];
    const float* s_lfa2  = (const float*)d_in[14];
    const float* b_lfa2  = (const float*)d_in[15];
    const float* w_fc2   = (const float*)d_in[16];
    const float* w_am2   = (const float*)d_in[17];
    const float* s_am2   = (const float*)d_in[18];
    const float* b_am2   = (const float*)d_in[19];
    const float* w_mlp2  = (const float*)d_in[20];
    const float* s_mlp2  = (const float*)d_in[21];
    const float* b_mlp2  = (const float*)d_in[22];
    const float* w_sc    = (const float*)d_in[23];
    const float* s_sc    = (const float*)d_in[24];
    const float* b_sc    = (const float*)d_in[25];
    float* out = (float*)d_out;

    cudaFuncSetAttribute(kern_att1, cudaFuncAttributeMaxDynamicSharedMemorySize, K2_SMEM_BYTES);
    cudaFuncSetAttribute(kern_att2, cudaFuncAttributeMaxDynamicSharedMemorySize, K3_SMEM_BYTES);
    cudaFuncSetAttribute(kern_out,  cudaFuncAttributeMaxDynamicSharedMemorySize, OUT_SMEM_BYTES);

    kern_mlp1<<<2048, 256>>>(feature, w_mlp1, s_mlp1, b_mlp1);

    kern_att1<<<148, 640, K2_SMEM_BYTES>>>(
        xyz, neigh,
        w_lfa1, s_lfa1, b_lfa1,
        w_fc1,
        w_am1, s_am1, b_am1,
        w_lfa2, s_lfa2, b_lfa2);

    kern_att2<<<148, 736, K3_SMEM_BYTES>>>(neigh, w_fc2);

    kern_out<<<148, 576, OUT_SMEM_BYTES>>>(
        feature,
        w_am2, s_am2, b_am2,
        w_mlp2, s_mlp2, b_mlp2,
        w_sc, s_sc, b_sc,
        out);
}

// round 15
// speedup vs baseline: 1.5716x; 1.0919x over previous
#include <cuda_runtime.h>
#include <cuda_fp16.h>
#include <math.h>

#define BATCH 4
#define NPTS  40960
#define KNN   16
#define P_TOTAL (BATCH * NPTS)   // 163840

#define FS_H2  36    // fs/elg tile row stride in half2 units (4 mod 32)
#define WH64   68    // fp16 B-tile stride, 64 cols, uint2 units
#define WH32   36    // fp16 B-tile stride, 32 cols, uint2 units
#define P2F64  68    // float2 B-tile stride, 64 cols (4 mod 16)
#define P2F128 132   // float2 B-tile stride, 128 cols (4 mod 16)
#define RP2    12    // relpos tile stride in half2 units
#define OA_PAD 100   // kern_out A tile stride (4 mod 32)

// Scratch (device globals) -- gathered tensors stored pre-packed fp16
__device__ __half2 g_f_pc_h [P_TOTAL * 16];                  // 10.5 MB
__device__ __half2 g_f_agg_h[P_TOTAL * 16];                  // 10.5 MB
__device__ float   g_agg2 [(size_t)P_TOTAL * 64];            // 42 MB
__device__ __half2 g_fx2  [(size_t)P_TOTAL * KNN * 16];      // 168 MB

__device__ __forceinline__ float to_tf32(float x) {
    float r;
    asm("cvt.rna.tf32.f32 %0, %1;" : "=f"(r) : "f"(x));
    return r;
}
__device__ __forceinline__ unsigned f2_to_u(float a, float b) {
    __half2 h = __floats2half2_rn(a, b);
    return *(unsigned*)&h;
}

__device__ __forceinline__ void mma_tf32(float* c,
                                         unsigned a0, unsigned a1, unsigned a2, unsigned a3,
                                         unsigned b0, unsigned b1) {
    asm("mma.sync.aligned.m16n8k8.row.col.f32.tf32.tf32.f32 "
        "{%0,%1,%2,%3}, {%4,%5,%6,%7}, {%8,%9}, {%0,%1,%2,%3};"
        : "+f"(c[0]), "+f"(c[1]), "+f"(c[2]), "+f"(c[3])
        : "r"(a0), "r"(a1), "r"(a2), "r"(a3), "r"(b0), "r"(b1));
}
__device__ __forceinline__ void mma_f16(float* c,
                                        unsigned a0, unsigned a1, unsigned a2, unsigned a3,
                                        unsigned b0, unsigned b1) {
    asm("mma.sync.aligned.m16n8k16.row.col.f32.f16.f16.f32 "
        "{%0,%1,%2,%3}, {%4,%5,%6,%7}, {%8,%9}, {%0,%1,%2,%3};"
        : "+f"(c[0]), "+f"(c[1]), "+f"(c[2]), "+f"(c[3])
        : "r"(a0), "r"(a1), "r"(a2), "r"(a3), "r"(b0), "r"(b1));
}

// dual-point logits -> exp(logit-8) stored as fp16 weight tiles (elg).
__device__ __forceinline__ void logits_exp_x2(const unsigned* __restrict__ fsw0,
                                              const unsigned* __restrict__ fsw1,
                                              __half2* __restrict__ elg0,
                                              __half2* __restrict__ elg1,
                                              const uint2* __restrict__ wfc, int lane)
{
    const int gid = lane >> 2;
    const int tig = lane & 3;
    float ac0[8][4], ac1[8][4];
    #pragma unroll
    for (int n = 0; n < 8; n++)
        #pragma unroll
        for (int j = 0; j < 4; j++) { ac0[n][j] = 0.f; ac1[n][j] = 0.f; }
    #pragma unroll
    for (int q = 0; q < 4; q++) {
        unsigned a00 = fsw0[gid * FS_H2 + q * 8 + tig];
        unsigned a01 = fsw0[(gid + 8) * FS_H2 + q * 8 + tig];
        unsigned a02 = fsw0[gid * FS_H2 + q * 8 + tig + 4];
        unsigned a03 = fsw0[(gid + 8) * FS_H2 + q * 8 + tig + 4];
        unsigned a10 = fsw1[gid * FS_H2 + q * 8 + tig];
        unsigned a11 = fsw1[(gid + 8) * FS_H2 + q * 8 + tig];
        unsigned a12 = fsw1[gid * FS_H2 + q * 8 + tig + 4];
        unsigned a13 = fsw1[(gid + 8) * FS_H2 + q * 8 + tig + 4];
        const uint2* br = wfc + (q * 4 + tig) * WH64 + gid;
        #pragma unroll
        for (int n = 0; n < 8; n++) {
            uint2 b = br[8 * n];
            mma_f16(ac0[n], a00, a01, a02, a03, b.x, b.y);
            mma_f16(ac1[n], a10, a11, a12, a13, b.x, b.y);
        }
    }
    #pragma unroll
    for (int n = 0; n < 8; n++) {
        elg0[gid * FS_H2 + n * 4 + tig] =
            __floats2half2_rn(__expf(ac0[n][0] - 8.f), __expf(ac0[n][1] - 8.f));
        elg0[(gid + 8) * FS_H2 + n * 4 + tig] =
            __floats2half2_rn(__expf(ac0[n][2] - 8.f), __expf(ac0[n][3] - 8.f));
        elg1[gid * FS_H2 + n * 4 + tig] =
            __floats2half2_rn(__expf(ac1[n][0] - 8.f), __expf(ac1[n][1] - 8.f));
        elg1[(gid + 8) * FS_H2 + n * 4 + tig] =
            __floats2half2_rn(__expf(ac1[n][2] - 8.f), __expf(ac1[n][3] - 8.f));
    }
}

// Pool for channel pair (2*lane, 2*lane+1): conflict-free half2 loads,
// two (sum, acc) chains per half (even/odd k).
__device__ __forceinline__ float2 att_pool_e2(const __half2* __restrict__ elg,
                                              const __half2* __restrict__ fs_h, int lane)
{
    float sx0 = 0.f, ax0 = 0.f, sx1 = 0.f, ax1 = 0.f;
    float sy0 = 0.f, ay0 = 0.f, sy1 = 0.f, ay1 = 0.f;
    #pragma unroll
    for (int k = 0; k < KNN; k += 2) {
        float2 e0 = __half22float2(elg[k * FS_H2 + lane]);
        float2 v0 = __half22float2(fs_h[k * FS_H2 + lane]);
        float2 e1 = __half22float2(elg[(k + 1) * FS_H2 + lane]);
        float2 v1 = __half22float2(fs_h[(k + 1) * FS_H2 + lane]);
        sx0 += e0.x; ax0 += e0.x * v0.x;
        sy0 += e0.y; ay0 += e0.y * v0.y;
        sx1 += e1.x; ax1 += e1.x * v1.x;
        sy1 += e1.y; ay1 += e1.y * v1.y;
    }
    return make_float2(__fdividef(ax0 + ax1, sx0 + sx1),
                       __fdividef(ay0 + ay1, sy0 + sy1));
}

// ---------------------------------------------------------------------------
// Kernel 1: f_pc = ReLU((feature @ w_mlp1) * s + b) -> fp16 packed
// ---------------------------------------------------------------------------
__global__ __launch_bounds__(256) void kern_mlp1(
    const float* __restrict__ feature,
    const float* __restrict__ w, const float* __restrict__ s, const float* __restrict__ b)
{
    __shared__ float xs[8][32];

    const int lane = threadIdx.x & 31;
    const int warp = threadIdx.x >> 5;

    float wcol[32];
    #pragma unroll
    for (int j = 0; j < 32; j++) wcol[j] = w[j * 32 + lane];
    const float sv = s[lane];
    const float bv = b[lane];

    unsigned* dst = (unsigned*)g_f_pc_h;

    const int nwarps = (gridDim.x * blockDim.x) >> 5;
    int gw = (blockIdx.x * blockDim.x + threadIdx.x) >> 5;

    for (int p = gw; p < P_TOTAL; p += nwarps) {
        xs[warp][lane] = feature[(size_t)p * 32 + lane];
        __syncwarp();
        float acc = 0.f;
        #pragma unroll
        for (int j4 = 0; j4 < 32; j4 += 4) {
            float4 f = *(const float4*)(&xs[warp][j4]);
            acc += f.x * wcol[j4] + f.y * wcol[j4 + 1]
                 + f.z * wcol[j4 + 2] + f.w * wcol[j4 + 3];
        }
        float o = fmaxf(acc * sv + bv, 0.f);
        float o1 = __shfl_xor_sync(0xffffffffu, o, 1);
        if (!(lane & 1))
            dst[(size_t)p * 16 + (lane >> 1)] = f2_to_u(o, o1);
        __syncwarp();
    }
}

// ---------------------------------------------------------------------------
// Kernel 2: TWO points per warp. rel_pos + lfa1(f16) + direct fp16 gather +
//           logits->exp + pool(half2 pairs) + f_agg(fp16) ; lfa2 -> g_fx2.
// ---------------------------------------------------------------------------
#define K2_WARP_FLOATS 2432
#define K2_BASE_FLOATS 5216
#define K2_WARPS 20
#define K2_SMEM_BYTES ((K2_BASE_FLOATS + K2_WARPS * K2_WARP_FLOATS) * 4)

__global__ __launch_bounds__(640) void kern_att1(
    const float* __restrict__ xyz, const int* __restrict__ neigh,
    const float* __restrict__ wlfa1, const float* __restrict__ slfa1, const float* __restrict__ blfa1,
    const float* __restrict__ wfc1,
    const float* __restrict__ wam1, const float* __restrict__ sam1, const float* __restrict__ bam1,
    const float* __restrict__ wlfa2, const float* __restrict__ slfa2, const float* __restrict__ blfa2)
{
    extern __shared__ float sm[];
    uint2*  s_wfcp = (uint2*)sm;              // [16][68] uint2 = 2176 floats
    float2* s_wamp = (float2*)(sm + 2176);    // [32][32] float2 = 2048 floats
    uint2*  s_wl1p = (uint2*)(sm + 4224);     // [4][36] uint2 = 288 floats
    uint2*  s_wl2p = (uint2*)(sm + 4512);     // [8][36] uint2 = 576 floats
    float*  s_vec  = sm + 5088;               // 128: blfa1, blfa2, bam1
    float*  s_wrp  = sm + K2_BASE_FLOATS;

    for (int i = threadIdx.x; i < 1024; i += blockDim.x) {
        int r = i >> 6, c = i & 63;
        int q = r >> 2, t = r & 3;
        int k0 = 16 * q + 2 * t;
        s_wfcp[r * WH64 + c] = make_uint2(
            f2_to_u(wfc1[k0 * 64 + c], wfc1[(k0 + 1) * 64 + c]),
            f2_to_u(wfc1[(k0 + 8) * 64 + c], wfc1[(k0 + 9) * 64 + c]));
    }
    for (int i = threadIdx.x; i < 1024; i += blockDim.x) {
        int r = i >> 5, c = i & 31;
        s_wamp[r * 32 + c] = make_float2(wam1[(2 * r) * 32 + c] * sam1[c],
                                         wam1[(2 * r + 1) * 32 + c] * sam1[c]);
    }
    for (int i = threadIdx.x; i < 128; i += blockDim.x) {
        int t = i >> 5, c = i & 31;
        int k0 = 2 * t, k1 = 2 * t + 8;
        float w00 = wlfa1[k0 * 32 + c] * slfa1[c];
        float w01 = wlfa1[(k0 + 1) * 32 + c] * slfa1[c];
        float w10 = (k1 < 10) ? wlfa1[k1 * 32 + c] * slfa1[c] : 0.f;
        float w11 = (k1 + 1 < 10) ? wlfa1[(k1 + 1) * 32 + c] * slfa1[c] : 0.f;
        s_wl1p[t * WH32 + c] = make_uint2(f2_to_u(w00, w01), f2_to_u(w10, w11));
    }
    for (int i = threadIdx.x; i < 256; i += blockDim.x) {
        int r = i >> 5, c = i & 31;
        int q = r >> 2, t = r & 3;
        int k0 = 16 * q + 2 * t;
        s_wl2p[r * WH32 + c] = make_uint2(
            f2_to_u(wlfa2[k0 * 32 + c] * slfa2[c], wlfa2[(k0 + 1) * 32 + c] * slfa2[c]),
            f2_to_u(wlfa2[(k0 + 8) * 32 + c] * slfa2[c], wlfa2[(k0 + 9) * 32 + c] * slfa2[c]));
    }
    if (threadIdx.x < 32) {
        int l = threadIdx.x;
        s_vec[l]      = blfa1[l];
        s_vec[32 + l] = blfa2[l];
        s_vec[64 + l] = bam1[l];
    }
    __syncthreads();

    const int lane = threadIdx.x & 31;
    const int warp = threadIdx.x >> 5;
    const int gid = lane >> 2, tig = lane & 3;
    const int kk = lane >> 4, jj = lane & 15;
    float* wbase = s_wrp + warp * K2_WARP_FLOATS;
    __half2*  fs0_h = (__half2*)wbase;            // [16][36] half2
    __half2*  fs1_h = (__half2*)(wbase + 576);
    unsigned* fsw0  = (unsigned*)fs0_h;
    unsigned* fsw1  = (unsigned*)fs1_h;
    __half2*  elg0  = (__half2*)(wbase + 1152);   // [16][36] half2 (weights)
    __half2*  elg1  = (__half2*)(wbase + 1728);
    __half2*  rp0   = elg0;                       // relpos aliases elg (dead)
    __half2*  rp1   = elg1;
    unsigned* rp0w  = (unsigned*)rp0;
    unsigned* rp1w  = (unsigned*)rp1;
    float* agg_s = wbase + 2304;                  // [128]

    const unsigned* pc = (const unsigned*)g_f_pc_h;
    unsigned* fah = (unsigned*)g_f_agg_h;

    const int nwarps = (gridDim.x * blockDim.x) >> 5;
    int gw = (blockIdx.x * blockDim.x + threadIdx.x) >> 5;

    for (int pp = gw; pp < P_TOTAL / 2; pp += nwarps) {
        const int p0 = 2 * pp, p1 = p0 + 1;
        const int b = p0 / NPTS;
        const size_t bbase = (size_t)b * NPTS;

        int idx = neigh[(size_t)p0 * KNN + lane];

        // direct fp16 gather: 2 rows per pass, lane (kk,jj)
        #pragma unroll
        for (int k = 0; k < KNN; k += 2) {
            int nb = __shfl_sync(0xffffffffu, idx, k + kk);
            fsw0[(k + kk) * FS_H2 + jj] = pc[(bbase + (size_t)nb) * 16 + jj];
        }
        #pragma unroll
        for (int k = 0; k < KNN; k += 2) {
            int nb = __shfl_sync(0xffffffffu, idx, 16 + k + kk);
            fsw1[(k + kk) * FS_H2 + jj] = pc[(bbase + (size_t)nb) * 16 + jj];
        }

        {
            const int myp = (lane < 16) ? p0 : p1;
            const int krow = lane & 15;
            float cx = xyz[(size_t)myp * 3 + 0];
            float cy = xyz[(size_t)myp * 3 + 1];
            float cz = xyz[(size_t)myp * 3 + 2];
            size_t nb = bbase + (size_t)idx;
            float nx = xyz[nb * 3 + 0], ny = xyz[nb * 3 + 1], nz = xyz[nb * 3 + 2];
            float rx = cx - nx, ry = cy - ny, rz = cz - nz;
            float d = sqrtf(rx * rx + ry * ry + rz * rz);
            __half2* rp = (lane < 16) ? rp0 : rp1;
            __half2 z = __floats2half2_rn(0.f, 0.f);
            rp[krow * RP2 + 0] = __floats2half2_rn(d, rx);
            rp[krow * RP2 + 1] = __floats2half2_rn(ry, rz);
            rp[krow * RP2 + 2] = __floats2half2_rn(cx, cy);
            rp[krow * RP2 + 3] = __floats2half2_rn(cz, nx);
            rp[krow * RP2 + 4] = __floats2half2_rn(ny, nz);
            rp[krow * RP2 + 5] = z;
            rp[krow * RP2 + 6] = z;
            rp[krow * RP2 + 7] = z;
        }
        __syncwarp();

        // lfa1 via f16 mma (K=16 covers all 10 rows), B shared
        {
            unsigned a00 = rp0w[gid * RP2 + tig];
            unsigned a01 = rp0w[(gid + 8) * RP2 + tig];
            unsigned a02 = rp0w[gid * RP2 + tig + 4];
            unsigned a03 = rp0w[(gid + 8) * RP2 + tig + 4];
            unsigned a10 = rp1w[gid * RP2 + tig];
            unsigned a11 = rp1w[(gid + 8) * RP2 + tig];
            unsigned a12 = rp1w[gid * RP2 + tig + 4];
            unsigned a13 = rp1w[(gid + 8) * RP2 + tig + 4];
            float ac0[4][4], ac1[4][4];
            #pragma unroll
            for (int n = 0; n < 4; n++)
                #pragma unroll
                for (int j = 0; j < 4; j++) { ac0[n][j] = 0.f; ac1[n][j] = 0.f; }
            const uint2* br = s_wl1p + tig * WH32 + gid;
            #pragma unroll
            for (int n = 0; n < 4; n++) {
                uint2 bb = br[8 * n];
                mma_f16(ac0[n], a00, a01, a02, a03, bb.x, bb.y);
                mma_f16(ac1[n], a10, a11, a12, a13, bb.x, bb.y);
            }
            #pragma unroll
            for (int n = 0; n < 4; n++) {
                int c0 = n * 8 + 2 * tig;
                float b0 = s_vec[c0], b1 = s_vec[c0 + 1];
                fs0_h[gid * FS_H2 + 16 + n * 4 + tig] =
                    __floats2half2_rn(fmaxf(ac0[n][0] + b0, 0.f), fmaxf(ac0[n][1] + b1, 0.f));
                fs0_h[(gid + 8) * FS_H2 + 16 + n * 4 + tig] =
                    __floats2half2_rn(fmaxf(ac0[n][2] + b0, 0.f), fmaxf(ac0[n][3] + b1, 0.f));
                fs1_h[gid * FS_H2 + 16 + n * 4 + tig] =
                    __floats2half2_rn(fmaxf(ac1[n][0] + b0, 0.f), fmaxf(ac1[n][1] + b1, 0.f));
                fs1_h[(gid + 8) * FS_H2 + 16 + n * 4 + tig] =
                    __floats2half2_rn(fmaxf(ac1[n][2] + b0, 0.f), fmaxf(ac1[n][3] + b1, 0.f));
            }
        }
        __syncwarp();

        // logits mma -> exp -> fp16 weight tiles (overwrites rp -- dead)
        logits_exp_x2(fsw0, fsw1, elg0, elg1, s_wfcp, lane);
        __syncwarp();
        *(float2*)(agg_s + 2 * lane)      = att_pool_e2(elg0, fs0_h, lane);
        *(float2*)(agg_s + 64 + 2 * lane) = att_pool_e2(elg1, fs1_h, lane);
        __syncwarp();

        // f_agg for both points, wam read once; fp16 packed write
        {
            float acc0 = 0.f, acc1 = 0.f;
            #pragma unroll
            for (int d2 = 0; d2 < 32; d2 += 2) {
                float4 a0 = *(const float4*)(agg_s + 2 * d2);
                float4 a1 = *(const float4*)(agg_s + 64 + 2 * d2);
                float2 w0 = s_wamp[d2 * 32 + lane];
                float2 w1 = s_wamp[(d2 + 1) * 32 + lane];
                acc0 += a0.x * w0.x + a0.y * w0.y + a0.z * w1.x + a0.w * w1.y;
                acc1 += a1.x * w0.x + a1.y * w0.y + a1.z * w1.x + a1.w * w1.y;
            }
            float bb = s_vec[64 + lane];
            float o0 = fmaxf(acc0 + bb, 0.f);
            float o1 = fmaxf(acc1 + bb, 0.f);
            float o0x = __shfl_xor_sync(0xffffffffu, o0, 1);
            float o1x = __shfl_xor_sync(0xffffffffu, o1, 1);
            if (!(lane & 1)) {
                fah[(size_t)p0 * 16 + (lane >> 1)] = f2_to_u(o0, o0x);
                fah[(size_t)p1 * 16 + (lane >> 1)] = f2_to_u(o1, o1x);
            }
        }

        // lfa2 via f16 mma, B shared -> g_fx2
        {
            float ac0[4][4], ac1[4][4];
            #pragma unroll
            for (int n = 0; n < 4; n++)
                #pragma unroll
                for (int j = 0; j < 4; j++) { ac0[n][j] = 0.f; ac1[n][j] = 0.f; }
            #pragma unroll
            for (int q = 0; q < 2; q++) {
                unsigned a00 = fsw0[gid * FS_H2 + 16 + q * 8 + tig];
                unsigned a01 = fsw0[(gid + 8) * FS_H2 + 16 + q * 8 + tig];
                unsigned a02 = fsw0[gid * FS_H2 + 16 + q * 8 + tig + 4];
                unsigned a03 = fsw0[(gid + 8) * FS_H2 + 16 + q * 8 + tig + 4];
                unsigned a10 = fsw1[gid * FS_H2 + 16 + q * 8 + tig];
                unsigned a11 = fsw1[(gid + 8) * FS_H2 + 16 + q * 8 + tig];
                unsigned a12 = fsw1[gid * FS_H2 + 16 + q * 8 + tig + 4];
                unsigned a13 = fsw1[(gid + 8) * FS_H2 + 16 + q * 8 + tig + 4];
                const uint2* br = s_wl2p + (q * 4 + tig) * WH32 + gid;
                #pragma unroll
                for (int n = 0; n < 4; n++) {
                    uint2 bb = br[8 * n];
                    mma_f16(ac0[n], a00, a01, a02, a03, bb.x, bb.y);
                    mma_f16(ac1[n], a10, a11, a12, a13, bb.x, bb.y);
                }
            }
            #pragma unroll
            for (int n = 0; n < 4; n++) {
                int c0 = n * 8 + 2 * tig;
                float b0 = s_vec[32 + c0], b1 = s_vec[32 + c0 + 1];
                g_fx2[((size_t)p0 * KNN + gid) * 16 + (c0 >> 1)] =
                    __floats2half2_rn(fmaxf(ac0[n][0] + b0, 0.f), fmaxf(ac0[n][1] + b1, 0.f));
                g_fx2[((size_t)p0 * KNN + gid + 8) * 16 + (c0 >> 1)] =
                    __floats2half2_rn(fmaxf(ac0[n][2] + b0, 0.f), fmaxf(ac0[n][3] + b1, 0.f));
                g_fx2[((size_t)p1 * KNN + gid) * 16 + (c0 >> 1)] =
                    __floats2half2_rn(fmaxf(ac1[n][0] + b0, 0.f), fmaxf(ac1[n][1] + b1, 0.f));
                g_fx2[((size_t)p1 * KNN + gid + 8) * 16 + (c0 >> 1)] =
                    __floats2half2_rn(fmaxf(ac1[n][2] + b0, 0.f), fmaxf(ac1[n][3] + b1, 0.f));
            }
        }
        __syncwarp();
    }
}

// ---------------------------------------------------------------------------
// Kernel 3: TWO points per warp: direct fp16 gather(f_agg) + fx2 +
//           logits->exp + pools -> g_agg2.  23 warps.
// ---------------------------------------------------------------------------
#define K3_WARP_FLOATS 2304
#define K3_BASE_FLOATS 2176
#define K3_WARPS 23
#define K3_SMEM_BYTES ((K3_BASE_FLOATS + K3_WARPS * K3_WARP_FLOATS) * 4)

__global__ __launch_bounds__(736) void kern_att2(
    const int* __restrict__ neigh,
    const float* __restrict__ wfc2)
{
    extern __shared__ float sm[];
    uint2* s_wfcp = (uint2*)sm;               // [16][68] uint2
    float* s_wrp  = sm + K3_BASE_FLOATS;

    for (int i = threadIdx.x; i < 1024; i += blockDim.x) {
        int r = i >> 6, c = i & 63;
        int q = r >> 2, t = r & 3;
        int k0 = 16 * q + 2 * t;
        s_wfcp[r * WH64 + c] = make_uint2(
            f2_to_u(wfc2[k0 * 64 + c], wfc2[(k0 + 1) * 64 + c]),
            f2_to_u(wfc2[(k0 + 8) * 64 + c], wfc2[(k0 + 9) * 64 + c]));
    }
    __syncthreads();

    const int lane = threadIdx.x & 31;
    const int warp = threadIdx.x >> 5;
    float* wbase = s_wrp + warp * K3_WARP_FLOATS;
    __half2*  fs0_h = (__half2*)wbase;
    __half2*  fs1_h = (__half2*)(wbase + 576);
    unsigned* fsw0  = (unsigned*)fs0_h;
    unsigned* fsw1  = (unsigned*)fs1_h;
    __half2*  elg0  = (__half2*)(wbase + 1152);
    __half2*  elg1  = (__half2*)(wbase + 1728);

    const int kk = lane >> 4;
    const int jj = lane & 15;

    const unsigned* fah = (const unsigned*)g_f_agg_h;

    const int nwarps = (gridDim.x * blockDim.x) >> 5;
    int gw = (blockIdx.x * blockDim.x + threadIdx.x) >> 5;

    for (int pp = gw; pp < P_TOTAL / 2; pp += nwarps) {
        const int p0 = 2 * pp, p1 = p0 + 1;
        const int b = p0 / NPTS;
        const size_t bbase = (size_t)b * NPTS;

        int idx = neigh[(size_t)p0 * KNN + lane];

        #pragma unroll
        for (int k = 0; k < KNN; k += 2) {
            int nb = __shfl_sync(0xffffffffu, idx, k + kk);
            fsw0[(k + kk) * FS_H2 + jj] = fah[(bbase + (size_t)nb) * 16 + jj];
        }
        #pragma unroll
        for (int k = 0; k < KNN; k += 2) {
            int nb = __shfl_sync(0xffffffffu, idx, 16 + k + kk);
            fsw1[(k + kk) * FS_H2 + jj] = fah[(bbase + (size_t)nb) * 16 + jj];
        }
        const unsigned* src0 = (const unsigned*)(g_fx2 + (size_t)p0 * KNN * 16);
        const unsigned* src1 = (const unsigned*)(g_fx2 + (size_t)p1 * KNN * 16);
        #pragma unroll
        for (int k = 0; k < KNN; k += 2) {
            fsw0[(k + kk) * FS_H2 + 16 + jj] = src0[(k + kk) * 16 + jj];
            fsw1[(k + kk) * FS_H2 + 16 + jj] = src1[(k + kk) * 16 + jj];
        }
        __syncwarp();

        logits_exp_x2(fsw0, fsw1, elg0, elg1, s_wfcp, lane);
        __syncwarp();

        *(float2*)(&g_agg2[(size_t)p0 * 64 + 2 * lane]) = att_pool_e2(elg0, fs0_h, lane);
        *(float2*)(&g_agg2[(size_t)p1 * 64 + 2 * lane]) = att_pool_e2(elg1, fs1_h, lane);
        __syncwarp();
    }
}

// ---------------------------------------------------------------------------
// Kernel 4: 16-point tiles, SINGLE TF32 GEMMs with float2-packed B. 18 warps.
// ---------------------------------------------------------------------------
#define OUT_WARPS 18
#define OUT_BASE_FLOATS 17216
#define OUT_WARP_FLOATS 1600
#define OUT_SMEM_BYTES ((OUT_BASE_FLOATS + OUT_WARPS * OUT_WARP_FLOATS) * 4)

__global__ __launch_bounds__(576) void kern_out(
    const float* __restrict__ feature,
    const float* __restrict__ wam2, const float* __restrict__ sam2, const float* __restrict__ bam2,
    const float* __restrict__ wmlp2, const float* __restrict__ smlp2, const float* __restrict__ bmlp2,
    const float* __restrict__ wsc, const float* __restrict__ ssc, const float* __restrict__ bsc,
    float* __restrict__ out)
{
    extern __shared__ float sm[];
    float2* w1p  = (float2*)sm;              // [32][68] float2 = 4352 floats
    float2* w23p = (float2*)(sm + 4352);     // [48][132] float2 = 12672 floats
    float*  b1   = sm + 17024;               // [64]
    float*  b2   = sm + 17088;               // [128]
    float*  wrp  = sm + OUT_BASE_FLOATS;

    for (int i = threadIdx.x; i < 2048; i += blockDim.x) {
        int r = i >> 6, c = i & 63;
        int k0 = (r >> 2) * 8 + (r & 3), k1 = k0 + 4;
        w1p[r * P2F64 + c] = make_float2(to_tf32(wam2[k0 * 64 + c] * sam2[c]),
                                         to_tf32(wam2[k1 * 64 + c] * sam2[c]));
    }
    for (int i = threadIdx.x; i < 6144; i += blockDim.x) {
        int r = i >> 7, c = i & 127;
        int k0 = (r >> 2) * 8 + (r & 3), k1 = k0 + 4;
        float v0 = (k0 < 64) ? wmlp2[k0 * 128 + c] * smlp2[c] : wsc[(k0 - 64) * 128 + c] * ssc[c];
        float v1 = (k1 < 64) ? wmlp2[k1 * 128 + c] * smlp2[c] : wsc[(k1 - 64) * 128 + c] * ssc[c];
        w23p[r * P2F128 + c] = make_float2(to_tf32(v0), to_tf32(v1));
    }
    if (threadIdx.x < 64)  b1[threadIdx.x] = bam2[threadIdx.x];
    if (threadIdx.x < 128) b2[threadIdx.x] = bmlp2[threadIdx.x] + bsc[threadIdx.x];
    __syncthreads();

    const int lane = threadIdx.x & 31;
    const int warp = threadIdx.x >> 5;
    const int gid = lane >> 2, tig = lane & 3;
    float* A1 = wrp + warp * OUT_WARP_FLOATS;  // [16][100]

    const int nwarps = (gridDim.x * blockDim.x) >> 5;
    int gw = (blockIdx.x * blockDim.x + threadIdx.x) >> 5;
    const int ntiles = P_TOTAL / 16;

    for (int t = gw; t < ntiles; t += nwarps) {
        const int p0 = t * 16;

        #pragma unroll
        for (int r = 0; r < 16; r++) {
            A1[r * OA_PAD + lane]      = g_agg2[(size_t)(p0 + r) * 64 + lane];
            A1[r * OA_PAD + 32 + lane] = g_agg2[(size_t)(p0 + r) * 64 + 32 + lane];
            A1[r * OA_PAD + 64 + lane] = feature[(size_t)(p0 + r) * 32 + lane];
        }
        __syncwarp();

        // GEMM1 (single tf32): pc2 = relu(agg @ w1 + b1) -> A cols 0..63
        {
            float acc[8][4];
            #pragma unroll
            for (int n = 0; n < 8; n++) { acc[n][0]=0.f; acc[n][1]=0.f; acc[n][2]=0.f; acc[n][3]=0.f; }
            #pragma unroll
            for (int q = 0; q < 8; q++) {
                unsigned a0 = __float_as_uint(to_tf32(A1[gid * OA_PAD + q * 8 + tig]));
                unsigned a1 = __float_as_uint(to_tf32(A1[(gid + 8) * OA_PAD + q * 8 + tig]));
                unsigned a2 = __float_as_uint(to_tf32(A1[gid * OA_PAD + q * 8 + tig + 4]));
                unsigned a3 = __float_as_uint(to_tf32(A1[(gid + 8) * OA_PAD + q * 8 + tig + 4]));
                const float2* br = w1p + (q * 4 + tig) * P2F64 + gid;
                #pragma unroll
                for (int n = 0; n < 8; n++) {
                    float2 b = br[8 * n];
                    mma_tf32(acc[n], a0, a1, a2, a3,
                             __float_as_uint(b.x), __float_as_uint(b.y));
                }
            }
            __syncwarp();
            #pragma unroll
            for (int n = 0; n < 8; n++) {
                int c0 = n * 8 + 2 * tig;
                float bb0 = b1[c0], bb1 = b1[c0 + 1];
                *(float2*)(A1 + gid * OA_PAD + c0) =
                    make_float2(fmaxf(acc[n][0] + bb0, 0.f), fmaxf(acc[n][1] + bb1, 0.f));
                *(float2*)(A1 + (gid + 8) * OA_PAD + c0) =
                    make_float2(fmaxf(acc[n][2] + bb0, 0.f), fmaxf(acc[n][3] + bb1, 0.f));
            }
        }
        __syncwarp();

        // GEMM2 (single tf32): out = leaky(A[16][96] @ w23 + b2), two n-halves
        #pragma unroll
        for (int h = 0; h < 2; h++) {
            float acc[8][4];
            #pragma unroll
            for (int n = 0; n < 8; n++) { acc[n][0]=0.f; acc[n][1]=0.f; acc[n][2]=0.f; acc[n][3]=0.f; }
            #pragma unroll
            for (int q = 0; q < 12; q++) {
                unsigned a0 = __float_as_uint(to_tf32(A1[gid * OA_PAD + q * 8 + tig]));
                unsigned a1 = __float_as_uint(to_tf32(A1[(gid + 8) * OA_PAD + q * 8 + tig]));
                unsigned a2 = __float_as_uint(to_tf32(A1[gid * OA_PAD + q * 8 + tig + 4]));
                unsigned a3 = __float_as_uint(to_tf32(A1[(gid + 8) * OA_PAD + q * 8 + tig + 4]));
                const float2* br = w23p + (q * 4 + tig) * P2F128 + h * 64 + gid;
                #pragma unroll
                for (int n = 0; n < 8; n++) {
                    float2 b = br[8 * n];
                    mma_tf32(acc[n], a0, a1, a2, a3,
                             __float_as_uint(b.x), __float_as_uint(b.y));
                }
            }
            #pragma unroll
            for (int n = 0; n < 8; n++) {
                int c0 = h * 64 + n * 8 + 2 * tig;
                float bb0 = b2[c0], bb1 = b2[c0 + 1];
                float v0 = acc[n][0] + bb0; v0 = (v0 < 0.f) ? 0.2f * v0 : v0;
                float v1 = acc[n][1] + bb1; v1 = (v1 < 0.f) ? 0.2f * v1 : v1;
                float v2 = acc[n][2] + bb0; v2 = (v2 < 0.f) ? 0.2f * v2 : v2;
                float v3 = acc[n][3] + bb1; v3 = (v3 < 0.f) ? 0.2f * v3 : v3;
                *(float2*)(&out[(size_t)(p0 + gid) * 128 + c0])     = make_float2(v0, v1);
                *(float2*)(&out[(size_t)(p0 + gid + 8) * 128 + c0]) = make_float2(v2, v3);
            }
        }
        __syncwarp();
    }
}

// ---------------------------------------------------------------------------
extern "C" void kernel_launch(void* const* d_in, const int* in_sizes, int n_in,
                              void* d_out, int out_size)
{
    const float* feature = (const float*)d_in[0];
    const float* xyz     = (const float*)d_in[1];
    const int*   neigh   = (const int*)  d_in[2];
    const float* w_mlp1  = (const float*)d_in[3];
    const float* s_mlp1  = (const float*)d_in[4];
    const float* b_mlp1  = (const float*)d_in[5];
    const float* w_lfa1  = (const float*)d_in[6];
    const float* s_lfa1  = (const float*)d_in[7];
    const float* b_lfa1  = (const float*)d_in[8];
    const float* w_fc1   = (const float*)d_in[9];
    const float* w_am1   = (const float*)d_in[10];
    const float* s_am1   = (const float*)d_in[11];
    const float* b_am1   = (const float*)d_in[12];
    const float* w_lfa2  = (const float*)d_in[13];
    const float* s_lfa2  = (const float*)d_in[14];
    const float* b_lfa2  = (const float*)d_in[15];
    const float* w_fc2   = (const float*)d_in[16];
    const float* w_am2   = (const float*)d_in[17];
    const float* s_am2   = (const float*)d_in[18];
    const float* b_am2   = (const float*)d_in[19];
    const float* w_mlp2  = (const float*)d_in[20];
    const float* s_mlp2  = (const float*)d_in[21];
    const float* b_mlp2  = (const float*)d_in[22];
    const float* w_sc    = (const float*)d_in[23];
    const float* s_sc    = (const float*)d_in[24];
    const float* b_sc    = (const float*)d_in[25];
    float* out = (float*)d_out;

    cudaFuncSetAttribute(kern_att1, cudaFuncAttributeMaxDynamicSharedMemorySize, K2_SMEM_BYTES);
    cudaFuncSetAttribute(kern_att2, cudaFuncAttributeMaxDynamicSharedMemorySize, K3_SMEM_BYTES);
    cudaFuncSetAttribute(kern_out,  cudaFuncAttributeMaxDynamicSharedMemorySize, OUT_SMEM_BYTES);

    kern_mlp1<<<2048, 256>>>(feature, w_mlp1, s_mlp1, b_mlp1);

    kern_att1<<<148, 640, K2_SMEM_BYTES>>>(
        xyz, neigh,
        w_lfa1, s_lfa1, b_lfa1,
        w_fc1,
        w_am1, s_am1, b_am1,
        w_lfa2, s_lfa2, b_lfa2);

    kern_att2<<<148, 736, K3_SMEM_BYTES>>>(neigh, w_fc2);

    kern_out<<<148, 576, OUT_SMEM_BYTES>>>(
        feature,
        w_am2, s_am2, b_am2,
        w_mlp2, s_mlp2, b_mlp2,
        w_sc, s_sc, b_sc,
        out);
}